// round 7
// baseline (speedup 1.0000x reference)
#include <cuda_runtime.h>
#include <cuda_fp16.h>
#include <cstdint>

// Problem constants
#define T_LEN   8192
#define BATCH   4
#define D_MODEL 1024
#define NHEAD   16
#define HD      64
#define QKV_LD  (3 * D_MODEL)        // 3072
#define NROWS   (T_LEN * BATCH)      // 32768
#define NHEADS_TOTAL (BATCH * NHEAD) // 64
#define STATS_PER_HEAD 4352

// Scratch (device globals: allocation-free)
__device__ float  g_qkv[(size_t)NROWS * QKV_LD];                 // 384 MB (q,k used)
__device__ __half g_qh[(size_t)NROWS * D_MODEL];                 // 64 MB  query fp16
__device__ __half g_wh[(size_t)QKV_LD * D_MODEL];                // 6 MB   Wqkv fp16
__device__ __half g_vh[(size_t)NROWS * D_MODEL];                 // 64 MB  v fp16
__device__ __half g_mh[(size_t)BATCH * D_MODEL * D_MODEL];       // 8 MB  Meff fp16
__device__ float  g_stats[NHEADS_TOTAL * STATS_PER_HEAD];
__device__ float  g_corr[NHEADS_TOTAL * HD * HD];

// ===========================================================================
// helpers
// ===========================================================================
__device__ __forceinline__ uint32_t smem_to_u32(const void* p) {
    uint32_t a;
    asm("{ .reg .u64 t; cvta.to.shared.u64 t, %1; cvt.u32.u64 %0, t; }"
        : "=r"(a) : "l"(p));
    return a;
}

__device__ __forceinline__ void ldsm4(uint32_t (&r)[4], uint32_t addr) {
    asm volatile("ldmatrix.sync.aligned.m8n8.x4.shared.b16 {%0,%1,%2,%3}, [%4];"
        : "=r"(r[0]), "=r"(r[1]), "=r"(r[2]), "=r"(r[3]) : "r"(addr));
}

__device__ __forceinline__ void mma16816(float (&c)[4], const uint32_t (&a)[4],
                                         uint32_t b0, uint32_t b1) {
    asm volatile(
        "mma.sync.aligned.m16n8k16.row.col.f32.f16.f16.f32 "
        "{%0,%1,%2,%3}, {%4,%5,%6,%7}, {%8,%9}, {%0,%1,%2,%3};"
        : "+f"(c[0]), "+f"(c[1]), "+f"(c[2]), "+f"(c[3])
        : "r"(a[0]), "r"(a[1]), "r"(a[2]), "r"(a[3]), "r"(b0), "r"(b1));
}

#define CP_COMMIT() asm volatile("cp.async.commit_group;" ::: "memory")
#define CP16(dst, src) \
    asm volatile("cp.async.cg.shared.global [%0], [%1], 16;" \
        :: "r"(dst), "l"(src) : "memory")

// ===========================================================================
// fp16 single-pass HMMA GEMM (NT): C[m,n] = sum_k A[m,k]*B[n,k] + bias[n]
// 256x128x32 CTA tile, 16 warps (4x4), warp tile 64x32. 512 threads.
// 4-stage cp.async pipeline. smem rows 80B (conflict-free ldmatrix).
// Optional epilogue: columns >= 2048 written as fp16 (v output).
// ===========================================================================
#define BM 256
#define BN 128
#define BK 32
#define NTHR 512
#define ROWB 80
#define A_TILEB (256 * ROWB)    // 20480
#define B_TILEB (128 * ROWB)    // 10240
#define OFF_A  0
#define OFF_B  A_TILEB
#define STAGEB (A_TILEB + B_TILEB)      // 30720
#define NSTAGE 4
#define SMEMB (NSTAGE * STAGEB)         // 122880

__global__ void __launch_bounds__(NTHR, 1) gemm_fp16_kernel(
    const __half* __restrict__ Ah, int strideA, long long batchA,
    const __half* __restrict__ Bh, int strideB, long long batchB,
    const float* __restrict__ bias,
    float* __restrict__ C, int strideC, long long batchC,
    __half* __restrict__ Vh,
    int K)
{
    extern __shared__ char smem[];
    const uint32_t sb = smem_to_u32(smem);
    const int tid = threadIdx.x;
    const int lane = tid & 31;
    const int wid = tid >> 5;         // 0..15
    const int wm = (wid & 3) * 64;    // 0,64,128,192
    const int wn = (wid >> 2) * 32;   // 0,32,64,96
    const int z = blockIdx.z;

    const __half* Ab = Ah + (size_t)blockIdx.y * BM * strideA + (size_t)z * batchA;
    const __half* Bb = Bh + (size_t)blockIdx.x * BN * strideB + (size_t)z * batchB;

    float acc[4][4][4];
    #pragma unroll
    for (int mt = 0; mt < 4; mt++)
        #pragma unroll
        for (int nt = 0; nt < 4; nt++)
            #pragma unroll
            for (int r = 0; r < 4; r++) acc[mt][nt][r] = 0.0f;

    const int NKT = K / BK;

    // 3 x 16B cp.async per thread per stage:
    // i=0,1 -> A (1024 chunks: 256 rows x 4), i=2 -> B (512 chunks)
    #define ISSUE_STAGE(kt, buf) do { \
        const uint32_t sbase = sb + (buf) * STAGEB; \
        _Pragma("unroll") \
        for (int i = 0; i < 3; i++) { \
            const int ci = i * NTHR + tid; \
            const __half* src; uint32_t dst; \
            if (i < 2) { \
                const int r_ = ci >> 2, c_ = ci & 3; \
                src = Ab + (size_t)r_ * strideA + (kt) * BK + c_ * 8; \
                dst = sbase + OFF_A + r_ * ROWB + c_ * 16; \
            } else { \
                const int j_ = ci - 1024, r_ = j_ >> 2, c_ = j_ & 3; \
                src = Bb + (size_t)r_ * strideB + (kt) * BK + c_ * 8; \
                dst = sbase + OFF_B + r_ * ROWB + c_ * 16; \
            } \
            CP16(dst, src); \
        } \
    } while (0)

    ISSUE_STAGE(0, 0); CP_COMMIT();
    ISSUE_STAGE(1, 1); CP_COMMIT();
    ISSUE_STAGE(2, 2); CP_COMMIT();

    // frag address components (constant per thread)
    const uint32_t a_off = (uint32_t)((lane & 15) * ROWB + (lane >> 4) * 16);
    const uint32_t b_row = (uint32_t)((lane & 7) + ((lane >> 4) << 3));
    const uint32_t b_off = (uint32_t)(b_row * ROWB + ((lane >> 3) & 1) * 16);

    for (int kt = 0; kt < NKT; kt++) {
        asm volatile("cp.async.wait_group 2;" ::: "memory");
        __syncthreads();

        if (kt + 3 < NKT) { ISSUE_STAGE(kt + 3, (kt + 3) % NSTAGE); CP_COMMIT(); }

        const uint32_t base = sb + (kt % NSTAGE) * STAGEB;
        #pragma unroll
        for (int kk = 0; kk < 2; kk++) {
            const uint32_t koff = kk * 32;
            uint32_t a[4][4];
            #pragma unroll
            for (int mt = 0; mt < 4; mt++)
                ldsm4(a[mt], base + OFF_A + (wm + mt * 16) * ROWB + a_off + koff);
            #pragma unroll
            for (int ng = 0; ng < 2; ng++) {
                uint32_t bh[4];
                ldsm4(bh, base + OFF_B + (wn + ng * 16) * ROWB + b_off + koff);
                #pragma unroll
                for (int mt = 0; mt < 4; mt++) {
                    mma16816(acc[mt][2*ng],   a[mt], bh[0], bh[1]);
                    mma16816(acc[mt][2*ng+1], a[mt], bh[2], bh[3]);
                }
            }
        }
    }

    // ---- epilogue ----
    const int rbase = blockIdx.y * BM + wm + (lane >> 2);
    const int cbase = blockIdx.x * BN + wn + (lane & 3) * 2;
    float* Cz = C + (size_t)z * batchC;
    #pragma unroll
    for (int mt = 0; mt < 4; mt++) {
        #pragma unroll
        for (int nt = 0; nt < 4; nt++) {
            const int row = rbase + mt * 16;
            const int col = cbase + nt * 8;
            const float b0 = bias[col], b1 = bias[col + 1];
            const float v0 = acc[mt][nt][0] + b0, v1 = acc[mt][nt][1] + b1;
            const float v2 = acc[mt][nt][2] + b0, v3 = acc[mt][nt][3] + b1;
            if (Vh != nullptr && col >= 2048) {
                const int vc = col - 2048;
                *(__half2*)(Vh + (size_t)row * D_MODEL + vc)       = __floats2half2_rn(v0, v1);
                *(__half2*)(Vh + (size_t)(row + 8) * D_MODEL + vc) = __floats2half2_rn(v2, v3);
            } else {
                float2 o0, o1;
                o0.x = v0; o0.y = v1; o1.x = v2; o1.y = v3;
                *(float2*)(Cz + (size_t)row * strideC + col) = o0;
                *(float2*)(Cz + (size_t)(row + 8) * strideC + col) = o1;
            }
        }
    }
}

// ===========================================================================
// Converter: fp32 -> fp16
// ===========================================================================
__global__ void conv_half_kernel(const float* __restrict__ in,
                                 __half* __restrict__ outh, int n4) {
    int idx = blockIdx.x * blockDim.x + threadIdx.x;
    if (idx < n4) {
        float4 v = ((const float4*)in)[idx];
        ((__half2*)outh)[2 * idx]     = __floats2half2_rn(v.x, v.y);
        ((__half2*)outh)[2 * idx + 1] = __floats2half2_rn(v.z, v.w);
    }
}

// ===========================================================================
// Zero the stats accumulator
// ===========================================================================
__global__ void zero_stats_kernel() {
    int idx = blockIdx.x * blockDim.x + threadIdx.x;
    if (idx < NHEADS_TOTAL * STATS_PER_HEAD) g_stats[idx] = 0.0f;
}

// ===========================================================================
// Stats: per head (b,h) accumulate C[i][j]=sum_t q_i k_j, Sq, Sk, Sqq, Skk
// ===========================================================================
#define TSPLIT 8
#define TCHUNK (T_LEN / TSPLIT)   // 1024

__global__ __launch_bounds__(256) void stats_kernel(const float* __restrict__ qkv) {
    const int head = blockIdx.y;
    const int b = head >> 4, h = head & 15;
    const int tid = threadIdx.x;

    __shared__ float qs[16][HD];
    __shared__ float ks[16][HD];

    const float* qbase = qkv + (size_t)b * QKV_LD + h * HD;
    const float* kbase = qbase + D_MODEL;

    float acc[4][4];
    #pragma unroll
    for (int i = 0; i < 4; i++)
        #pragma unroll
        for (int j = 0; j < 4; j++) acc[i][j] = 0.0f;
    float sq = 0.f, sqq = 0.f, sk = 0.f, skk = 0.f;

    const int i0 = (tid >> 4) * 4, j0 = (tid & 15) * 4;
    const int lrow = tid >> 4;
    const int lcol = (tid & 15) * 4;

    const int tstart = blockIdx.x * TCHUNK;
    for (int t0 = tstart; t0 < tstart + TCHUNK; t0 += 16) {
        size_t grow = (size_t)(t0 + lrow) * BATCH * QKV_LD;
        *(float4*)&qs[lrow][lcol] = *(const float4*)(qbase + grow + lcol);
        *(float4*)&ks[lrow][lcol] = *(const float4*)(kbase + grow + lcol);
        __syncthreads();

        if (tid < 64) {
            #pragma unroll
            for (int tt = 0; tt < 16; tt++) {
                float v = qs[tt][tid]; sq += v; sqq += v * v;
            }
        } else if (tid < 128) {
            int j = tid - 64;
            #pragma unroll
            for (int tt = 0; tt < 16; tt++) {
                float v = ks[tt][j]; sk += v; skk += v * v;
            }
        }
        #pragma unroll
        for (int tt = 0; tt < 16; tt++) {
            float4 qa = *(const float4*)&qs[tt][i0];
            float4 kb = *(const float4*)&ks[tt][j0];
            float qv[4] = {qa.x, qa.y, qa.z, qa.w};
            float kv[4] = {kb.x, kb.y, kb.z, kb.w};
            #pragma unroll
            for (int ii = 0; ii < 4; ii++)
                #pragma unroll
                for (int jj = 0; jj < 4; jj++)
                    acc[ii][jj] += qv[ii] * kv[jj];
        }
        __syncthreads();
    }

    float* st = g_stats + (size_t)head * STATS_PER_HEAD;
    #pragma unroll
    for (int ii = 0; ii < 4; ii++)
        #pragma unroll
        for (int jj = 0; jj < 4; jj++)
            atomicAdd(&st[(i0 + ii) * HD + (j0 + jj)], acc[ii][jj]);
    if (tid < 64) {
        atomicAdd(&st[4096 + tid], sq);
        atomicAdd(&st[4224 + tid], sqq);
    } else if (tid < 128) {
        atomicAdd(&st[4160 + (tid - 64)], sk);
        atomicAdd(&st[4288 + (tid - 64)], skk);
    }
}

// ===========================================================================
// Corr: corr = softmax_i(clip(cov/sqrt(sx*sy),0,1))
// ===========================================================================
__global__ __launch_bounds__(256) void corr_kernel() {
    const int head = blockIdx.x;
    const int tid = threadIdx.x;
    __shared__ float sc[HD][HD + 1];
    __shared__ float mq[HD], mk[HD], isx[HD], isy[HD];

    const float* st = g_stats + (size_t)head * STATS_PER_HEAD;
    const float invT = 1.0f / (float)T_LEN;

    if (tid < 64) {
        float s = st[4096 + tid], s2 = st[4224 + tid];
        mq[tid] = s;
        isx[tid] = rsqrtf(s2 - s * s * invT);
    } else if (tid < 128) {
        int j = tid - 64;
        float s = st[4160 + j], s2 = st[4288 + j];
        mk[j] = s;
        isy[j] = rsqrtf(s2 - s * s * invT);
    }
    __syncthreads();

    for (int idx = tid; idx < HD * HD; idx += 256) {
        int i = idx >> 6, j = idx & 63;
        float cov = st[idx] - mq[i] * mk[j] * invT;
        float c = cov * isx[i] * isy[j];
        c = fminf(fmaxf(c, 0.0f), 1.0f);
        sc[i][j] = c;
    }
    __syncthreads();

    if (tid < 64) {
        int j = tid;
        float mx = -1e30f;
        #pragma unroll 4
        for (int i = 0; i < HD; i++) mx = fmaxf(mx, sc[i][j]);
        float sum = 0.f;
        #pragma unroll 4
        for (int i = 0; i < HD; i++) {
            float e = expf(sc[i][j] - mx);
            sc[i][j] = e; sum += e;
        }
        float inv = 1.0f / sum;
        #pragma unroll 4
        for (int i = 0; i < HD; i++) sc[i][j] *= inv;
    }
    __syncthreads();

    for (int idx = tid; idx < HD * HD; idx += 256)
        g_corr[(size_t)head * HD * HD + idx] = sc[idx >> 6][idx & 63];
}

// ===========================================================================
// Meff: Meff^T[b][o][h*64+d] = sum_e corr[b,h][d][e] * Wout[o][h*64+e]
// Emitted directly as fp16 for GEMM2's B operand.
// ===========================================================================
__global__ __launch_bounds__(256) void meff_kernel(const float* __restrict__ Wout) {
    const int head = blockIdx.x;
    const int b = head >> 4, h = head & 15;
    const int tid = threadIdx.x;
    __shared__ float sc[HD][HD + 1];

    for (int idx = tid; idx < HD * HD; idx += 256)
        sc[idx >> 6][idx & 63] = g_corr[(size_t)head * HD * HD + idx];
    __syncthreads();

    const size_t mbase = (size_t)b * D_MODEL * D_MODEL + h * HD;
    const float* Wb = Wout + h * HD;

    for (int idx = tid; idx < D_MODEL * HD; idx += 256) {
        int o = idx >> 6, d = idx & 63;
        const float* wrow = Wb + (size_t)o * D_MODEL;
        float s = 0.f;
        #pragma unroll
        for (int e = 0; e < HD; e++) s += sc[d][e] * wrow[e];
        g_mh[mbase + (size_t)o * D_MODEL + d] = __float2half_rn(s);
    }
}

// ===========================================================================
// Launch
// ===========================================================================
extern "C" void kernel_launch(void* const* d_in, const int* in_sizes, int n_in,
                              void* d_out, int out_size) {
    const float* query = (const float*)d_in[0];
    const float* Wqkv  = (const float*)d_in[1];
    const float* bqkv  = (const float*)d_in[2];
    const float* Wout  = (const float*)d_in[3];
    const float* bout  = (const float*)d_in[4];
    float* out = (float*)d_out;

    void* p;
    cudaGetSymbolAddress(&p, g_qkv);  float*  qkv = (float*)p;
    cudaGetSymbolAddress(&p, g_qh);   __half* qh  = (__half*)p;
    cudaGetSymbolAddress(&p, g_wh);   __half* wh  = (__half*)p;
    cudaGetSymbolAddress(&p, g_vh);   __half* vh  = (__half*)p;
    cudaGetSymbolAddress(&p, g_mh);   __half* mh  = (__half*)p;

    cudaFuncSetAttribute(gemm_fp16_kernel,
                         cudaFuncAttributeMaxDynamicSharedMemorySize, SMEMB);

    // 0. zero stats accumulator
    {
        int total = NHEADS_TOTAL * STATS_PER_HEAD;
        zero_stats_kernel<<<(total + 1023) / 1024, 1024>>>();
    }

    // 1. converters: query -> fp16, Wqkv -> fp16
    {
        int n4q = NROWS * D_MODEL / 4;      // 8388608
        conv_half_kernel<<<n4q / 256, 256>>>(query, qh, n4q);
        int n4w = QKV_LD * D_MODEL / 4;     // 786432
        conv_half_kernel<<<n4w / 256, 256>>>(Wqkv, wh, n4w);
    }

    // 2. GEMM1: qkv = query @ Wqkv^T + bqkv. q,k -> fp32 g_qkv; v -> fp16.
    gemm_fp16_kernel<<<dim3(QKV_LD / BN, NROWS / BM, 1), NTHR, SMEMB>>>(
        qh, D_MODEL, 0,
        wh, D_MODEL, 0,
        bqkv,
        qkv, QKV_LD, 0,
        vh,
        D_MODEL);

    // 3. per-head stats
    stats_kernel<<<dim3(TSPLIT, NHEADS_TOTAL), 256>>>(qkv);

    // 4. correlation + softmax
    corr_kernel<<<NHEADS_TOTAL, 256>>>();

    // 5. Meff_b = blockdiag(corr_b) @ Wout^T  (fp16)
    meff_kernel<<<NHEADS_TOTAL, 256>>>(Wout);

    // 6. out = v @ Meff_b^T + bout   per batch z
    gemm_fp16_kernel<<<dim3(D_MODEL / BN, T_LEN / BM, BATCH), NTHR, SMEMB>>>(
        vh, BATCH * D_MODEL, D_MODEL,
        mh, D_MODEL, (long long)D_MODEL * D_MODEL,
        bout,
        out, BATCH * D_MODEL, D_MODEL,
        nullptr,
        D_MODEL);
}

// round 8
// speedup vs baseline: 1.0060x; 1.0060x over previous
#include <cuda_runtime.h>
#include <cuda_fp16.h>
#include <cstdint>

// Problem constants
#define T_LEN   8192
#define BATCH   4
#define D_MODEL 1024
#define NHEAD   16
#define HD      64
#define QKV_LD  (3 * D_MODEL)        // 3072
#define NROWS   (T_LEN * BATCH)      // 32768
#define NHEADS_TOTAL (BATCH * NHEAD) // 64
#define STATS_PER_HEAD 4352

// Scratch (device globals: allocation-free)
__device__ __half g_qkvh[(size_t)NROWS * QKV_LD];                // 192 MB q,k,v fp16
__device__ __half g_qh[(size_t)NROWS * D_MODEL];                 // 64 MB  query fp16
__device__ __half g_wh[(size_t)QKV_LD * D_MODEL];                // 6 MB   Wqkv fp16
__device__ __half g_mh[(size_t)BATCH * D_MODEL * D_MODEL];       // 8 MB  Meff fp16
__device__ float  g_stats[NHEADS_TOTAL * STATS_PER_HEAD];
__device__ float  g_corr[NHEADS_TOTAL * HD * HD];

// ===========================================================================
// helpers
// ===========================================================================
__device__ __forceinline__ uint32_t smem_to_u32(const void* p) {
    uint32_t a;
    asm("{ .reg .u64 t; cvta.to.shared.u64 t, %1; cvt.u32.u64 %0, t; }"
        : "=r"(a) : "l"(p));
    return a;
}

__device__ __forceinline__ void ldsm4(uint32_t (&r)[4], uint32_t addr) {
    asm volatile("ldmatrix.sync.aligned.m8n8.x4.shared.b16 {%0,%1,%2,%3}, [%4];"
        : "=r"(r[0]), "=r"(r[1]), "=r"(r[2]), "=r"(r[3]) : "r"(addr));
}

__device__ __forceinline__ void mma16816(float (&c)[4], const uint32_t (&a)[4],
                                         uint32_t b0, uint32_t b1) {
    asm volatile(
        "mma.sync.aligned.m16n8k16.row.col.f32.f16.f16.f32 "
        "{%0,%1,%2,%3}, {%4,%5,%6,%7}, {%8,%9}, {%0,%1,%2,%3};"
        : "+f"(c[0]), "+f"(c[1]), "+f"(c[2]), "+f"(c[3])
        : "r"(a[0]), "r"(a[1]), "r"(a[2]), "r"(a[3]), "r"(b0), "r"(b1));
}

#define CP_COMMIT() asm volatile("cp.async.commit_group;" ::: "memory")
#define CP16(dst, src) \
    asm volatile("cp.async.cg.shared.global [%0], [%1], 16;" \
        :: "r"(dst), "l"(src) : "memory")

// ===========================================================================
// fp16 single-pass HMMA GEMM (NT): C[m,n] = sum_k A[m,k]*B[n,k] + bias[n]
// 256x128x32 CTA tile, 8 warps (4x2), warp tile 64x64. 256 threads.
// 4-stage cp.async pipeline. smem rows 80B (conflict-free ldmatrix).
// If Ch != null: entire output written as fp16 to Ch (stride strideC).
// Else: fp32 to C.
// ===========================================================================
#define BM 256
#define BN 128
#define BK 32
#define NTHR 256
#define ROWB 80
#define A_TILEB (256 * ROWB)    // 20480
#define B_TILEB (128 * ROWB)    // 10240
#define OFF_A  0
#define OFF_B  A_TILEB
#define STAGEB (A_TILEB + B_TILEB)      // 30720
#define NSTAGE 4
#define SMEMB (NSTAGE * STAGEB)         // 122880

__global__ void __launch_bounds__(NTHR, 1) gemm_fp16_kernel(
    const __half* __restrict__ Ah, int strideA, long long batchA,
    const __half* __restrict__ Bh, int strideB, long long batchB,
    const float* __restrict__ bias,
    float* __restrict__ C, __half* __restrict__ Ch,
    int strideC, long long batchC,
    int K)
{
    extern __shared__ char smem[];
    const uint32_t sb = smem_to_u32(smem);
    const int tid = threadIdx.x;
    const int lane = tid & 31;
    const int wid = tid >> 5;         // 0..7
    const int wm = (wid >> 1) * 64;   // 0,64,128,192
    const int wn = (wid & 1) * 64;    // 0,64
    const int z = blockIdx.z;

    const __half* Ab = Ah + (size_t)blockIdx.y * BM * strideA + (size_t)z * batchA;
    const __half* Bb = Bh + (size_t)blockIdx.x * BN * strideB + (size_t)z * batchB;

    float acc[4][8][4];
    #pragma unroll
    for (int mt = 0; mt < 4; mt++)
        #pragma unroll
        for (int nt = 0; nt < 8; nt++)
            #pragma unroll
            for (int r = 0; r < 4; r++) acc[mt][nt][r] = 0.0f;

    const int NKT = K / BK;

    // 6 x 16B cp.async per thread per stage:
    // i<4 -> A (1024 chunks: 256 rows x 4), i=4,5 -> B (512 chunks)
    #define ISSUE_STAGE(kt, buf) do { \
        const uint32_t sbase = sb + (buf) * STAGEB; \
        _Pragma("unroll") \
        for (int i = 0; i < 6; i++) { \
            const int ci = i * NTHR + tid; \
            const __half* src; uint32_t dst; \
            if (i < 4) { \
                const int r_ = ci >> 2, c_ = ci & 3; \
                src = Ab + (size_t)r_ * strideA + (kt) * BK + c_ * 8; \
                dst = sbase + OFF_A + r_ * ROWB + c_ * 16; \
            } else { \
                const int j_ = ci - 1024, r_ = j_ >> 2, c_ = j_ & 3; \
                src = Bb + (size_t)r_ * strideB + (kt) * BK + c_ * 8; \
                dst = sbase + OFF_B + r_ * ROWB + c_ * 16; \
            } \
            CP16(dst, src); \
        } \
    } while (0)

    ISSUE_STAGE(0, 0); CP_COMMIT();
    ISSUE_STAGE(1, 1); CP_COMMIT();
    ISSUE_STAGE(2, 2); CP_COMMIT();

    // frag address components (constant per thread)
    const uint32_t a_off = (uint32_t)((lane & 15) * ROWB + (lane >> 4) * 16);
    const uint32_t b_row = (uint32_t)((lane & 7) + ((lane >> 4) << 3));
    const uint32_t b_off = (uint32_t)(b_row * ROWB + ((lane >> 3) & 1) * 16);

    for (int kt = 0; kt < NKT; kt++) {
        asm volatile("cp.async.wait_group 2;" ::: "memory");
        __syncthreads();

        if (kt + 3 < NKT) { ISSUE_STAGE(kt + 3, (kt + 3) % NSTAGE); CP_COMMIT(); }

        const uint32_t base = sb + (kt % NSTAGE) * STAGEB;
        #pragma unroll
        for (int kk = 0; kk < 2; kk++) {
            const uint32_t koff = kk * 32;
            uint32_t a[4][4];
            #pragma unroll
            for (int mt = 0; mt < 4; mt++)
                ldsm4(a[mt], base + OFF_A + (wm + mt * 16) * ROWB + a_off + koff);
            #pragma unroll
            for (int ng = 0; ng < 4; ng++) {
                uint32_t bh[4];
                ldsm4(bh, base + OFF_B + (wn + ng * 16) * ROWB + b_off + koff);
                #pragma unroll
                for (int mt = 0; mt < 4; mt++) {
                    mma16816(acc[mt][2*ng],   a[mt], bh[0], bh[1]);
                    mma16816(acc[mt][2*ng+1], a[mt], bh[2], bh[3]);
                }
            }
        }
    }

    // ---- epilogue ----
    const int rbase = blockIdx.y * BM + wm + (lane >> 2);
    const int cbase = blockIdx.x * BN + wn + (lane & 3) * 2;
    #pragma unroll
    for (int mt = 0; mt < 4; mt++) {
        #pragma unroll
        for (int nt = 0; nt < 8; nt++) {
            const int row = rbase + mt * 16;
            const int col = cbase + nt * 8;
            const float b0 = bias[col], b1 = bias[col + 1];
            const float v0 = acc[mt][nt][0] + b0, v1 = acc[mt][nt][1] + b1;
            const float v2 = acc[mt][nt][2] + b0, v3 = acc[mt][nt][3] + b1;
            if (Ch != nullptr) {
                *(__half2*)(Ch + (size_t)row * strideC + col)       = __floats2half2_rn(v0, v1);
                *(__half2*)(Ch + (size_t)(row + 8) * strideC + col) = __floats2half2_rn(v2, v3);
            } else {
                float* Cz = C + (size_t)z * batchC;
                float2 o0, o1;
                o0.x = v0; o0.y = v1; o1.x = v2; o1.y = v3;
                *(float2*)(Cz + (size_t)row * strideC + col) = o0;
                *(float2*)(Cz + (size_t)(row + 8) * strideC + col) = o1;
            }
        }
    }
}

// ===========================================================================
// Converter: fp32 -> fp16
// ===========================================================================
__global__ void conv_half_kernel(const float* __restrict__ in,
                                 __half* __restrict__ outh, int n4) {
    int idx = blockIdx.x * blockDim.x + threadIdx.x;
    if (idx < n4) {
        float4 v = ((const float4*)in)[idx];
        ((__half2*)outh)[2 * idx]     = __floats2half2_rn(v.x, v.y);
        ((__half2*)outh)[2 * idx + 1] = __floats2half2_rn(v.z, v.w);
    }
}

// ===========================================================================
// Zero the stats accumulator
// ===========================================================================
__global__ void zero_stats_kernel() {
    int idx = blockIdx.x * blockDim.x + threadIdx.x;
    if (idx < NHEADS_TOTAL * STATS_PER_HEAD) g_stats[idx] = 0.0f;
}

// ===========================================================================
// Stats: per head (b,h) accumulate C[i][j]=sum_t q_i k_j, Sq, Sk, Sqq, Skk
// Reads fp16 qkv, accumulates fp32.
// ===========================================================================
#define TSPLIT 8
#define TCHUNK (T_LEN / TSPLIT)   // 1024

__global__ __launch_bounds__(256) void stats_kernel(const __half* __restrict__ qkvh) {
    const int head = blockIdx.y;
    const int b = head >> 4, h = head & 15;
    const int tid = threadIdx.x;

    __shared__ float qs[16][HD];
    __shared__ float ks[16][HD];

    const __half* qbase = qkvh + (size_t)b * QKV_LD + h * HD;
    const __half* kbase = qbase + D_MODEL;

    float acc[4][4];
    #pragma unroll
    for (int i = 0; i < 4; i++)
        #pragma unroll
        for (int j = 0; j < 4; j++) acc[i][j] = 0.0f;
    float sq = 0.f, sqq = 0.f, sk = 0.f, skk = 0.f;

    const int i0 = (tid >> 4) * 4, j0 = (tid & 15) * 4;
    const int lrow = tid >> 4;
    const int lcol = (tid & 15) * 4;

    const int tstart = blockIdx.x * TCHUNK;
    for (int t0 = tstart; t0 < tstart + TCHUNK; t0 += 16) {
        size_t grow = (size_t)(t0 + lrow) * BATCH * QKV_LD;
        {
            uint2 qa = *(const uint2*)(qbase + grow + lcol);
            uint2 kb = *(const uint2*)(kbase + grow + lcol);
            float2 q0 = __half22float2(*(__half2*)&qa.x);
            float2 q1 = __half22float2(*(__half2*)&qa.y);
            float2 k0 = __half22float2(*(__half2*)&kb.x);
            float2 k1 = __half22float2(*(__half2*)&kb.y);
            qs[lrow][lcol] = q0.x; qs[lrow][lcol + 1] = q0.y;
            qs[lrow][lcol + 2] = q1.x; qs[lrow][lcol + 3] = q1.y;
            ks[lrow][lcol] = k0.x; ks[lrow][lcol + 1] = k0.y;
            ks[lrow][lcol + 2] = k1.x; ks[lrow][lcol + 3] = k1.y;
        }
        __syncthreads();

        if (tid < 64) {
            #pragma unroll
            for (int tt = 0; tt < 16; tt++) {
                float v = qs[tt][tid]; sq += v; sqq += v * v;
            }
        } else if (tid < 128) {
            int j = tid - 64;
            #pragma unroll
            for (int tt = 0; tt < 16; tt++) {
                float v = ks[tt][j]; sk += v; skk += v * v;
            }
        }
        #pragma unroll
        for (int tt = 0; tt < 16; tt++) {
            float4 qa = *(const float4*)&qs[tt][i0];
            float4 kb = *(const float4*)&ks[tt][j0];
            float qv[4] = {qa.x, qa.y, qa.z, qa.w};
            float kv[4] = {kb.x, kb.y, kb.z, kb.w};
            #pragma unroll
            for (int ii = 0; ii < 4; ii++)
                #pragma unroll
                for (int jj = 0; jj < 4; jj++)
                    acc[ii][jj] += qv[ii] * kv[jj];
        }
        __syncthreads();
    }

    float* st = g_stats + (size_t)head * STATS_PER_HEAD;
    #pragma unroll
    for (int ii = 0; ii < 4; ii++)
        #pragma unroll
        for (int jj = 0; jj < 4; jj++)
            atomicAdd(&st[(i0 + ii) * HD + (j0 + jj)], acc[ii][jj]);
    if (tid < 64) {
        atomicAdd(&st[4096 + tid], sq);
        atomicAdd(&st[4224 + tid], sqq);
    } else if (tid < 128) {
        atomicAdd(&st[4160 + (tid - 64)], sk);
        atomicAdd(&st[4288 + (tid - 64)], skk);
    }
}

// ===========================================================================
// Corr: corr = softmax_i(clip(cov/sqrt(sx*sy),0,1))
// ===========================================================================
__global__ __launch_bounds__(256) void corr_kernel() {
    const int head = blockIdx.x;
    const int tid = threadIdx.x;
    __shared__ float sc[HD][HD + 1];
    __shared__ float mq[HD], mk[HD], isx[HD], isy[HD];

    const float* st = g_stats + (size_t)head * STATS_PER_HEAD;
    const float invT = 1.0f / (float)T_LEN;

    if (tid < 64) {
        float s = st[4096 + tid], s2 = st[4224 + tid];
        mq[tid] = s;
        isx[tid] = rsqrtf(s2 - s * s * invT);
    } else if (tid < 128) {
        int j = tid - 64;
        float s = st[4160 + j], s2 = st[4288 + j];
        mk[j] = s;
        isy[j] = rsqrtf(s2 - s * s * invT);
    }
    __syncthreads();

    for (int idx = tid; idx < HD * HD; idx += 256) {
        int i = idx >> 6, j = idx & 63;
        float cov = st[idx] - mq[i] * mk[j] * invT;
        float c = cov * isx[i] * isy[j];
        c = fminf(fmaxf(c, 0.0f), 1.0f);
        sc[i][j] = c;
    }
    __syncthreads();

    if (tid < 64) {
        int j = tid;
        float mx = -1e30f;
        #pragma unroll 4
        for (int i = 0; i < HD; i++) mx = fmaxf(mx, sc[i][j]);
        float sum = 0.f;
        #pragma unroll 4
        for (int i = 0; i < HD; i++) {
            float e = expf(sc[i][j] - mx);
            sc[i][j] = e; sum += e;
        }
        float inv = 1.0f / sum;
        #pragma unroll 4
        for (int i = 0; i < HD; i++) sc[i][j] *= inv;
    }
    __syncthreads();

    for (int idx = tid; idx < HD * HD; idx += 256)
        g_corr[(size_t)head * HD * HD + idx] = sc[idx >> 6][idx & 63];
}

// ===========================================================================
// Meff: Meff^T[b][o][h*64+d] = sum_e corr[b,h][d][e] * Wout[o][h*64+e]
// Emitted directly as fp16 for GEMM2's B operand.
// ===========================================================================
__global__ __launch_bounds__(256) void meff_kernel(const float* __restrict__ Wout) {
    const int head = blockIdx.x;
    const int b = head >> 4, h = head & 15;
    const int tid = threadIdx.x;
    __shared__ float sc[HD][HD + 1];

    for (int idx = tid; idx < HD * HD; idx += 256)
        sc[idx >> 6][idx & 63] = g_corr[(size_t)head * HD * HD + idx];
    __syncthreads();

    const size_t mbase = (size_t)b * D_MODEL * D_MODEL + h * HD;
    const float* Wb = Wout + h * HD;

    for (int idx = tid; idx < D_MODEL * HD; idx += 256) {
        int o = idx >> 6, d = idx & 63;
        const float* wrow = Wb + (size_t)o * D_MODEL;
        float s = 0.f;
        #pragma unroll
        for (int e = 0; e < HD; e++) s += sc[d][e] * wrow[e];
        g_mh[mbase + (size_t)o * D_MODEL + d] = __float2half_rn(s);
    }
}

// ===========================================================================
// Launch
// ===========================================================================
extern "C" void kernel_launch(void* const* d_in, const int* in_sizes, int n_in,
                              void* d_out, int out_size) {
    const float* query = (const float*)d_in[0];
    const float* Wqkv  = (const float*)d_in[1];
    const float* bqkv  = (const float*)d_in[2];
    const float* Wout  = (const float*)d_in[3];
    const float* bout  = (const float*)d_in[4];
    float* out = (float*)d_out;

    void* p;
    cudaGetSymbolAddress(&p, g_qkvh); __half* qkvh = (__half*)p;
    cudaGetSymbolAddress(&p, g_qh);   __half* qh   = (__half*)p;
    cudaGetSymbolAddress(&p, g_wh);   __half* wh   = (__half*)p;
    cudaGetSymbolAddress(&p, g_mh);   __half* mh   = (__half*)p;

    cudaFuncSetAttribute(gemm_fp16_kernel,
                         cudaFuncAttributeMaxDynamicSharedMemorySize, SMEMB);

    // 0. zero stats accumulator
    {
        int total = NHEADS_TOTAL * STATS_PER_HEAD;
        zero_stats_kernel<<<(total + 1023) / 1024, 1024>>>();
    }

    // 1. converters: query -> fp16, Wqkv -> fp16
    {
        int n4q = NROWS * D_MODEL / 4;      // 8388608
        conv_half_kernel<<<n4q / 256, 256>>>(query, qh, n4q);
        int n4w = QKV_LD * D_MODEL / 4;     // 786432
        conv_half_kernel<<<n4w / 256, 256>>>(Wqkv, wh, n4w);
    }

    // 2. GEMM1: qkv = query @ Wqkv^T + bqkv -> fp16 qkvh (q,k,v all fp16)
    gemm_fp16_kernel<<<dim3(QKV_LD / BN, NROWS / BM, 1), NTHR, SMEMB>>>(
        qh, D_MODEL, 0,
        wh, D_MODEL, 0,
        bqkv,
        nullptr, qkvh, QKV_LD, 0,
        D_MODEL);

    // 3. per-head stats (fp16 input)
    stats_kernel<<<dim3(TSPLIT, NHEADS_TOTAL), 256>>>(qkvh);

    // 4. correlation + softmax
    corr_kernel<<<NHEADS_TOTAL, 256>>>();

    // 5. Meff_b = blockdiag(corr_b) @ Wout^T  (fp16)
    meff_kernel<<<NHEADS_TOTAL, 256>>>(Wout);

    // 6. out = v @ Meff_b^T + bout   per batch z (v = qkvh + 2048, fp16)
    gemm_fp16_kernel<<<dim3(D_MODEL / BN, T_LEN / BM, BATCH), NTHR, SMEMB>>>(
        qkvh + 2 * D_MODEL, BATCH * QKV_LD, QKV_LD,
        mh, D_MODEL, (long long)D_MODEL * D_MODEL,
        bout,
        out, nullptr, BATCH * D_MODEL, D_MODEL,
        D_MODEL);
}

// round 9
// speedup vs baseline: 1.0538x; 1.0475x over previous
#include <cuda_runtime.h>
#include <cuda_fp16.h>
#include <cstdint>

// Problem constants
#define T_LEN   8192
#define BATCH   4
#define D_MODEL 1024
#define NHEAD   16
#define HD      64
#define QKV_LD  (3 * D_MODEL)        // 3072
#define NROWS   (T_LEN * BATCH)      // 32768
#define NHEADS_TOTAL (BATCH * NHEAD) // 64
#define STATS_PER_HEAD 4352

// Scratch (device globals: allocation-free)
__device__ __half g_qkvh[(size_t)NROWS * QKV_LD];                // 192 MB q,k,v fp16
__device__ __half g_qh[(size_t)NROWS * D_MODEL];                 // 64 MB  query fp16
__device__ __half g_wh[(size_t)QKV_LD * D_MODEL];                // 6 MB   Wqkv fp16
__device__ __half g_mh[(size_t)BATCH * D_MODEL * D_MODEL];       // 8 MB  Meff fp16
__device__ float  g_stats[NHEADS_TOTAL * STATS_PER_HEAD];

// ===========================================================================
// helpers
// ===========================================================================
__device__ __forceinline__ uint32_t smem_to_u32(const void* p) {
    uint32_t a;
    asm("{ .reg .u64 t; cvta.to.shared.u64 t, %1; cvt.u32.u64 %0, t; }"
        : "=r"(a) : "l"(p));
    return a;
}

__device__ __forceinline__ void ldsm4(uint32_t (&r)[4], uint32_t addr) {
    asm volatile("ldmatrix.sync.aligned.m8n8.x4.shared.b16 {%0,%1,%2,%3}, [%4];"
        : "=r"(r[0]), "=r"(r[1]), "=r"(r[2]), "=r"(r[3]) : "r"(addr));
}

__device__ __forceinline__ void ldsm4t(uint32_t (&r)[4], uint32_t addr) {
    asm volatile("ldmatrix.sync.aligned.m8n8.x4.trans.shared.b16 {%0,%1,%2,%3}, [%4];"
        : "=r"(r[0]), "=r"(r[1]), "=r"(r[2]), "=r"(r[3]) : "r"(addr));
}

__device__ __forceinline__ void mma16816(float (&c)[4], const uint32_t (&a)[4],
                                         uint32_t b0, uint32_t b1) {
    asm volatile(
        "mma.sync.aligned.m16n8k16.row.col.f32.f16.f16.f32 "
        "{%0,%1,%2,%3}, {%4,%5,%6,%7}, {%8,%9}, {%0,%1,%2,%3};"
        : "+f"(c[0]), "+f"(c[1]), "+f"(c[2]), "+f"(c[3])
        : "r"(a[0]), "r"(a[1]), "r"(a[2]), "r"(a[3]), "r"(b0), "r"(b1));
}

#define CP_COMMIT() asm volatile("cp.async.commit_group;" ::: "memory")
#define CP16(dst, src) \
    asm volatile("cp.async.cg.shared.global [%0], [%1], 16;" \
        :: "r"(dst), "l"(src) : "memory")

// ===========================================================================
// fp16 single-pass HMMA GEMM (NT): C[m,n] = sum_k A[m,k]*B[n,k] + bias[n]
// 256x128x32 CTA tile, 8 warps (4x2), warp tile 64x64. 256 threads.
// (unchanged from R8 — at the mma.sync issue-rate ceiling)
// ===========================================================================
#define BM 256
#define BN 128
#define BK 32
#define NTHR 256
#define ROWB 80
#define A_TILEB (256 * ROWB)    // 20480
#define B_TILEB (128 * ROWB)    // 10240
#define OFF_A  0
#define OFF_B  A_TILEB
#define STAGEB (A_TILEB + B_TILEB)      // 30720
#define NSTAGE 4
#define SMEMB (NSTAGE * STAGEB)         // 122880

__global__ void __launch_bounds__(NTHR, 1) gemm_fp16_kernel(
    const __half* __restrict__ Ah, int strideA, long long batchA,
    const __half* __restrict__ Bh, int strideB, long long batchB,
    const float* __restrict__ bias,
    float* __restrict__ C, __half* __restrict__ Ch,
    int strideC, long long batchC,
    int K)
{
    extern __shared__ char smem[];
    const uint32_t sb = smem_to_u32(smem);
    const int tid = threadIdx.x;
    const int lane = tid & 31;
    const int wid = tid >> 5;         // 0..7
    const int wm = (wid >> 1) * 64;   // 0,64,128,192
    const int wn = (wid & 1) * 64;    // 0,64
    const int z = blockIdx.z;

    const __half* Ab = Ah + (size_t)blockIdx.y * BM * strideA + (size_t)z * batchA;
    const __half* Bb = Bh + (size_t)blockIdx.x * BN * strideB + (size_t)z * batchB;

    float acc[4][8][4];
    #pragma unroll
    for (int mt = 0; mt < 4; mt++)
        #pragma unroll
        for (int nt = 0; nt < 8; nt++)
            #pragma unroll
            for (int r = 0; r < 4; r++) acc[mt][nt][r] = 0.0f;

    const int NKT = K / BK;

    #define ISSUE_STAGE(kt, buf) do { \
        const uint32_t sbase = sb + (buf) * STAGEB; \
        _Pragma("unroll") \
        for (int i = 0; i < 6; i++) { \
            const int ci = i * NTHR + tid; \
            const __half* src; uint32_t dst; \
            if (i < 4) { \
                const int r_ = ci >> 2, c_ = ci & 3; \
                src = Ab + (size_t)r_ * strideA + (kt) * BK + c_ * 8; \
                dst = sbase + OFF_A + r_ * ROWB + c_ * 16; \
            } else { \
                const int j_ = ci - 1024, r_ = j_ >> 2, c_ = j_ & 3; \
                src = Bb + (size_t)r_ * strideB + (kt) * BK + c_ * 8; \
                dst = sbase + OFF_B + r_ * ROWB + c_ * 16; \
            } \
            CP16(dst, src); \
        } \
    } while (0)

    ISSUE_STAGE(0, 0); CP_COMMIT();
    ISSUE_STAGE(1, 1); CP_COMMIT();
    ISSUE_STAGE(2, 2); CP_COMMIT();

    const uint32_t a_off = (uint32_t)((lane & 15) * ROWB + (lane >> 4) * 16);
    const uint32_t b_row = (uint32_t)((lane & 7) + ((lane >> 4) << 3));
    const uint32_t b_off = (uint32_t)(b_row * ROWB + ((lane >> 3) & 1) * 16);

    for (int kt = 0; kt < NKT; kt++) {
        asm volatile("cp.async.wait_group 2;" ::: "memory");
        __syncthreads();

        if (kt + 3 < NKT) { ISSUE_STAGE(kt + 3, (kt + 3) % NSTAGE); CP_COMMIT(); }

        const uint32_t base = sb + (kt % NSTAGE) * STAGEB;
        #pragma unroll
        for (int kk = 0; kk < 2; kk++) {
            const uint32_t koff = kk * 32;
            uint32_t a[4][4];
            #pragma unroll
            for (int mt = 0; mt < 4; mt++)
                ldsm4(a[mt], base + OFF_A + (wm + mt * 16) * ROWB + a_off + koff);
            #pragma unroll
            for (int ng = 0; ng < 4; ng++) {
                uint32_t bh[4];
                ldsm4(bh, base + OFF_B + (wn + ng * 16) * ROWB + b_off + koff);
                #pragma unroll
                for (int mt = 0; mt < 4; mt++) {
                    mma16816(acc[mt][2*ng],   a[mt], bh[0], bh[1]);
                    mma16816(acc[mt][2*ng+1], a[mt], bh[2], bh[3]);
                }
            }
        }
    }

    // ---- epilogue ----
    const int rbase = blockIdx.y * BM + wm + (lane >> 2);
    const int cbase = blockIdx.x * BN + wn + (lane & 3) * 2;
    #pragma unroll
    for (int mt = 0; mt < 4; mt++) {
        #pragma unroll
        for (int nt = 0; nt < 8; nt++) {
            const int row = rbase + mt * 16;
            const int col = cbase + nt * 8;
            const float b0 = bias[col], b1 = bias[col + 1];
            const float v0 = acc[mt][nt][0] + b0, v1 = acc[mt][nt][1] + b1;
            const float v2 = acc[mt][nt][2] + b0, v3 = acc[mt][nt][3] + b1;
            if (Ch != nullptr) {
                *(__half2*)(Ch + (size_t)row * strideC + col)       = __floats2half2_rn(v0, v1);
                *(__half2*)(Ch + (size_t)(row + 8) * strideC + col) = __floats2half2_rn(v2, v3);
            } else {
                float* Cz = C + (size_t)z * batchC;
                float2 o0, o1;
                o0.x = v0; o0.y = v1; o1.x = v2; o1.y = v3;
                *(float2*)(Cz + (size_t)row * strideC + col) = o0;
                *(float2*)(Cz + (size_t)(row + 8) * strideC + col) = o1;
            }
        }
    }
}

// ===========================================================================
// Converter: fp32 -> fp16
// ===========================================================================
__global__ void conv_half_kernel(const float* __restrict__ in,
                                 __half* __restrict__ outh, int n4) {
    int idx = blockIdx.x * blockDim.x + threadIdx.x;
    if (idx < n4) {
        float4 v = ((const float4*)in)[idx];
        ((__half2*)outh)[2 * idx]     = __floats2half2_rn(v.x, v.y);
        ((__half2*)outh)[2 * idx + 1] = __floats2half2_rn(v.z, v.w);
    }
}

// ===========================================================================
// Zero the stats accumulator
// ===========================================================================
__global__ void zero_stats_kernel() {
    int idx = blockIdx.x * blockDim.x + threadIdx.x;
    if (idx < NHEADS_TOTAL * STATS_PER_HEAD) g_stats[idx] = 0.0f;
}

// ===========================================================================
// Tensor-core stats: per head (b,h):
//   C[i][j] = sum_t q[t,i]*k[t,j]  via mma (A = q^T, B-frag from [t][j] mem,
//   both through ldmatrix.x4.trans), plus Sq/Sqq/Sk/Skk via FFMA warps.
// grid (TSPLIT, 64). 256 threads: warps 0-3 mma (i-tile = 16*wid),
// warps 4-7 sums. smem: [t][i] tiles 16x72 halfs (144B rows), double buffered.
//
// trans-frag address derivation (lane l):
//  A-frag (q): mat0=T[t0-7][i0-7], mat1=T[t0-7][i8-15],
//              mat2=T[t8-15][i0-7], mat3=T[t8-15][i8-15]
//    addr = ((l&7)+((l>>4)<<3))*144 + (i0 + ((l>>3)&1)*8)*2
//  B-frag (k): mat0=T[t0-7][j0-7], mat1=T[t8-15][j0-7],
//              mat2=T[t0-7][j8-15], mat3=T[t8-15][j8-15]
//    addr = (l&15)*144 + ((l>>4)*8 + j0)*2
// ===========================================================================
#define TSPLIT 8
#define TCHUNK (T_LEN / TSPLIT)   // 1024
#define SRS    72                 // halfs per smem row (64 + 8 pad) = 144B
#define STILEB (16 * SRS * 2)     // 2304 bytes per tile
#define SSTG   (2 * STILEB)       // 4608 per stage (q + k)

__global__ __launch_bounds__(256) void stats_mma_kernel(const __half* __restrict__ qkvh) {
    const int head = blockIdx.y;
    const int b = head >> 4, h = head & 15;
    const int tid = threadIdx.x;
    const int lane = tid & 31;
    const int wid = tid >> 5;

    __shared__ __align__(16) char ssm[2 * SSTG];
    const uint32_t sb = smem_to_u32(ssm);

    const __half* qkbase = qkvh + (size_t)b * QKV_LD + h * HD;
    const int tstart = blockIdx.x * TCHUNK;

    // loader slot: t = tid>>4 (0-15), sub = tid&15 (sub<8 -> q, else k)
    const int lt = tid >> 4;
    const int sub = tid & 15;
    const size_t lsrc_off = (sub < 8 ? 0 : D_MODEL) + (sub & 7) * 8;
    const uint32_t ldst_off = (sub < 8 ? 0 : STILEB) + lt * 144 + (sub & 7) * 16;

    #define ST_ISSUE(s, buf) do { \
        const __half* src = qkbase \
            + (size_t)(tstart + (s) * 16 + lt) * (BATCH * QKV_LD) + lsrc_off; \
        CP16(sb + (buf) * SSTG + ldst_off, src); \
    } while (0)

    float acc[8][4];
    float s1 = 0.f, s2 = 0.f;
    #pragma unroll
    for (int nt = 0; nt < 8; nt++)
        #pragma unroll
        for (int r = 0; r < 4; r++) acc[nt][r] = 0.0f;

    // mma warp address components
    const uint32_t a_addr0 = (uint32_t)(((lane & 7) + ((lane >> 4) << 3)) * 144
                                        + (wid * 16 + ((lane >> 3) & 1) * 8) * 2);
    const uint32_t b_addr0 = (uint32_t)((lane & 15) * 144 + ((lane >> 4) * 8) * 2);

    // sum warp: i index and q/k select
    const int si = ((wid - 4) & 1) * 32 + lane;     // 0..63
    const uint32_t sum_tile = (wid < 6) ? 0u : (uint32_t)STILEB;

    const int NS = TCHUNK / 16;   // 64
    ST_ISSUE(0, 0); CP_COMMIT();

    for (int s = 0; s < NS; s++) {
        if (s + 1 < NS) {
            ST_ISSUE(s + 1, (s + 1) & 1); CP_COMMIT();
            asm volatile("cp.async.wait_group 1;" ::: "memory");
        } else {
            asm volatile("cp.async.wait_group 0;" ::: "memory");
        }
        __syncthreads();

        const uint32_t base = sb + (s & 1) * SSTG;
        if (wid < 4) {
            uint32_t a[4];
            ldsm4t(a, base + a_addr0);
            #pragma unroll
            for (int ng = 0; ng < 4; ng++) {
                uint32_t bb[4];
                ldsm4t(bb, base + STILEB + b_addr0 + ng * 32);  // j0 = 16*ng
                mma16816(acc[2*ng],   a, bb[0], bb[1]);
                mma16816(acc[2*ng+1], a, bb[2], bb[3]);
            }
        } else {
            const char* tp = ssm + (s & 1) * SSTG + sum_tile;
            #pragma unroll
            for (int t = 0; t < 16; t++) {
                float v = __half2float(*(const __half*)(tp + t * 144 + si * 2));
                s1 += v; s2 += v * v;
            }
        }
        __syncthreads();
    }

    float* st = g_stats + (size_t)head * STATS_PER_HEAD;
    if (wid < 4) {
        const int ib = wid * 16 + (lane >> 2);
        const int jb = 2 * (lane & 3);
        #pragma unroll
        for (int nt = 0; nt < 8; nt++) {
            const int j0 = 8 * nt + jb;
            atomicAdd(&st[ib * HD + j0],           acc[nt][0]);
            atomicAdd(&st[ib * HD + j0 + 1],       acc[nt][1]);
            atomicAdd(&st[(ib + 8) * HD + j0],     acc[nt][2]);
            atomicAdd(&st[(ib + 8) * HD + j0 + 1], acc[nt][3]);
        }
    } else if (wid < 6) {
        atomicAdd(&st[4096 + si], s1);
        atomicAdd(&st[4224 + si], s2);
    } else {
        atomicAdd(&st[4160 + si], s1);
        atomicAdd(&st[4288 + si], s2);
    }
}

// ===========================================================================
// Fused corr + meff: one CTA per head.
//   corr = softmax_i(clip(cov/sqrt(sx*sy),0,1)) held in smem, then
//   Meff^T[b][o][h*64+d] = sum_e corr[d][e] * Wout[o][h*64+e]  (fp16 out)
// ===========================================================================
__global__ __launch_bounds__(256) void corr_meff_kernel(const float* __restrict__ Wout) {
    const int head = blockIdx.x;
    const int b = head >> 4, h = head & 15;
    const int tid = threadIdx.x;
    __shared__ float sc[HD][HD + 1];
    __shared__ float mq[HD], mk[HD], isx[HD], isy[HD];

    const float* st = g_stats + (size_t)head * STATS_PER_HEAD;
    const float invT = 1.0f / (float)T_LEN;

    if (tid < 64) {
        float s = st[4096 + tid], s2 = st[4224 + tid];
        mq[tid] = s;
        isx[tid] = rsqrtf(s2 - s * s * invT);
    } else if (tid < 128) {
        int j = tid - 64;
        float s = st[4160 + j], s2 = st[4288 + j];
        mk[j] = s;
        isy[j] = rsqrtf(s2 - s * s * invT);
    }
    __syncthreads();

    for (int idx = tid; idx < HD * HD; idx += 256) {
        int i = idx >> 6, j = idx & 63;
        float cov = st[idx] - mq[i] * mk[j] * invT;
        float c = cov * isx[i] * isy[j];
        c = fminf(fmaxf(c, 0.0f), 1.0f);
        sc[i][j] = c;
    }
    __syncthreads();

    if (tid < 64) {
        int j = tid;
        float mx = -1e30f;
        #pragma unroll 4
        for (int i = 0; i < HD; i++) mx = fmaxf(mx, sc[i][j]);
        float sum = 0.f;
        #pragma unroll 4
        for (int i = 0; i < HD; i++) {
            float e = expf(sc[i][j] - mx);
            sc[i][j] = e; sum += e;
        }
        float inv = 1.0f / sum;
        #pragma unroll 4
        for (int i = 0; i < HD; i++) sc[i][j] *= inv;
    }
    __syncthreads();

    const size_t mbase = (size_t)b * D_MODEL * D_MODEL + h * HD;
    const float* Wb = Wout + h * HD;

    for (int idx = tid; idx < D_MODEL * HD; idx += 256) {
        int o = idx >> 6, d = idx & 63;
        const float* wrow = Wb + (size_t)o * D_MODEL;
        float s = 0.f;
        #pragma unroll
        for (int e = 0; e < HD; e++) s += sc[d][e] * wrow[e];
        g_mh[mbase + (size_t)o * D_MODEL + d] = __float2half_rn(s);
    }
}

// ===========================================================================
// Launch
// ===========================================================================
extern "C" void kernel_launch(void* const* d_in, const int* in_sizes, int n_in,
                              void* d_out, int out_size) {
    const float* query = (const float*)d_in[0];
    const float* Wqkv  = (const float*)d_in[1];
    const float* bqkv  = (const float*)d_in[2];
    const float* Wout  = (const float*)d_in[3];
    const float* bout  = (const float*)d_in[4];
    float* out = (float*)d_out;

    void* p;
    cudaGetSymbolAddress(&p, g_qkvh); __half* qkvh = (__half*)p;
    cudaGetSymbolAddress(&p, g_qh);   __half* qh   = (__half*)p;
    cudaGetSymbolAddress(&p, g_wh);   __half* wh   = (__half*)p;
    cudaGetSymbolAddress(&p, g_mh);   __half* mh   = (__half*)p;

    cudaFuncSetAttribute(gemm_fp16_kernel,
                         cudaFuncAttributeMaxDynamicSharedMemorySize, SMEMB);

    // 0. zero stats accumulator
    {
        int total = NHEADS_TOTAL * STATS_PER_HEAD;
        zero_stats_kernel<<<(total + 1023) / 1024, 1024>>>();
    }

    // 1. converters: query -> fp16, Wqkv -> fp16
    {
        int n4q = NROWS * D_MODEL / 4;      // 8388608
        conv_half_kernel<<<n4q / 256, 256>>>(query, qh, n4q);
        int n4w = QKV_LD * D_MODEL / 4;     // 786432
        conv_half_kernel<<<n4w / 256, 256>>>(Wqkv, wh, n4w);
    }

    // 2. GEMM1: qkv = query @ Wqkv^T + bqkv -> fp16 qkvh (q,k,v all fp16)
    gemm_fp16_kernel<<<dim3(QKV_LD / BN, NROWS / BM, 1), NTHR, SMEMB>>>(
        qh, D_MODEL, 0,
        wh, D_MODEL, 0,
        bqkv,
        nullptr, qkvh, QKV_LD, 0,
        D_MODEL);

    // 3. per-head stats (tensor cores)
    stats_mma_kernel<<<dim3(TSPLIT, NHEADS_TOTAL), 256>>>(qkvh);

    // 4. correlation + softmax + Meff (fused)
    corr_meff_kernel<<<NHEADS_TOTAL, 256>>>(Wout);

    // 5. out = v @ Meff_b^T + bout   per batch z (v = qkvh + 2048, fp16)
    gemm_fp16_kernel<<<dim3(D_MODEL / BN, T_LEN / BM, BATCH), NTHR, SMEMB>>>(
        qkvh + 2 * D_MODEL, BATCH * QKV_LD, QKV_LD,
        mh, D_MODEL, (long long)D_MODEL * D_MODEL,
        bout,
        out, nullptr, BATCH * D_MODEL, D_MODEL,
        D_MODEL);
}

// round 10
// speedup vs baseline: 1.0861x; 1.0307x over previous
#include <cuda_runtime.h>
#include <cuda_fp16.h>
#include <cstdint>

// Problem constants
#define T_LEN   8192
#define BATCH   4
#define D_MODEL 1024
#define NHEAD   16
#define HD      64
#define QKV_LD  (3 * D_MODEL)        // 3072
#define NROWS   (T_LEN * BATCH)      // 32768
#define NHEADS_TOTAL (BATCH * NHEAD) // 64
#define STATS_PER_HEAD 4352

// Scratch (device globals: allocation-free)
__device__ __half g_qh[(size_t)NROWS * D_MODEL];                 // 64 MB  query fp16
__device__ __half g_wh[(size_t)QKV_LD * D_MODEL];                // 6 MB   Wqkv fp16
__device__ __half g_vh[(size_t)NROWS * D_MODEL];                 // 64 MB  v fp16
__device__ __half g_mh[(size_t)BATCH * D_MODEL * D_MODEL];       // 8 MB   Meff fp16
__device__ __half g_G[(size_t)BATCH * D_MODEL * D_MODEL];        // 8 MB   Gram fp16
__device__ __half g_Ht[(size_t)BATCH * 2 * D_MODEL * D_MODEL];   // 16 MB  Wqk*G fp16
__device__ float  g_s[BATCH * D_MODEL];                          // col sums
__device__ float  g_zbias[D_MODEL];                              // zero bias (never written)
__device__ float  g_stats[NHEADS_TOTAL * STATS_PER_HEAD];

// ===========================================================================
// helpers
// ===========================================================================
__device__ __forceinline__ uint32_t smem_to_u32(const void* p) {
    uint32_t a;
    asm("{ .reg .u64 t; cvta.to.shared.u64 t, %1; cvt.u32.u64 %0, t; }"
        : "=r"(a) : "l"(p));
    return a;
}

__device__ __forceinline__ void ldsm4(uint32_t (&r)[4], uint32_t addr) {
    asm volatile("ldmatrix.sync.aligned.m8n8.x4.shared.b16 {%0,%1,%2,%3}, [%4];"
        : "=r"(r[0]), "=r"(r[1]), "=r"(r[2]), "=r"(r[3]) : "r"(addr));
}

__device__ __forceinline__ void ldsm4t(uint32_t (&r)[4], uint32_t addr) {
    asm volatile("ldmatrix.sync.aligned.m8n8.x4.trans.shared.b16 {%0,%1,%2,%3}, [%4];"
        : "=r"(r[0]), "=r"(r[1]), "=r"(r[2]), "=r"(r[3]) : "r"(addr));
}

__device__ __forceinline__ void mma16816(float (&c)[4], const uint32_t (&a)[4],
                                         uint32_t b0, uint32_t b1) {
    asm volatile(
        "mma.sync.aligned.m16n8k16.row.col.f32.f16.f16.f32 "
        "{%0,%1,%2,%3}, {%4,%5,%6,%7}, {%8,%9}, {%0,%1,%2,%3};"
        : "+f"(c[0]), "+f"(c[1]), "+f"(c[2]), "+f"(c[3])
        : "r"(a[0]), "r"(a[1]), "r"(a[2]), "r"(a[3]), "r"(b0), "r"(b1));
}

#define CP_COMMIT() asm volatile("cp.async.commit_group;" ::: "memory")
#define CP16(dst, src) \
    asm volatile("cp.async.cg.shared.global [%0], [%1], 16;" \
        :: "r"(dst), "l"(src) : "memory")

// ===========================================================================
// fp16 single-pass HMMA GEMM (NT): C[m,n] = sum_k A[m,k]*B[n,k] + bias[n]
// 256x128x32 CTA tile, 8 warps (4x2), warp tile 64x64. 256 threads.
// ===========================================================================
#define BM 256
#define BN 128
#define BK 32
#define NTHR 256
#define ROWB 80
#define A_TILEB (256 * ROWB)
#define B_TILEB (128 * ROWB)
#define OFF_A  0
#define OFF_B  A_TILEB
#define STAGEB (A_TILEB + B_TILEB)
#define NSTAGE 4
#define SMEMB (NSTAGE * STAGEB)         // 122880

__global__ void __launch_bounds__(NTHR, 1) gemm_fp16_kernel(
    const __half* __restrict__ Ah, int strideA, long long batchA,
    const __half* __restrict__ Bh, int strideB, long long batchB,
    const float* __restrict__ bias,
    float* __restrict__ C, __half* __restrict__ Ch,
    int strideC, long long batchC,
    int K)
{
    extern __shared__ char smem[];
    const uint32_t sb = smem_to_u32(smem);
    const int tid = threadIdx.x;
    const int lane = tid & 31;
    const int wid = tid >> 5;
    const int wm = (wid >> 1) * 64;
    const int wn = (wid & 1) * 64;
    const int z = blockIdx.z;

    const __half* Ab = Ah + (size_t)blockIdx.y * BM * strideA + (size_t)z * batchA;
    const __half* Bb = Bh + (size_t)blockIdx.x * BN * strideB + (size_t)z * batchB;

    float acc[4][8][4];
    #pragma unroll
    for (int mt = 0; mt < 4; mt++)
        #pragma unroll
        for (int nt = 0; nt < 8; nt++)
            #pragma unroll
            for (int r = 0; r < 4; r++) acc[mt][nt][r] = 0.0f;

    const int NKT = K / BK;

    #define ISSUE_STAGE(kt, buf) do { \
        const uint32_t sbase = sb + (buf) * STAGEB; \
        _Pragma("unroll") \
        for (int i = 0; i < 6; i++) { \
            const int ci = i * NTHR + tid; \
            const __half* src; uint32_t dst; \
            if (i < 4) { \
                const int r_ = ci >> 2, c_ = ci & 3; \
                src = Ab + (size_t)r_ * strideA + (kt) * BK + c_ * 8; \
                dst = sbase + OFF_A + r_ * ROWB + c_ * 16; \
            } else { \
                const int j_ = ci - 1024, r_ = j_ >> 2, c_ = j_ & 3; \
                src = Bb + (size_t)r_ * strideB + (kt) * BK + c_ * 8; \
                dst = sbase + OFF_B + r_ * ROWB + c_ * 16; \
            } \
            CP16(dst, src); \
        } \
    } while (0)

    ISSUE_STAGE(0, 0); CP_COMMIT();
    ISSUE_STAGE(1, 1); CP_COMMIT();
    ISSUE_STAGE(2, 2); CP_COMMIT();

    const uint32_t a_off = (uint32_t)((lane & 15) * ROWB + (lane >> 4) * 16);
    const uint32_t b_row = (uint32_t)((lane & 7) + ((lane >> 4) << 3));
    const uint32_t b_off = (uint32_t)(b_row * ROWB + ((lane >> 3) & 1) * 16);

    for (int kt = 0; kt < NKT; kt++) {
        asm volatile("cp.async.wait_group 2;" ::: "memory");
        __syncthreads();

        if (kt + 3 < NKT) { ISSUE_STAGE(kt + 3, (kt + 3) % NSTAGE); CP_COMMIT(); }

        const uint32_t base = sb + (kt % NSTAGE) * STAGEB;
        #pragma unroll
        for (int kk = 0; kk < 2; kk++) {
            const uint32_t koff = kk * 32;
            uint32_t a[4][4];
            #pragma unroll
            for (int mt = 0; mt < 4; mt++)
                ldsm4(a[mt], base + OFF_A + (wm + mt * 16) * ROWB + a_off + koff);
            #pragma unroll
            for (int ng = 0; ng < 4; ng++) {
                uint32_t bh[4];
                ldsm4(bh, base + OFF_B + (wn + ng * 16) * ROWB + b_off + koff);
                #pragma unroll
                for (int mt = 0; mt < 4; mt++) {
                    mma16816(acc[mt][2*ng],   a[mt], bh[0], bh[1]);
                    mma16816(acc[mt][2*ng+1], a[mt], bh[2], bh[3]);
                }
            }
        }
    }

    // ---- epilogue ----
    const int rbase = blockIdx.y * BM + wm + (lane >> 2);
    const int cbase = blockIdx.x * BN + wn + (lane & 3) * 2;
    #pragma unroll
    for (int mt = 0; mt < 4; mt++) {
        #pragma unroll
        for (int nt = 0; nt < 8; nt++) {
            const int row = rbase + mt * 16;
            const int col = cbase + nt * 8;
            const float b0 = bias[col], b1 = bias[col + 1];
            const float v0 = acc[mt][nt][0] + b0, v1 = acc[mt][nt][1] + b1;
            const float v2 = acc[mt][nt][2] + b0, v3 = acc[mt][nt][3] + b1;
            if (Ch != nullptr) {
                __half* Chz = Ch + (size_t)z * batchC;
                *(__half2*)(Chz + (size_t)row * strideC + col)       = __floats2half2_rn(v0, v1);
                *(__half2*)(Chz + (size_t)(row + 8) * strideC + col) = __floats2half2_rn(v2, v3);
            } else {
                float* Cz = C + (size_t)z * batchC;
                float2 o0, o1;
                o0.x = v0; o0.y = v1; o1.x = v2; o1.y = v3;
                *(float2*)(Cz + (size_t)row * strideC + col) = o0;
                *(float2*)(Cz + (size_t)(row + 8) * strideC + col) = o1;
            }
        }
    }
}

// ===========================================================================
// Converter: fp32 -> fp16
// ===========================================================================
__global__ void conv_half_kernel(const float* __restrict__ in,
                                 __half* __restrict__ outh, int n4) {
    int idx = blockIdx.x * blockDim.x + threadIdx.x;
    if (idx < n4) {
        float4 v = ((const float4*)in)[idx];
        ((__half2*)outh)[2 * idx]     = __floats2half2_rn(v.x, v.y);
        ((__half2*)outh)[2 * idx + 1] = __floats2half2_rn(v.z, v.w);
    }
}

// ===========================================================================
// zero g_s
// ===========================================================================
__global__ void zero_s_kernel() {
    int idx = blockIdx.x * blockDim.x + threadIdx.x;
    if (idx < BATCH * D_MODEL) g_s[idx] = 0.0f;
}

// ===========================================================================
// colsum: s_b[n] = sum_t X[(t*4+b)][n]   (X = qh fp16). grid (4, 4, 8).
// ===========================================================================
__global__ __launch_bounds__(256) void colsum_kernel(const __half* __restrict__ X) {
    const int n = blockIdx.x * 256 + threadIdx.x;
    const int b = blockIdx.y;
    const int t0 = blockIdx.z * (T_LEN / 8);
    float s = 0.f;
    const __half* p = X + (size_t)(t0 * BATCH + b) * D_MODEL + n;
    #pragma unroll 4
    for (int t = 0; t < T_LEN / 8; t++)
        s += __half2float(p[(size_t)t * BATCH * D_MODEL]);
    atomicAdd(&g_s[b * D_MODEL + n], s);
}

// ===========================================================================
// SYRK: G_b = X_b^T X_b (fp16 in/out, fp32 acc). Triangular 128x128 tiles.
// grid (36, 4). 8 warps (2x4), warp 64(i) x 32(j). Trans-ldmatrix frags
// (validated in R9 stats_mma). smem rows 272B (17x16B, conflict-free).
// ===========================================================================
#define SKT 32
#define SROWH 136                       // halfs per row = 272B
#define S_TILEB (SKT * SROWH * 2)       // 8704
#define S_STG (2 * S_TILEB)             // 17408
#define S_NST 3

__global__ __launch_bounds__(256) void syrk_kernel(const __half* __restrict__ X) {
    __shared__ __align__(16) char ssm[S_NST * S_STG];
    const uint32_t sb = smem_to_u32(ssm);
    const int tid = threadIdx.x, lane = tid & 31, wid = tid >> 5;
    const int b = blockIdx.y;

    int x = blockIdx.x, ti = 0;
    while (x >= 8 - ti) { x -= 8 - ti; ti++; }
    const int tj = ti + x;

    const __half* Xb = X + (size_t)b * D_MODEL;

    // loader: 1024 cp16 per stage: ci = i*256+tid; i<2 -> tileA(i-range), else tileB(j-range)
    // chunk: r = (ci&511)>>4 (row 0..31), c = ci&15
    #define SY_ISSUE(s, buf) do { \
        _Pragma("unroll") \
        for (int i = 0; i < 4; i++) { \
            const int ci = i * 256 + tid; \
            const int r_ = (ci & 511) >> 4, c_ = ci & 15; \
            const int irange = (ci < 512) ? ti : tj; \
            const uint32_t toff = (ci < 512) ? 0u : (uint32_t)S_TILEB; \
            const __half* src = Xb + (size_t)((s) * SKT + r_) * (BATCH * D_MODEL) \
                                + irange * 128 + c_ * 8; \
            CP16(sb + (buf) * S_STG + toff + r_ * 272 + c_ * 16, src); \
        } \
    } while (0)

    float acc[4][4][4];
    #pragma unroll
    for (int mt = 0; mt < 4; mt++)
        #pragma unroll
        for (int nt = 0; nt < 4; nt++)
            #pragma unroll
            for (int r = 0; r < 4; r++) acc[mt][nt][r] = 0.0f;

    const int wi = wid >> 2;   // 0,1  -> i offset wi*64
    const int wj = wid & 3;    // 0..3 -> j offset wj*32

    const uint32_t a_base = (uint32_t)(((lane & 7) + ((lane >> 4) << 3)) * 272
                                       + (wi * 64 + ((lane >> 3) & 1) * 8) * 2);
    const uint32_t b_base = (uint32_t)((lane & 15) * 272 + ((lane >> 4) * 8 + wj * 32) * 2);

    const int NS = T_LEN / SKT;   // 256
    SY_ISSUE(0, 0); CP_COMMIT();
    SY_ISSUE(1, 1); CP_COMMIT();

    for (int s = 0; s < NS; s++) {
        if (s >= NS - 2) { asm volatile("cp.async.wait_group 0;" ::: "memory"); }
        else             { asm volatile("cp.async.wait_group 1;" ::: "memory"); }
        __syncthreads();
        if (s + 2 < NS) { SY_ISSUE(s + 2, (s + 2) % S_NST); CP_COMMIT(); }

        const uint32_t base = sb + (s % S_NST) * S_STG;
        #pragma unroll
        for (int kk = 0; kk < 2; kk++) {
            const uint32_t krow = kk * 16 * 272;
            uint32_t a[4][4];
            #pragma unroll
            for (int mt = 0; mt < 4; mt++)
                ldsm4t(a[mt], base + a_base + krow + mt * 32);  // i += 16*mt -> +32B
            #pragma unroll
            for (int jn = 0; jn < 2; jn++) {
                uint32_t bb[4];
                ldsm4t(bb, base + S_TILEB + b_base + krow + jn * 32);  // j += 16*jn
                #pragma unroll
                for (int mt = 0; mt < 4; mt++) {
                    mma16816(acc[mt][2*jn],   a[mt], bb[0], bb[1]);
                    mma16816(acc[mt][2*jn+1], a[mt], bb[2], bb[3]);
                }
            }
        }
        __syncthreads();
    }

    // epilogue: write G[b] tile (ti,tj) fp16 + mirror
    __half* G = g_G + (size_t)b * D_MODEL * D_MODEL;
    #pragma unroll
    for (int mt = 0; mt < 4; mt++) {
        #pragma unroll
        for (int jn = 0; jn < 4; jn++) {
            const int i0 = ti * 128 + wi * 64 + mt * 16 + (lane >> 2);
            const int j0 = tj * 128 + wj * 32 + jn * 8 + (lane & 3) * 2;
            const __half c0 = __float2half_rn(acc[mt][jn][0]);
            const __half c1 = __float2half_rn(acc[mt][jn][1]);
            const __half c2 = __float2half_rn(acc[mt][jn][2]);
            const __half c3 = __float2half_rn(acc[mt][jn][3]);
            *(__half2*)(G + (size_t)i0 * D_MODEL + j0)       = __halves2half2(c0, c1);
            *(__half2*)(G + (size_t)(i0 + 8) * D_MODEL + j0) = __halves2half2(c2, c3);
            if (ti != tj) {
                G[(size_t)j0 * D_MODEL + i0]           = c0;
                G[(size_t)(j0 + 1) * D_MODEL + i0]     = c1;
                G[(size_t)j0 * D_MODEL + i0 + 8]       = c2;
                G[(size_t)(j0 + 1) * D_MODEL + i0 + 8] = c3;
            }
        }
    }
}

// ===========================================================================
// Stats assembly: one CTA per head.
//  C[i][j]  = (Wq G Wk^T)[i][j] + bq_i*u_k[j] + u_q[i]*bk_j + T*bq_i*bk_j
//  Sq[i]    = u_q[i] + T*bq_i          (u_q[i] = Wq_i . s_b)
//  Sqq[i]   = (Wq G Wq^T)_ii + 2 bq_i u_q[i] + T bq_i^2
//  using Ht = [Wq G ; Wk G] fp16, Wqkv fp16, s_b fp32.
// ===========================================================================
__global__ __launch_bounds__(256) void stats_asm_kernel(const float* __restrict__ bqkv) {
    const int head = blockIdx.x;
    const int b = head >> 4, h = head & 15;
    const int tid = threadIdx.x;

    __shared__ __half sT[4][64][72];   // 0=Hq 1=Wq 2=Hk 3=Wk
    __shared__ float su_q[64], su_k[64], ssqq[64], sskk[64], sch[64];

    const __half* Hq = g_Ht + (size_t)b * 2 * D_MODEL * D_MODEL + (size_t)(h * 64) * D_MODEL;
    const __half* Hk = Hq + (size_t)D_MODEL * D_MODEL;
    const __half* Wq = g_wh + (size_t)(h * 64) * D_MODEL;
    const __half* Wk = g_wh + (size_t)(D_MODEL + h * 64) * D_MODEL;
    const float* sv = g_s + b * D_MODEL;

    const int ty = tid >> 4, tx = tid & 15;
    float accC[4][4];
    #pragma unroll
    for (int a = 0; a < 4; a++)
        #pragma unroll
        for (int c = 0; c < 4; c++) accC[a][c] = 0.f;
    float aqq = 0.f, auq = 0.f, akk = 0.f, auk = 0.f;

    for (int nc = 0; nc < 16; nc++) {
        #pragma unroll
        for (int i = 0; i < 8; i++) {
            const int ci = i * 256 + tid;
            const int tile = ci >> 9, r = (ci >> 3) & 63, c = ci & 7;
            const __half* src = (tile == 0 ? Hq : tile == 1 ? Wq : tile == 2 ? Hk : Wk)
                                + (size_t)r * D_MODEL + nc * 64 + c * 8;
            *(uint4*)&sT[tile][r][c * 8] = *(const uint4*)src;
        }
        if (tid < 64) sch[tid] = sv[nc * 64 + tid];
        __syncthreads();

        // C block
        #pragma unroll 8
        for (int n = 0; n < 64; n++) {
            float hq[4], wk[4];
            #pragma unroll
            for (int a = 0; a < 4; a++) hq[a] = __half2float(sT[0][ty * 4 + a][n]);
            #pragma unroll
            for (int c = 0; c < 4; c++) wk[c] = __half2float(sT[3][tx * 4 + c][n]);
            #pragma unroll
            for (int a = 0; a < 4; a++)
                #pragma unroll
                for (int c = 0; c < 4; c++) accC[a][c] += hq[a] * wk[c];
        }
        // diagonals + u
        if (tid < 64) {
            #pragma unroll 8
            for (int n = 0; n < 64; n++) {
                float hv = __half2float(sT[0][tid][n]);
                float wv = __half2float(sT[1][tid][n]);
                aqq += hv * wv; auq += wv * sch[n];
            }
        } else if (tid < 128) {
            const int j = tid - 64;
            #pragma unroll 8
            for (int n = 0; n < 64; n++) {
                float hv = __half2float(sT[2][j][n]);
                float wv = __half2float(sT[3][j][n]);
                akk += hv * wv; auk += wv * sch[n];
            }
        }
        __syncthreads();
    }

    if (tid < 64)       { su_q[tid] = auq; ssqq[tid] = aqq; }
    else if (tid < 128) { su_k[tid - 64] = auk; sskk[tid - 64] = akk; }
    __syncthreads();

    float* st = g_stats + (size_t)head * STATS_PER_HEAD;
    const float Tf = (float)T_LEN;
    #pragma unroll
    for (int a = 0; a < 4; a++) {
        const int i = ty * 4 + a;
        const float bq = bqkv[h * 64 + i];
        #pragma unroll
        for (int c = 0; c < 4; c++) {
            const int j = tx * 4 + c;
            const float bk = bqkv[D_MODEL + h * 64 + j];
            st[i * 64 + j] = accC[a][c] + bq * su_k[j] + su_q[i] * bk + Tf * bq * bk;
        }
    }
    if (tid < 64) {
        const int i = tid;
        const float bq = bqkv[h * 64 + i];
        st[4096 + i] = su_q[i] + Tf * bq;
        st[4224 + i] = ssqq[i] + 2.f * bq * su_q[i] + Tf * bq * bq;
    } else if (tid < 128) {
        const int j = tid - 64;
        const float bk = bqkv[D_MODEL + h * 64 + j];
        st[4160 + j] = su_k[j] + Tf * bk;
        st[4288 + j] = sskk[j] + 2.f * bk * su_k[j] + Tf * bk * bk;
    }
}

// ===========================================================================
// Fused corr + meff (unchanged from R9)
// ===========================================================================
__global__ __launch_bounds__(256) void corr_meff_kernel(const float* __restrict__ Wout) {
    const int head = blockIdx.x;
    const int b = head >> 4, h = head & 15;
    const int tid = threadIdx.x;
    __shared__ float sc[HD][HD + 1];
    __shared__ float mq[HD], mk[HD], isx[HD], isy[HD];

    const float* st = g_stats + (size_t)head * STATS_PER_HEAD;
    const float invT = 1.0f / (float)T_LEN;

    if (tid < 64) {
        float s = st[4096 + tid], s2 = st[4224 + tid];
        mq[tid] = s;
        isx[tid] = rsqrtf(s2 - s * s * invT);
    } else if (tid < 128) {
        int j = tid - 64;
        float s = st[4160 + j], s2 = st[4288 + j];
        mk[j] = s;
        isy[j] = rsqrtf(s2 - s * s * invT);
    }
    __syncthreads();

    for (int idx = tid; idx < HD * HD; idx += 256) {
        int i = idx >> 6, j = idx & 63;
        float cov = st[idx] - mq[i] * mk[j] * invT;
        float c = cov * isx[i] * isy[j];
        c = fminf(fmaxf(c, 0.0f), 1.0f);
        sc[i][j] = c;
    }
    __syncthreads();

    if (tid < 64) {
        int j = tid;
        float mx = -1e30f;
        #pragma unroll 4
        for (int i = 0; i < HD; i++) mx = fmaxf(mx, sc[i][j]);
        float sum = 0.f;
        #pragma unroll 4
        for (int i = 0; i < HD; i++) {
            float e = expf(sc[i][j] - mx);
            sc[i][j] = e; sum += e;
        }
        float inv = 1.0f / sum;
        #pragma unroll 4
        for (int i = 0; i < HD; i++) sc[i][j] *= inv;
    }
    __syncthreads();

    const size_t mbase = (size_t)b * D_MODEL * D_MODEL + h * HD;
    const float* Wb = Wout + h * HD;

    for (int idx = tid; idx < D_MODEL * HD; idx += 256) {
        int o = idx >> 6, d = idx & 63;
        const float* wrow = Wb + (size_t)o * D_MODEL;
        float s = 0.f;
        #pragma unroll
        for (int e = 0; e < HD; e++) s += sc[d][e] * wrow[e];
        g_mh[mbase + (size_t)o * D_MODEL + d] = __float2half_rn(s);
    }
}

// ===========================================================================
// Launch
// ===========================================================================
extern "C" void kernel_launch(void* const* d_in, const int* in_sizes, int n_in,
                              void* d_out, int out_size) {
    const float* query = (const float*)d_in[0];
    const float* Wqkv  = (const float*)d_in[1];
    const float* bqkv  = (const float*)d_in[2];
    const float* Wout  = (const float*)d_in[3];
    const float* bout  = (const float*)d_in[4];
    float* out = (float*)d_out;

    void* p;
    cudaGetSymbolAddress(&p, g_qh);   __half* qh = (__half*)p;
    cudaGetSymbolAddress(&p, g_wh);   __half* wh = (__half*)p;
    cudaGetSymbolAddress(&p, g_vh);   __half* vh = (__half*)p;
    cudaGetSymbolAddress(&p, g_mh);   __half* mh = (__half*)p;
    cudaGetSymbolAddress(&p, g_G);    __half* G  = (__half*)p;
    cudaGetSymbolAddress(&p, g_Ht);   __half* Ht = (__half*)p;
    cudaGetSymbolAddress(&p, g_zbias); float* zb = (float*)p;

    cudaFuncSetAttribute(gemm_fp16_kernel,
                         cudaFuncAttributeMaxDynamicSharedMemorySize, SMEMB);

    // 1. converters + zero s
    {
        int n4q = NROWS * D_MODEL / 4;
        conv_half_kernel<<<n4q / 256, 256>>>(query, qh, n4q);
        int n4w = QKV_LD * D_MODEL / 4;
        conv_half_kernel<<<n4w / 256, 256>>>(Wqkv, wh, n4w);
        zero_s_kernel<<<(BATCH * D_MODEL + 255) / 256, 256>>>();
    }

    // 2. col sums s_b
    colsum_kernel<<<dim3(D_MODEL / 256, BATCH, 8), 256>>>(qh);

    // 3. G_b = X_b^T X_b (triangular)
    syrk_kernel<<<dim3(36, BATCH), 256>>>(qh);

    // 4. Ht = Wqk * G_b  [2048 x 1024] per batch (G symmetric -> NT gemm valid)
    gemm_fp16_kernel<<<dim3(D_MODEL / BN, 2 * D_MODEL / BM, BATCH), NTHR, SMEMB>>>(
        wh, D_MODEL, 0,
        G, D_MODEL, (long long)D_MODEL * D_MODEL,
        zb,
        nullptr, Ht, D_MODEL, (long long)2 * D_MODEL * D_MODEL,
        D_MODEL);

    // 5. v = query @ Wv^T + bv  -> fp16
    gemm_fp16_kernel<<<dim3(D_MODEL / BN, NROWS / BM, 1), NTHR, SMEMB>>>(
        qh, D_MODEL, 0,
        wh + (size_t)2 * D_MODEL * D_MODEL, D_MODEL, 0,
        bqkv + 2 * D_MODEL,
        nullptr, vh, D_MODEL, 0,
        D_MODEL);

    // 6. assemble per-head stats from Ht, W, s
    stats_asm_kernel<<<NHEADS_TOTAL, 256>>>(bqkv);

    // 7. correlation + softmax + Meff (fused)
    corr_meff_kernel<<<NHEADS_TOTAL, 256>>>(Wout);

    // 8. out = v @ Meff_b^T + bout   per batch z
    gemm_fp16_kernel<<<dim3(D_MODEL / BN, T_LEN / BM, BATCH), NTHR, SMEMB>>>(
        vh, BATCH * D_MODEL, D_MODEL,
        mh, D_MODEL, (long long)D_MODEL * D_MODEL,
        bout,
        out, nullptr, BATCH * D_MODEL, D_MODEL,
        D_MODEL);
}

// round 11
// speedup vs baseline: 1.3796x; 1.2702x over previous
#include <cuda_runtime.h>
#include <cuda_fp16.h>
#include <cstdint>

// Problem constants
#define T_LEN   8192
#define BATCH   4
#define D_MODEL 1024
#define NHEAD   16
#define HD      64
#define QKV_LD  (3 * D_MODEL)        // 3072
#define NROWS   (T_LEN * BATCH)      // 32768
#define NHEADS_TOTAL (BATCH * NHEAD) // 64
#define STATS_PER_HEAD 4352

// Scratch (device globals: allocation-free)
__device__ __half g_qh[(size_t)NROWS * D_MODEL];                 // 64 MB  query fp16
__device__ __half g_wh[(size_t)QKV_LD * D_MODEL];                // 6 MB   Wqkv fp16
__device__ __half g_wvT[(size_t)D_MODEL * D_MODEL];              // 2 MB   Wv^T fp16
__device__ __half g_mh[(size_t)BATCH * D_MODEL * D_MODEL];       // 8 MB   Meff fp16
__device__ __half g_P[(size_t)BATCH * D_MODEL * D_MODEL];        // 8 MB   P fp16
__device__ __half g_G[(size_t)BATCH * D_MODEL * D_MODEL];        // 8 MB   Gram fp16
__device__ __half g_Ht[(size_t)BATCH * 2 * D_MODEL * D_MODEL];   // 16 MB  Wqk*G fp16
__device__ float  g_s[BATCH * D_MODEL];                          // col sums
__device__ float  g_c[BATCH * D_MODEL];                          // per-batch out bias
__device__ float  g_zbias[D_MODEL];                              // zero bias (never written)
__device__ float  g_stats[NHEADS_TOTAL * STATS_PER_HEAD];

// ===========================================================================
// helpers
// ===========================================================================
__device__ __forceinline__ uint32_t smem_to_u32(const void* p) {
    uint32_t a;
    asm("{ .reg .u64 t; cvta.to.shared.u64 t, %1; cvt.u32.u64 %0, t; }"
        : "=r"(a) : "l"(p));
    return a;
}

__device__ __forceinline__ void ldsm4(uint32_t (&r)[4], uint32_t addr) {
    asm volatile("ldmatrix.sync.aligned.m8n8.x4.shared.b16 {%0,%1,%2,%3}, [%4];"
        : "=r"(r[0]), "=r"(r[1]), "=r"(r[2]), "=r"(r[3]) : "r"(addr));
}

__device__ __forceinline__ void ldsm4t(uint32_t (&r)[4], uint32_t addr) {
    asm volatile("ldmatrix.sync.aligned.m8n8.x4.trans.shared.b16 {%0,%1,%2,%3}, [%4];"
        : "=r"(r[0]), "=r"(r[1]), "=r"(r[2]), "=r"(r[3]) : "r"(addr));
}

__device__ __forceinline__ void mma16816(float (&c)[4], const uint32_t (&a)[4],
                                         uint32_t b0, uint32_t b1) {
    asm volatile(
        "mma.sync.aligned.m16n8k16.row.col.f32.f16.f16.f32 "
        "{%0,%1,%2,%3}, {%4,%5,%6,%7}, {%8,%9}, {%0,%1,%2,%3};"
        : "+f"(c[0]), "+f"(c[1]), "+f"(c[2]), "+f"(c[3])
        : "r"(a[0]), "r"(a[1]), "r"(a[2]), "r"(a[3]), "r"(b0), "r"(b1));
}

#define CP_COMMIT() asm volatile("cp.async.commit_group;" ::: "memory")
#define CP16(dst, src) \
    asm volatile("cp.async.cg.shared.global [%0], [%1], 16;" \
        :: "r"(dst), "l"(src) : "memory")

// ===========================================================================
// fp16 single-pass HMMA GEMM (NT): C[m,n] = sum_k A[m,k]*B[n,k] + bias[n]
// 256x128x32 CTA tile, 8 warps (4x2), warp tile 64x64. 256 threads.
// bias is per-batch via biasBatch stride.
// ===========================================================================
#define BM 256
#define BN 128
#define BK 32
#define NTHR 256
#define ROWB 80
#define A_TILEB (256 * ROWB)
#define B_TILEB (128 * ROWB)
#define OFF_A  0
#define OFF_B  A_TILEB
#define STAGEB (A_TILEB + B_TILEB)
#define NSTAGE 4
#define SMEMB (NSTAGE * STAGEB)         // 122880

__global__ void __launch_bounds__(NTHR, 1) gemm_fp16_kernel(
    const __half* __restrict__ Ah, int strideA, long long batchA,
    const __half* __restrict__ Bh, int strideB, long long batchB,
    const float* __restrict__ bias, long long biasBatch,
    float* __restrict__ C, __half* __restrict__ Ch,
    int strideC, long long batchC,
    int K)
{
    extern __shared__ char smem[];
    const uint32_t sb = smem_to_u32(smem);
    const int tid = threadIdx.x;
    const int lane = tid & 31;
    const int wid = tid >> 5;
    const int wm = (wid >> 1) * 64;
    const int wn = (wid & 1) * 64;
    const int z = blockIdx.z;

    const __half* Ab = Ah + (size_t)blockIdx.y * BM * strideA + (size_t)z * batchA;
    const __half* Bb = Bh + (size_t)blockIdx.x * BN * strideB + (size_t)z * batchB;
    const float* biasz = bias + (size_t)z * biasBatch;

    float acc[4][8][4];
    #pragma unroll
    for (int mt = 0; mt < 4; mt++)
        #pragma unroll
        for (int nt = 0; nt < 8; nt++)
            #pragma unroll
            for (int r = 0; r < 4; r++) acc[mt][nt][r] = 0.0f;

    const int NKT = K / BK;

    #define ISSUE_STAGE(kt, buf) do { \
        const uint32_t sbase = sb + (buf) * STAGEB; \
        _Pragma("unroll") \
        for (int i = 0; i < 6; i++) { \
            const int ci = i * NTHR + tid; \
            const __half* src; uint32_t dst; \
            if (i < 4) { \
                const int r_ = ci >> 2, c_ = ci & 3; \
                src = Ab + (size_t)r_ * strideA + (kt) * BK + c_ * 8; \
                dst = sbase + OFF_A + r_ * ROWB + c_ * 16; \
            } else { \
                const int j_ = ci - 1024, r_ = j_ >> 2, c_ = j_ & 3; \
                src = Bb + (size_t)r_ * strideB + (kt) * BK + c_ * 8; \
                dst = sbase + OFF_B + r_ * ROWB + c_ * 16; \
            } \
            CP16(dst, src); \
        } \
    } while (0)

    ISSUE_STAGE(0, 0); CP_COMMIT();
    ISSUE_STAGE(1, 1); CP_COMMIT();
    ISSUE_STAGE(2, 2); CP_COMMIT();

    const uint32_t a_off = (uint32_t)((lane & 15) * ROWB + (lane >> 4) * 16);
    const uint32_t b_row = (uint32_t)((lane & 7) + ((lane >> 4) << 3));
    const uint32_t b_off = (uint32_t)(b_row * ROWB + ((lane >> 3) & 1) * 16);

    for (int kt = 0; kt < NKT; kt++) {
        asm volatile("cp.async.wait_group 2;" ::: "memory");
        __syncthreads();

        if (kt + 3 < NKT) { ISSUE_STAGE(kt + 3, (kt + 3) % NSTAGE); CP_COMMIT(); }

        const uint32_t base = sb + (kt % NSTAGE) * STAGEB;
        #pragma unroll
        for (int kk = 0; kk < 2; kk++) {
            const uint32_t koff = kk * 32;
            uint32_t a[4][4];
            #pragma unroll
            for (int mt = 0; mt < 4; mt++)
                ldsm4(a[mt], base + OFF_A + (wm + mt * 16) * ROWB + a_off + koff);
            #pragma unroll
            for (int ng = 0; ng < 4; ng++) {
                uint32_t bh[4];
                ldsm4(bh, base + OFF_B + (wn + ng * 16) * ROWB + b_off + koff);
                #pragma unroll
                for (int mt = 0; mt < 4; mt++) {
                    mma16816(acc[mt][2*ng],   a[mt], bh[0], bh[1]);
                    mma16816(acc[mt][2*ng+1], a[mt], bh[2], bh[3]);
                }
            }
        }
    }

    // ---- epilogue ----
    const int rbase = blockIdx.y * BM + wm + (lane >> 2);
    const int cbase = blockIdx.x * BN + wn + (lane & 3) * 2;
    #pragma unroll
    for (int mt = 0; mt < 4; mt++) {
        #pragma unroll
        for (int nt = 0; nt < 8; nt++) {
            const int row = rbase + mt * 16;
            const int col = cbase + nt * 8;
            const float b0 = biasz[col], b1 = biasz[col + 1];
            const float v0 = acc[mt][nt][0] + b0, v1 = acc[mt][nt][1] + b1;
            const float v2 = acc[mt][nt][2] + b0, v3 = acc[mt][nt][3] + b1;
            if (Ch != nullptr) {
                __half* Chz = Ch + (size_t)z * batchC;
                *(__half2*)(Chz + (size_t)row * strideC + col)       = __floats2half2_rn(v0, v1);
                *(__half2*)(Chz + (size_t)(row + 8) * strideC + col) = __floats2half2_rn(v2, v3);
            } else {
                float* Cz = C + (size_t)z * batchC;
                float2 o0, o1;
                o0.x = v0; o0.y = v1; o1.x = v2; o1.y = v3;
                *(float2*)(Cz + (size_t)row * strideC + col) = o0;
                *(float2*)(Cz + (size_t)(row + 8) * strideC + col) = o1;
            }
        }
    }
}

// ===========================================================================
// Converter: fp32 -> fp16
// ===========================================================================
__global__ void conv_half_kernel(const float* __restrict__ in,
                                 __half* __restrict__ outh, int n4) {
    int idx = blockIdx.x * blockDim.x + threadIdx.x;
    if (idx < n4) {
        float4 v = ((const float4*)in)[idx];
        ((__half2*)outh)[2 * idx]     = __floats2half2_rn(v.x, v.y);
        ((__half2*)outh)[2 * idx + 1] = __floats2half2_rn(v.z, v.w);
    }
}

// ===========================================================================
// zero g_s
// ===========================================================================
__global__ void zero_s_kernel() {
    int idx = blockIdx.x * blockDim.x + threadIdx.x;
    if (idx < BATCH * D_MODEL) g_s[idx] = 0.0f;
}

// ===========================================================================
// colsum (vectorized): s_b[n] = sum_t X[(t*B+b)][n]. grid (BATCH, 64),
// block 128: thread owns 8 columns (one uint4 per row), 128 rows per block.
// ===========================================================================
__global__ __launch_bounds__(128) void colsum_kernel(const __half* __restrict__ X) {
    const int b = blockIdx.x;
    const int t0 = blockIdx.y * (T_LEN / 64);
    const int n0 = threadIdx.x * 8;
    float s[8];
    #pragma unroll
    for (int i = 0; i < 8; i++) s[i] = 0.f;
    const __half* p = X + (size_t)(t0 * BATCH + b) * D_MODEL + n0;
    #pragma unroll 4
    for (int t = 0; t < T_LEN / 64; t++) {
        uint4 v = *(const uint4*)(p + (size_t)t * BATCH * D_MODEL);
        const __half2* h = (const __half2*)&v;
        #pragma unroll
        for (int i = 0; i < 4; i++) {
            float2 f = __half22float2(h[i]);
            s[2*i] += f.x; s[2*i+1] += f.y;
        }
    }
    #pragma unroll
    for (int i = 0; i < 8; i++)
        atomicAdd(&g_s[b * D_MODEL + n0 + i], s[i]);
}

// ===========================================================================
// Transpose Wv: WvT[k][d] = Wv[d][k].  32x32 smem tiles.
// ===========================================================================
__global__ __launch_bounds__(256) void transpose_wv_kernel(const __half* __restrict__ Wv,
                                                           __half* __restrict__ WvT) {
    __shared__ __half tile[32][33];
    const int bx = blockIdx.x * 32, by = blockIdx.y * 32;
    const int tx = threadIdx.x & 31, ty = threadIdx.x >> 5;  // 32x8
    #pragma unroll
    for (int i = 0; i < 4; i++)
        tile[ty + i * 8][tx] = Wv[(size_t)(by + ty + i * 8) * D_MODEL + bx + tx];
    __syncthreads();
    #pragma unroll
    for (int i = 0; i < 4; i++)
        WvT[(size_t)(bx + ty + i * 8) * D_MODEL + by + tx] = tile[tx][ty + i * 8];
}

// ===========================================================================
// cbias: c[b][o] = bout[o] + sum_d bv[d] * mh[b][o][d]
// grid 16, block 256: thread per (b,o). bv cached in smem.
// ===========================================================================
__global__ __launch_bounds__(256) void cbias_kernel(const float* __restrict__ bqkv,
                                                    const float* __restrict__ bout) {
    __shared__ float sbv[D_MODEL];
    for (int i = threadIdx.x; i < D_MODEL; i += 256)
        sbv[i] = bqkv[2 * D_MODEL + i];
    __syncthreads();
    const int idx = blockIdx.x * 256 + threadIdx.x;   // 0..4095
    const int b = idx >> 10, o = idx & 1023;
    const __half* row = g_mh + (size_t)b * D_MODEL * D_MODEL + (size_t)o * D_MODEL;
    float s = 0.f;
    #pragma unroll 4
    for (int d8 = 0; d8 < D_MODEL / 8; d8++) {
        uint4 v = *(const uint4*)(row + d8 * 8);
        const __half2* h = (const __half2*)&v;
        #pragma unroll
        for (int i = 0; i < 4; i++) {
            float2 f = __half22float2(h[i]);
            s += f.x * sbv[d8 * 8 + 2 * i] + f.y * sbv[d8 * 8 + 2 * i + 1];
        }
    }
    g_c[idx] = s + bout[o];
}

// ===========================================================================
// SYRK: G_b = X_b^T X_b (fp16 in/out, fp32 acc). Triangular 128x128 tiles.
// ===========================================================================
#define SKT 32
#define SROWH 136
#define S_TILEB (SKT * SROWH * 2)       // 8704
#define S_STG (2 * S_TILEB)             // 17408
#define S_NST 3

__global__ __launch_bounds__(256) void syrk_kernel(const __half* __restrict__ X) {
    __shared__ __align__(16) char ssm[S_NST * S_STG];
    const uint32_t sb = smem_to_u32(ssm);
    const int tid = threadIdx.x, lane = tid & 31, wid = tid >> 5;
    const int b = blockIdx.y;

    int x = blockIdx.x, ti = 0;
    while (x >= 8 - ti) { x -= 8 - ti; ti++; }
    const int tj = ti + x;

    const __half* Xb = X + (size_t)b * D_MODEL;

    #define SY_ISSUE(s, buf) do { \
        _Pragma("unroll") \
        for (int i = 0; i < 4; i++) { \
            const int ci = i * 256 + tid; \
            const int r_ = (ci & 511) >> 4, c_ = ci & 15; \
            const int irange = (ci < 512) ? ti : tj; \
            const uint32_t toff = (ci < 512) ? 0u : (uint32_t)S_TILEB; \
            const __half* src = Xb + (size_t)((s) * SKT + r_) * (BATCH * D_MODEL) \
                                + irange * 128 + c_ * 8; \
            CP16(sb + (buf) * S_STG + toff + r_ * 272 + c_ * 16, src); \
        } \
    } while (0)

    float acc[4][4][4];
    #pragma unroll
    for (int mt = 0; mt < 4; mt++)
        #pragma unroll
        for (int nt = 0; nt < 4; nt++)
            #pragma unroll
            for (int r = 0; r < 4; r++) acc[mt][nt][r] = 0.0f;

    const int wi = wid >> 2;
    const int wj = wid & 3;

    const uint32_t a_base = (uint32_t)(((lane & 7) + ((lane >> 4) << 3)) * 272
                                       + (wi * 64 + ((lane >> 3) & 1) * 8) * 2);
    const uint32_t b_base = (uint32_t)((lane & 15) * 272 + ((lane >> 4) * 8 + wj * 32) * 2);

    const int NS = T_LEN / SKT;   // 256
    SY_ISSUE(0, 0); CP_COMMIT();
    SY_ISSUE(1, 1); CP_COMMIT();

    for (int s = 0; s < NS; s++) {
        if (s >= NS - 2) { asm volatile("cp.async.wait_group 0;" ::: "memory"); }
        else             { asm volatile("cp.async.wait_group 1;" ::: "memory"); }
        __syncthreads();
        if (s + 2 < NS) { SY_ISSUE(s + 2, (s + 2) % S_NST); CP_COMMIT(); }

        const uint32_t base = sb + (s % S_NST) * S_STG;
        #pragma unroll
        for (int kk = 0; kk < 2; kk++) {
            const uint32_t krow = kk * 16 * 272;
            uint32_t a[4][4];
            #pragma unroll
            for (int mt = 0; mt < 4; mt++)
                ldsm4t(a[mt], base + a_base + krow + mt * 32);
            #pragma unroll
            for (int jn = 0; jn < 2; jn++) {
                uint32_t bb[4];
                ldsm4t(bb, base + S_TILEB + b_base + krow + jn * 32);
                #pragma unroll
                for (int mt = 0; mt < 4; mt++) {
                    mma16816(acc[mt][2*jn],   a[mt], bb[0], bb[1]);
                    mma16816(acc[mt][2*jn+1], a[mt], bb[2], bb[3]);
                }
            }
        }
        __syncthreads();
    }

    __half* G = g_G + (size_t)b * D_MODEL * D_MODEL;
    #pragma unroll
    for (int mt = 0; mt < 4; mt++) {
        #pragma unroll
        for (int jn = 0; jn < 4; jn++) {
            const int i0 = ti * 128 + wi * 64 + mt * 16 + (lane >> 2);
            const int j0 = tj * 128 + wj * 32 + jn * 8 + (lane & 3) * 2;
            const __half c0 = __float2half_rn(acc[mt][jn][0]);
            const __half c1 = __float2half_rn(acc[mt][jn][1]);
            const __half c2 = __float2half_rn(acc[mt][jn][2]);
            const __half c3 = __float2half_rn(acc[mt][jn][3]);
            *(__half2*)(G + (size_t)i0 * D_MODEL + j0)       = __halves2half2(c0, c1);
            *(__half2*)(G + (size_t)(i0 + 8) * D_MODEL + j0) = __halves2half2(c2, c3);
            if (ti != tj) {
                G[(size_t)j0 * D_MODEL + i0]           = c0;
                G[(size_t)(j0 + 1) * D_MODEL + i0]     = c1;
                G[(size_t)j0 * D_MODEL + i0 + 8]       = c2;
                G[(size_t)(j0 + 1) * D_MODEL + i0 + 8] = c3;
            }
        }
    }
}

// ===========================================================================
// Stats assembly (unchanged from R10)
// ===========================================================================
__global__ __launch_bounds__(256) void stats_asm_kernel(const float* __restrict__ bqkv) {
    const int head = blockIdx.x;
    const int b = head >> 4, h = head & 15;
    const int tid = threadIdx.x;

    __shared__ __half sT[4][64][72];
    __shared__ float su_q[64], su_k[64], ssqq[64], sskk[64], sch[64];

    const __half* Hq = g_Ht + (size_t)b * 2 * D_MODEL * D_MODEL + (size_t)(h * 64) * D_MODEL;
    const __half* Hk = Hq + (size_t)D_MODEL * D_MODEL;
    const __half* Wq = g_wh + (size_t)(h * 64) * D_MODEL;
    const __half* Wk = g_wh + (size_t)(D_MODEL + h * 64) * D_MODEL;
    const float* sv = g_s + b * D_MODEL;

    const int ty = tid >> 4, tx = tid & 15;
    float accC[4][4];
    #pragma unroll
    for (int a = 0; a < 4; a++)
        #pragma unroll
        for (int c = 0; c < 4; c++) accC[a][c] = 0.f;
    float aqq = 0.f, auq = 0.f, akk = 0.f, auk = 0.f;

    for (int nc = 0; nc < 16; nc++) {
        #pragma unroll
        for (int i = 0; i < 8; i++) {
            const int ci = i * 256 + tid;
            const int tile = ci >> 9, r = (ci >> 3) & 63, c = ci & 7;
            const __half* src = (tile == 0 ? Hq : tile == 1 ? Wq : tile == 2 ? Hk : Wk)
                                + (size_t)r * D_MODEL + nc * 64 + c * 8;
            *(uint4*)&sT[tile][r][c * 8] = *(const uint4*)src;
        }
        if (tid < 64) sch[tid] = sv[nc * 64 + tid];
        __syncthreads();

        #pragma unroll 8
        for (int n = 0; n < 64; n++) {
            float hq[4], wk[4];
            #pragma unroll
            for (int a = 0; a < 4; a++) hq[a] = __half2float(sT[0][ty * 4 + a][n]);
            #pragma unroll
            for (int c = 0; c < 4; c++) wk[c] = __half2float(sT[3][tx * 4 + c][n]);
            #pragma unroll
            for (int a = 0; a < 4; a++)
                #pragma unroll
                for (int c = 0; c < 4; c++) accC[a][c] += hq[a] * wk[c];
        }
        if (tid < 64) {
            #pragma unroll 8
            for (int n = 0; n < 64; n++) {
                float hv = __half2float(sT[0][tid][n]);
                float wv = __half2float(sT[1][tid][n]);
                aqq += hv * wv; auq += wv * sch[n];
            }
        } else if (tid < 128) {
            const int j = tid - 64;
            #pragma unroll 8
            for (int n = 0; n < 64; n++) {
                float hv = __half2float(sT[2][j][n]);
                float wv = __half2float(sT[3][j][n]);
                akk += hv * wv; auk += wv * sch[n];
            }
        }
        __syncthreads();
    }

    if (tid < 64)       { su_q[tid] = auq; ssqq[tid] = aqq; }
    else if (tid < 128) { su_k[tid - 64] = auk; sskk[tid - 64] = akk; }
    __syncthreads();

    float* st = g_stats + (size_t)head * STATS_PER_HEAD;
    const float Tf = (float)T_LEN;
    #pragma unroll
    for (int a = 0; a < 4; a++) {
        const int i = ty * 4 + a;
        const float bq = bqkv[h * 64 + i];
        #pragma unroll
        for (int c = 0; c < 4; c++) {
            const int j = tx * 4 + c;
            const float bk = bqkv[D_MODEL + h * 64 + j];
            st[i * 64 + j] = accC[a][c] + bq * su_k[j] + su_q[i] * bk + Tf * bq * bk;
        }
    }
    if (tid < 64) {
        const int i = tid;
        const float bq = bqkv[h * 64 + i];
        st[4096 + i] = su_q[i] + Tf * bq;
        st[4224 + i] = ssqq[i] + 2.f * bq * su_q[i] + Tf * bq * bq;
    } else if (tid < 128) {
        const int j = tid - 64;
        const float bk = bqkv[D_MODEL + h * 64 + j];
        st[4160 + j] = su_k[j] + Tf * bk;
        st[4288 + j] = sskk[j] + 2.f * bk * su_k[j] + Tf * bk * bk;
    }
}

// ===========================================================================
// Fused corr + meff (unchanged)
// ===========================================================================
__global__ __launch_bounds__(256) void corr_meff_kernel(const float* __restrict__ Wout) {
    const int head = blockIdx.x;
    const int b = head >> 4, h = head & 15;
    const int tid = threadIdx.x;
    __shared__ float sc[HD][HD + 1];
    __shared__ float mq[HD], mk[HD], isx[HD], isy[HD];

    const float* st = g_stats + (size_t)head * STATS_PER_HEAD;
    const float invT = 1.0f / (float)T_LEN;

    if (tid < 64) {
        float s = st[4096 + tid], s2 = st[4224 + tid];
        mq[tid] = s;
        isx[tid] = rsqrtf(s2 - s * s * invT);
    } else if (tid < 128) {
        int j = tid - 64;
        float s = st[4160 + j], s2 = st[4288 + j];
        mk[j] = s;
        isy[j] = rsqrtf(s2 - s * s * invT);
    }
    __syncthreads();

    for (int idx = tid; idx < HD * HD; idx += 256) {
        int i = idx >> 6, j = idx & 63;
        float cov = st[idx] - mq[i] * mk[j] * invT;
        float c = cov * isx[i] * isy[j];
        c = fminf(fmaxf(c, 0.0f), 1.0f);
        sc[i][j] = c;
    }
    __syncthreads();

    if (tid < 64) {
        int j = tid;
        float mx = -1e30f;
        #pragma unroll 4
        for (int i = 0; i < HD; i++) mx = fmaxf(mx, sc[i][j]);
        float sum = 0.f;
        #pragma unroll 4
        for (int i = 0; i < HD; i++) {
            float e = expf(sc[i][j] - mx);
            sc[i][j] = e; sum += e;
        }
        float inv = 1.0f / sum;
        #pragma unroll 4
        for (int i = 0; i < HD; i++) sc[i][j] *= inv;
    }
    __syncthreads();

    const size_t mbase = (size_t)b * D_MODEL * D_MODEL + h * HD;
    const float* Wb = Wout + h * HD;

    for (int idx = tid; idx < D_MODEL * HD; idx += 256) {
        int o = idx >> 6, d = idx & 63;
        const float* wrow = Wb + (size_t)o * D_MODEL;
        float s = 0.f;
        #pragma unroll
        for (int e = 0; e < HD; e++) s += sc[d][e] * wrow[e];
        g_mh[mbase + (size_t)o * D_MODEL + d] = __float2half_rn(s);
    }
}

// ===========================================================================
// Launch
// ===========================================================================
extern "C" void kernel_launch(void* const* d_in, const int* in_sizes, int n_in,
                              void* d_out, int out_size) {
    const float* query = (const float*)d_in[0];
    const float* Wqkv  = (const float*)d_in[1];
    const float* bqkv  = (const float*)d_in[2];
    const float* Wout  = (const float*)d_in[3];
    const float* bout  = (const float*)d_in[4];
    float* out = (float*)d_out;

    void* p;
    cudaGetSymbolAddress(&p, g_qh);    __half* qh  = (__half*)p;
    cudaGetSymbolAddress(&p, g_wh);    __half* wh  = (__half*)p;
    cudaGetSymbolAddress(&p, g_wvT);   __half* wvT = (__half*)p;
    cudaGetSymbolAddress(&p, g_mh);    __half* mh  = (__half*)p;
    cudaGetSymbolAddress(&p, g_P);     __half* P   = (__half*)p;
    cudaGetSymbolAddress(&p, g_G);     __half* G   = (__half*)p;
    cudaGetSymbolAddress(&p, g_Ht);    __half* Ht  = (__half*)p;
    cudaGetSymbolAddress(&p, g_zbias); float* zb   = (float*)p;
    cudaGetSymbolAddress(&p, g_c);     float* cb   = (float*)p;

    cudaFuncSetAttribute(gemm_fp16_kernel,
                         cudaFuncAttributeMaxDynamicSharedMemorySize, SMEMB);

    // 1. converters + zero s + Wv transpose
    {
        int n4q = NROWS * D_MODEL / 4;
        conv_half_kernel<<<n4q / 256, 256>>>(query, qh, n4q);
        int n4w = QKV_LD * D_MODEL / 4;
        conv_half_kernel<<<n4w / 256, 256>>>(Wqkv, wh, n4w);
        zero_s_kernel<<<(BATCH * D_MODEL + 255) / 256, 256>>>();
        transpose_wv_kernel<<<dim3(32, 32), 256>>>(
            wh + (size_t)2 * D_MODEL * D_MODEL, wvT);
    }

    // 2. col sums s_b  (vectorized)
    colsum_kernel<<<dim3(BATCH, 64), 128>>>(qh);

    // 3. G_b = X_b^T X_b (triangular)
    syrk_kernel<<<dim3(36, BATCH), 256>>>(qh);

    // 4. Ht = Wqk * G_b  [2048 x 1024] per batch
    gemm_fp16_kernel<<<dim3(D_MODEL / BN, 2 * D_MODEL / BM, BATCH), NTHR, SMEMB>>>(
        wh, D_MODEL, 0,
        G, D_MODEL, (long long)D_MODEL * D_MODEL,
        zb, 0,
        nullptr, Ht, D_MODEL, (long long)2 * D_MODEL * D_MODEL,
        D_MODEL);

    // 5. assemble per-head stats from Ht, W, s
    stats_asm_kernel<<<NHEADS_TOTAL, 256>>>(bqkv);

    // 6. correlation + softmax + Meff (fused)
    corr_meff_kernel<<<NHEADS_TOTAL, 256>>>(Wout);

    // 7. P_b = Meff_b @ WvT^T  (i.e. P[o][k] = sum_d mh[o][d] WvT[k][d])
    gemm_fp16_kernel<<<dim3(D_MODEL / BN, D_MODEL / BM, BATCH), NTHR, SMEMB>>>(
        mh, D_MODEL, (long long)D_MODEL * D_MODEL,
        wvT, D_MODEL, 0,
        zb, 0,
        nullptr, P, D_MODEL, (long long)D_MODEL * D_MODEL,
        D_MODEL);

    // 8. c_b[o] = bout[o] + sum_d bv[d]*mh_b[o][d]
    cbias_kernel<<<16, 256>>>(bqkv, bout);

    // 9. out = X @ P_b^T + c_b   per batch z
    gemm_fp16_kernel<<<dim3(D_MODEL / BN, T_LEN / BM, BATCH), NTHR, SMEMB>>>(
        qh, BATCH * D_MODEL, D_MODEL,
        P, D_MODEL, (long long)D_MODEL * D_MODEL,
        cb, D_MODEL,
        out, nullptr, BATCH * D_MODEL, D_MODEL,
        D_MODEL);
}

// round 12
// speedup vs baseline: 1.4418x; 1.0451x over previous
#include <cuda_runtime.h>
#include <cuda_fp16.h>
#include <cstdint>

// Problem constants
#define T_LEN   8192
#define BATCH   4
#define D_MODEL 1024
#define NHEAD   16
#define HD      64
#define QKV_LD  (3 * D_MODEL)        // 3072
#define NROWS   (T_LEN * BATCH)      // 32768
#define NHEADS_TOTAL (BATCH * NHEAD) // 64
#define STATS_PER_HEAD 4352

// Scratch (device globals: allocation-free)
__device__ __half g_qh[(size_t)NROWS * D_MODEL];                 // 64 MB  query fp16
__device__ __half g_wh[(size_t)QKV_LD * D_MODEL];                // 6 MB   Wqkv fp16
__device__ __half g_wvT[(size_t)D_MODEL * D_MODEL];              // 2 MB   Wv^T fp16
__device__ __half g_mh[(size_t)BATCH * D_MODEL * D_MODEL];       // 8 MB   Meff fp16
__device__ __half g_P[(size_t)BATCH * D_MODEL * D_MODEL];        // 8 MB   P fp16
__device__ __half g_G[(size_t)BATCH * D_MODEL * D_MODEL];        // 8 MB   Gram fp16
__device__ __half g_Ht[(size_t)BATCH * 2 * D_MODEL * D_MODEL];   // 16 MB  Wqk*G fp16
__device__ float  g_s[BATCH * D_MODEL];                          // col sums
__device__ float  g_c[BATCH * D_MODEL];                          // per-batch out bias
__device__ float  g_zbias[D_MODEL];                              // zero bias (never written)
__device__ float  g_stats[NHEADS_TOTAL * STATS_PER_HEAD];

// ===========================================================================
// helpers
// ===========================================================================
__device__ __forceinline__ uint32_t smem_to_u32(const void* p) {
    uint32_t a;
    asm("{ .reg .u64 t; cvta.to.shared.u64 t, %1; cvt.u32.u64 %0, t; }"
        : "=r"(a) : "l"(p));
    return a;
}

__device__ __forceinline__ void ldsm4(uint32_t (&r)[4], uint32_t addr) {
    asm volatile("ldmatrix.sync.aligned.m8n8.x4.shared.b16 {%0,%1,%2,%3}, [%4];"
        : "=r"(r[0]), "=r"(r[1]), "=r"(r[2]), "=r"(r[3]) : "r"(addr));
}

__device__ __forceinline__ void ldsm4t(uint32_t (&r)[4], uint32_t addr) {
    asm volatile("ldmatrix.sync.aligned.m8n8.x4.trans.shared.b16 {%0,%1,%2,%3}, [%4];"
        : "=r"(r[0]), "=r"(r[1]), "=r"(r[2]), "=r"(r[3]) : "r"(addr));
}

__device__ __forceinline__ void mma16816(float (&c)[4], const uint32_t (&a)[4],
                                         uint32_t b0, uint32_t b1) {
    asm volatile(
        "mma.sync.aligned.m16n8k16.row.col.f32.f16.f16.f32 "
        "{%0,%1,%2,%3}, {%4,%5,%6,%7}, {%8,%9}, {%0,%1,%2,%3};"
        : "+f"(c[0]), "+f"(c[1]), "+f"(c[2]), "+f"(c[3])
        : "r"(a[0]), "r"(a[1]), "r"(a[2]), "r"(a[3]), "r"(b0), "r"(b1));
}

#define CP_COMMIT() asm volatile("cp.async.commit_group;" ::: "memory")
#define CP16(dst, src) \
    asm volatile("cp.async.cg.shared.global [%0], [%1], 16;" \
        :: "r"(dst), "l"(src) : "memory")

// ===========================================================================
// fp16 single-pass HMMA GEMM (NT)  (unchanged)
// ===========================================================================
#define BM 256
#define BN 128
#define BK 32
#define NTHR 256
#define ROWB 80
#define A_TILEB (256 * ROWB)
#define B_TILEB (128 * ROWB)
#define OFF_A  0
#define OFF_B  A_TILEB
#define STAGEB (A_TILEB + B_TILEB)
#define NSTAGE 4
#define SMEMB (NSTAGE * STAGEB)         // 122880

__global__ void __launch_bounds__(NTHR, 1) gemm_fp16_kernel(
    const __half* __restrict__ Ah, int strideA, long long batchA,
    const __half* __restrict__ Bh, int strideB, long long batchB,
    const float* __restrict__ bias, long long biasBatch,
    float* __restrict__ C, __half* __restrict__ Ch,
    int strideC, long long batchC,
    int K)
{
    extern __shared__ char smem[];
    const uint32_t sb = smem_to_u32(smem);
    const int tid = threadIdx.x;
    const int lane = tid & 31;
    const int wid = tid >> 5;
    const int wm = (wid >> 1) * 64;
    const int wn = (wid & 1) * 64;
    const int z = blockIdx.z;

    const __half* Ab = Ah + (size_t)blockIdx.y * BM * strideA + (size_t)z * batchA;
    const __half* Bb = Bh + (size_t)blockIdx.x * BN * strideB + (size_t)z * batchB;
    const float* biasz = bias + (size_t)z * biasBatch;

    float acc[4][8][4];
    #pragma unroll
    for (int mt = 0; mt < 4; mt++)
        #pragma unroll
        for (int nt = 0; nt < 8; nt++)
            #pragma unroll
            for (int r = 0; r < 4; r++) acc[mt][nt][r] = 0.0f;

    const int NKT = K / BK;

    #define ISSUE_STAGE(kt, buf) do { \
        const uint32_t sbase = sb + (buf) * STAGEB; \
        _Pragma("unroll") \
        for (int i = 0; i < 6; i++) { \
            const int ci = i * NTHR + tid; \
            const __half* src; uint32_t dst; \
            if (i < 4) { \
                const int r_ = ci >> 2, c_ = ci & 3; \
                src = Ab + (size_t)r_ * strideA + (kt) * BK + c_ * 8; \
                dst = sbase + OFF_A + r_ * ROWB + c_ * 16; \
            } else { \
                const int j_ = ci - 1024, r_ = j_ >> 2, c_ = j_ & 3; \
                src = Bb + (size_t)r_ * strideB + (kt) * BK + c_ * 8; \
                dst = sbase + OFF_B + r_ * ROWB + c_ * 16; \
            } \
            CP16(dst, src); \
        } \
    } while (0)

    ISSUE_STAGE(0, 0); CP_COMMIT();
    ISSUE_STAGE(1, 1); CP_COMMIT();
    ISSUE_STAGE(2, 2); CP_COMMIT();

    const uint32_t a_off = (uint32_t)((lane & 15) * ROWB + (lane >> 4) * 16);
    const uint32_t b_row = (uint32_t)((lane & 7) + ((lane >> 4) << 3));
    const uint32_t b_off = (uint32_t)(b_row * ROWB + ((lane >> 3) & 1) * 16);

    for (int kt = 0; kt < NKT; kt++) {
        asm volatile("cp.async.wait_group 2;" ::: "memory");
        __syncthreads();

        if (kt + 3 < NKT) { ISSUE_STAGE(kt + 3, (kt + 3) % NSTAGE); CP_COMMIT(); }

        const uint32_t base = sb + (kt % NSTAGE) * STAGEB;
        #pragma unroll
        for (int kk = 0; kk < 2; kk++) {
            const uint32_t koff = kk * 32;
            uint32_t a[4][4];
            #pragma unroll
            for (int mt = 0; mt < 4; mt++)
                ldsm4(a[mt], base + OFF_A + (wm + mt * 16) * ROWB + a_off + koff);
            #pragma unroll
            for (int ng = 0; ng < 4; ng++) {
                uint32_t bh[4];
                ldsm4(bh, base + OFF_B + (wn + ng * 16) * ROWB + b_off + koff);
                #pragma unroll
                for (int mt = 0; mt < 4; mt++) {
                    mma16816(acc[mt][2*ng],   a[mt], bh[0], bh[1]);
                    mma16816(acc[mt][2*ng+1], a[mt], bh[2], bh[3]);
                }
            }
        }
    }

    const int rbase = blockIdx.y * BM + wm + (lane >> 2);
    const int cbase = blockIdx.x * BN + wn + (lane & 3) * 2;
    #pragma unroll
    for (int mt = 0; mt < 4; mt++) {
        #pragma unroll
        for (int nt = 0; nt < 8; nt++) {
            const int row = rbase + mt * 16;
            const int col = cbase + nt * 8;
            const float b0 = biasz[col], b1 = biasz[col + 1];
            const float v0 = acc[mt][nt][0] + b0, v1 = acc[mt][nt][1] + b1;
            const float v2 = acc[mt][nt][2] + b0, v3 = acc[mt][nt][3] + b1;
            if (Ch != nullptr) {
                __half* Chz = Ch + (size_t)z * batchC;
                *(__half2*)(Chz + (size_t)row * strideC + col)       = __floats2half2_rn(v0, v1);
                *(__half2*)(Chz + (size_t)(row + 8) * strideC + col) = __floats2half2_rn(v2, v3);
            } else {
                float* Cz = C + (size_t)z * batchC;
                float2 o0, o1;
                o0.x = v0; o0.y = v1; o1.x = v2; o1.y = v3;
                *(float2*)(Cz + (size_t)row * strideC + col) = o0;
                *(float2*)(Cz + (size_t)(row + 8) * strideC + col) = o1;
            }
        }
    }
}

// ===========================================================================
// Converter: fp32 -> fp16
// ===========================================================================
__global__ void conv_half_kernel(const float* __restrict__ in,
                                 __half* __restrict__ outh, int n4) {
    int idx = blockIdx.x * blockDim.x + threadIdx.x;
    if (idx < n4) {
        float4 v = ((const float4*)in)[idx];
        ((__half2*)outh)[2 * idx]     = __floats2half2_rn(v.x, v.y);
        ((__half2*)outh)[2 * idx + 1] = __floats2half2_rn(v.z, v.w);
    }
}

__global__ void zero_s_kernel() {
    int idx = blockIdx.x * blockDim.x + threadIdx.x;
    if (idx < BATCH * D_MODEL) g_s[idx] = 0.0f;
}

// ===========================================================================
// colsum (vectorized)
// ===========================================================================
__global__ __launch_bounds__(128) void colsum_kernel(const __half* __restrict__ X) {
    const int b = blockIdx.x;
    const int t0 = blockIdx.y * (T_LEN / 64);
    const int n0 = threadIdx.x * 8;
    float s[8];
    #pragma unroll
    for (int i = 0; i < 8; i++) s[i] = 0.f;
    const __half* p = X + (size_t)(t0 * BATCH + b) * D_MODEL + n0;
    #pragma unroll 4
    for (int t = 0; t < T_LEN / 64; t++) {
        uint4 v = *(const uint4*)(p + (size_t)t * BATCH * D_MODEL);
        const __half2* h = (const __half2*)&v;
        #pragma unroll
        for (int i = 0; i < 4; i++) {
            float2 f = __half22float2(h[i]);
            s[2*i] += f.x; s[2*i+1] += f.y;
        }
    }
    #pragma unroll
    for (int i = 0; i < 8; i++)
        atomicAdd(&g_s[b * D_MODEL + n0 + i], s[i]);
}

// ===========================================================================
// Transpose Wv
// ===========================================================================
__global__ __launch_bounds__(256) void transpose_wv_kernel(const __half* __restrict__ Wv,
                                                           __half* __restrict__ WvT) {
    __shared__ __half tile[32][33];
    const int bx = blockIdx.x * 32, by = blockIdx.y * 32;
    const int tx = threadIdx.x & 31, ty = threadIdx.x >> 5;
    #pragma unroll
    for (int i = 0; i < 4; i++)
        tile[ty + i * 8][tx] = Wv[(size_t)(by + ty + i * 8) * D_MODEL + bx + tx];
    __syncthreads();
    #pragma unroll
    for (int i = 0; i < 4; i++)
        WvT[(size_t)(bx + ty + i * 8) * D_MODEL + by + tx] = tile[tx][ty + i * 8];
}

// ===========================================================================
// cbias
// ===========================================================================
__global__ __launch_bounds__(256) void cbias_kernel(const float* __restrict__ bqkv,
                                                    const float* __restrict__ bout) {
    __shared__ float sbv[D_MODEL];
    for (int i = threadIdx.x; i < D_MODEL; i += 256)
        sbv[i] = bqkv[2 * D_MODEL + i];
    __syncthreads();
    const int idx = blockIdx.x * 256 + threadIdx.x;
    const int b = idx >> 10, o = idx & 1023;
    const __half* row = g_mh + (size_t)b * D_MODEL * D_MODEL + (size_t)o * D_MODEL;
    float s = 0.f;
    #pragma unroll 4
    for (int d8 = 0; d8 < D_MODEL / 8; d8++) {
        uint4 v = *(const uint4*)(row + d8 * 8);
        const __half2* h = (const __half2*)&v;
        #pragma unroll
        for (int i = 0; i < 4; i++) {
            float2 f = __half22float2(h[i]);
            s += f.x * sbv[d8 * 8 + 2 * i] + f.y * sbv[d8 * 8 + 2 * i + 1];
        }
    }
    g_c[idx] = s + bout[o];
}

// ===========================================================================
// SYRK: G_b = X_b^T X_b. Triangular 128x128 tiles. 4-stage pipeline,
// prefetch distance 3 (48 KB in flight). Dynamic smem.
// ===========================================================================
#define SKT 32
#define SROWH 136
#define S_TILEB (SKT * SROWH * 2)       // 8704
#define S_STG (2 * S_TILEB)             // 17408
#define S_NST 4
#define S_SMEMB (S_NST * S_STG)         // 69632

__global__ __launch_bounds__(256) void syrk_kernel(const __half* __restrict__ X) {
    extern __shared__ char ssm[];
    const uint32_t sb = smem_to_u32(ssm);
    const int tid = threadIdx.x, lane = tid & 31, wid = tid >> 5;
    const int b = blockIdx.y;

    int x = blockIdx.x, ti = 0;
    while (x >= 8 - ti) { x -= 8 - ti; ti++; }
    const int tj = ti + x;

    const __half* Xb = X + (size_t)b * D_MODEL;

    #define SY_ISSUE(s, buf) do { \
        _Pragma("unroll") \
        for (int i = 0; i < 4; i++) { \
            const int ci = i * 256 + tid; \
            const int r_ = (ci & 511) >> 4, c_ = ci & 15; \
            const int irange = (ci < 512) ? ti : tj; \
            const uint32_t toff = (ci < 512) ? 0u : (uint32_t)S_TILEB; \
            const __half* src = Xb + (size_t)((s) * SKT + r_) * (BATCH * D_MODEL) \
                                + irange * 128 + c_ * 8; \
            CP16(sb + (buf) * S_STG + toff + r_ * 272 + c_ * 16, src); \
        } \
    } while (0)

    float acc[4][4][4];
    #pragma unroll
    for (int mt = 0; mt < 4; mt++)
        #pragma unroll
        for (int nt = 0; nt < 4; nt++)
            #pragma unroll
            for (int r = 0; r < 4; r++) acc[mt][nt][r] = 0.0f;

    const int wi = wid >> 2;
    const int wj = wid & 3;

    const uint32_t a_base = (uint32_t)(((lane & 7) + ((lane >> 4) << 3)) * 272
                                       + (wi * 64 + ((lane >> 3) & 1) * 8) * 2);
    const uint32_t b_base = (uint32_t)((lane & 15) * 272 + ((lane >> 4) * 8 + wj * 32) * 2);

    const int NS = T_LEN / SKT;   // 256
    SY_ISSUE(0, 0); CP_COMMIT();
    SY_ISSUE(1, 1); CP_COMMIT();
    SY_ISSUE(2, 2); CP_COMMIT();

    for (int s = 0; s < NS; s++) {
        if (s >= NS - 3) { asm volatile("cp.async.wait_group 0;" ::: "memory"); }
        else             { asm volatile("cp.async.wait_group 2;" ::: "memory"); }
        __syncthreads();
        if (s + 3 < NS) { SY_ISSUE(s + 3, (s + 3) % S_NST); CP_COMMIT(); }

        const uint32_t base = sb + (s % S_NST) * S_STG;
        #pragma unroll
        for (int kk = 0; kk < 2; kk++) {
            const uint32_t krow = kk * 16 * 272;
            uint32_t a[4][4];
            #pragma unroll
            for (int mt = 0; mt < 4; mt++)
                ldsm4t(a[mt], base + a_base + krow + mt * 32);
            #pragma unroll
            for (int jn = 0; jn < 2; jn++) {
                uint32_t bb[4];
                ldsm4t(bb, base + S_TILEB + b_base + krow + jn * 32);
                #pragma unroll
                for (int mt = 0; mt < 4; mt++) {
                    mma16816(acc[mt][2*jn],   a[mt], bb[0], bb[1]);
                    mma16816(acc[mt][2*jn+1], a[mt], bb[2], bb[3]);
                }
            }
        }
        __syncthreads();
    }

    __half* G = g_G + (size_t)b * D_MODEL * D_MODEL;
    #pragma unroll
    for (int mt = 0; mt < 4; mt++) {
        #pragma unroll
        for (int jn = 0; jn < 4; jn++) {
            const int i0 = ti * 128 + wi * 64 + mt * 16 + (lane >> 2);
            const int j0 = tj * 128 + wj * 32 + jn * 8 + (lane & 3) * 2;
            const __half c0 = __float2half_rn(acc[mt][jn][0]);
            const __half c1 = __float2half_rn(acc[mt][jn][1]);
            const __half c2 = __float2half_rn(acc[mt][jn][2]);
            const __half c3 = __float2half_rn(acc[mt][jn][3]);
            *(__half2*)(G + (size_t)i0 * D_MODEL + j0)       = __halves2half2(c0, c1);
            *(__half2*)(G + (size_t)(i0 + 8) * D_MODEL + j0) = __halves2half2(c2, c3);
            if (ti != tj) {
                G[(size_t)j0 * D_MODEL + i0]           = c0;
                G[(size_t)(j0 + 1) * D_MODEL + i0]     = c1;
                G[(size_t)j0 * D_MODEL + i0 + 8]       = c2;
                G[(size_t)(j0 + 1) * D_MODEL + i0 + 8] = c3;
            }
        }
    }
}

// ===========================================================================
// Stats assembly: Wk tile stored TRANSPOSED (sTkT[n][j]) to kill the 8-way
// bank conflict in the accC inner loop.
// ===========================================================================
__global__ __launch_bounds__(256) void stats_asm_kernel(const float* __restrict__ bqkv) {
    const int head = blockIdx.x;
    const int b = head >> 4, h = head & 15;
    const int tid = threadIdx.x;

    __shared__ __half sT[3][64][72];    // 0=Hq 1=Wq 2=Hk
    __shared__ __half sTkT[64][68];     // Wk transposed: [n][j]
    __shared__ float su_q[64], su_k[64], ssqq[64], sskk[64], sch[64];

    const __half* Hq = g_Ht + (size_t)b * 2 * D_MODEL * D_MODEL + (size_t)(h * 64) * D_MODEL;
    const __half* Hk = Hq + (size_t)D_MODEL * D_MODEL;
    const __half* Wq = g_wh + (size_t)(h * 64) * D_MODEL;
    const __half* Wk = g_wh + (size_t)(D_MODEL + h * 64) * D_MODEL;
    const float* sv = g_s + b * D_MODEL;

    const int ty = tid >> 4, tx = tid & 15;
    float accC[4][4];
    #pragma unroll
    for (int a = 0; a < 4; a++)
        #pragma unroll
        for (int c = 0; c < 4; c++) accC[a][c] = 0.f;
    float aqq = 0.f, auq = 0.f, akk = 0.f, auk = 0.f;

    for (int nc = 0; nc < 16; nc++) {
        #pragma unroll
        for (int i = 0; i < 8; i++) {
            const int ci = i * 256 + tid;
            const int tile = ci >> 9, r = (ci >> 3) & 63, c = ci & 7;
            if (tile < 3) {
                const __half* src = (tile == 0 ? Hq : tile == 1 ? Wq : Hk)
                                    + (size_t)r * D_MODEL + nc * 64 + c * 8;
                *(uint4*)&sT[tile][r][c * 8] = *(const uint4*)src;
            } else {
                // Wk row r, cols nc*64 + c*8 .. +7 -> sTkT[c*8+e][r]
                const __half* src = Wk + (size_t)r * D_MODEL + nc * 64 + c * 8;
                uint4 v = *(const uint4*)src;
                const __half* hv = (const __half*)&v;
                #pragma unroll
                for (int e = 0; e < 8; e++) sTkT[c * 8 + e][r] = hv[e];
            }
        }
        if (tid < 64) sch[tid] = sv[nc * 64 + tid];
        __syncthreads();

        #pragma unroll 8
        for (int n = 0; n < 64; n++) {
            float hq[4], wk[4];
            #pragma unroll
            for (int a = 0; a < 4; a++) hq[a] = __half2float(sT[0][ty * 4 + a][n]);
            #pragma unroll
            for (int c = 0; c < 4; c++) wk[c] = __half2float(sTkT[n][tx * 4 + c]);
            #pragma unroll
            for (int a = 0; a < 4; a++)
                #pragma unroll
                for (int c = 0; c < 4; c++) accC[a][c] += hq[a] * wk[c];
        }
        if (tid < 64) {
            #pragma unroll 8
            for (int n = 0; n < 64; n++) {
                float hv = __half2float(sT[0][tid][n]);
                float wv = __half2float(sT[1][tid][n]);
                aqq += hv * wv; auq += wv * sch[n];
            }
        } else if (tid < 128) {
            const int j = tid - 64;
            #pragma unroll 8
            for (int n = 0; n < 64; n++) {
                float hv = __half2float(sT[2][j][n]);
                float wv = __half2float(sTkT[n][j]);
                akk += hv * wv; auk += wv * sch[n];
            }
        }
        __syncthreads();
    }

    if (tid < 64)       { su_q[tid] = auq; ssqq[tid] = aqq; }
    else if (tid < 128) { su_k[tid - 64] = auk; sskk[tid - 64] = akk; }
    __syncthreads();

    float* st = g_stats + (size_t)head * STATS_PER_HEAD;
    const float Tf = (float)T_LEN;
    #pragma unroll
    for (int a = 0; a < 4; a++) {
        const int i = ty * 4 + a;
        const float bq = bqkv[h * 64 + i];
        #pragma unroll
        for (int c = 0; c < 4; c++) {
            const int j = tx * 4 + c;
            const float bk = bqkv[D_MODEL + h * 64 + j];
            st[i * 64 + j] = accC[a][c] + bq * su_k[j] + su_q[i] * bk + Tf * bq * bk;
        }
    }
    if (tid < 64) {
        const int i = tid;
        const float bq = bqkv[h * 64 + i];
        st[4096 + i] = su_q[i] + Tf * bq;
        st[4224 + i] = ssqq[i] + 2.f * bq * su_q[i] + Tf * bq * bq;
    } else if (tid < 128) {
        const int j = tid - 64;
        const float bk = bqkv[D_MODEL + h * 64 + j];
        st[4160 + j] = su_k[j] + Tf * bk;
        st[4288 + j] = sskk[j] + 2.f * bk * su_k[j] + Tf * bk * bk;
    }
}

// ===========================================================================
// Fused corr + meff (unchanged)
// ===========================================================================
__global__ __launch_bounds__(256) void corr_meff_kernel(const float* __restrict__ Wout) {
    const int head = blockIdx.x;
    const int b = head >> 4, h = head & 15;
    const int tid = threadIdx.x;
    __shared__ float sc[HD][HD + 1];
    __shared__ float mq[HD], mk[HD], isx[HD], isy[HD];

    const float* st = g_stats + (size_t)head * STATS_PER_HEAD;
    const float invT = 1.0f / (float)T_LEN;

    if (tid < 64) {
        float s = st[4096 + tid], s2 = st[4224 + tid];
        mq[tid] = s;
        isx[tid] = rsqrtf(s2 - s * s * invT);
    } else if (tid < 128) {
        int j = tid - 64;
        float s = st[4160 + j], s2 = st[4288 + j];
        mk[j] = s;
        isy[j] = rsqrtf(s2 - s * s * invT);
    }
    __syncthreads();

    for (int idx = tid; idx < HD * HD; idx += 256) {
        int i = idx >> 6, j = idx & 63;
        float cov = st[idx] - mq[i] * mk[j] * invT;
        float c = cov * isx[i] * isy[j];
        c = fminf(fmaxf(c, 0.0f), 1.0f);
        sc[i][j] = c;
    }
    __syncthreads();

    if (tid < 64) {
        int j = tid;
        float mx = -1e30f;
        #pragma unroll 4
        for (int i = 0; i < HD; i++) mx = fmaxf(mx, sc[i][j]);
        float sum = 0.f;
        #pragma unroll 4
        for (int i = 0; i < HD; i++) {
            float e = expf(sc[i][j] - mx);
            sc[i][j] = e; sum += e;
        }
        float inv = 1.0f / sum;
        #pragma unroll 4
        for (int i = 0; i < HD; i++) sc[i][j] *= inv;
    }
    __syncthreads();

    const size_t mbase = (size_t)b * D_MODEL * D_MODEL + h * HD;
    const float* Wb = Wout + h * HD;

    for (int idx = tid; idx < D_MODEL * HD; idx += 256) {
        int o = idx >> 6, d = idx & 63;
        const float* wrow = Wb + (size_t)o * D_MODEL;
        float s = 0.f;
        #pragma unroll
        for (int e = 0; e < HD; e++) s += sc[d][e] * wrow[e];
        g_mh[mbase + (size_t)o * D_MODEL + d] = __float2half_rn(s);
    }
}

// ===========================================================================
// Launch  (syrk at launch index 3 for ncu capture)
// ===========================================================================
extern "C" void kernel_launch(void* const* d_in, const int* in_sizes, int n_in,
                              void* d_out, int out_size) {
    const float* query = (const float*)d_in[0];
    const float* Wqkv  = (const float*)d_in[1];
    const float* bqkv  = (const float*)d_in[2];
    const float* Wout  = (const float*)d_in[3];
    const float* bout  = (const float*)d_in[4];
    float* out = (float*)d_out;

    void* p;
    cudaGetSymbolAddress(&p, g_qh);    __half* qh  = (__half*)p;
    cudaGetSymbolAddress(&p, g_wh);    __half* wh  = (__half*)p;
    cudaGetSymbolAddress(&p, g_wvT);   __half* wvT = (__half*)p;
    cudaGetSymbolAddress(&p, g_mh);    __half* mh  = (__half*)p;
    cudaGetSymbolAddress(&p, g_P);     __half* P   = (__half*)p;
    cudaGetSymbolAddress(&p, g_G);     __half* G   = (__half*)p;
    cudaGetSymbolAddress(&p, g_Ht);    __half* Ht  = (__half*)p;
    cudaGetSymbolAddress(&p, g_zbias); float* zb   = (float*)p;
    cudaGetSymbolAddress(&p, g_c);     float* cb   = (float*)p;

    cudaFuncSetAttribute(gemm_fp16_kernel,
                         cudaFuncAttributeMaxDynamicSharedMemorySize, SMEMB);
    cudaFuncSetAttribute(syrk_kernel,
                         cudaFuncAttributeMaxDynamicSharedMemorySize, S_SMEMB);

    // idx 0-2
    {
        int n4q = NROWS * D_MODEL / 4;
        conv_half_kernel<<<n4q / 256, 256>>>(query, qh, n4q);
        int n4w = QKV_LD * D_MODEL / 4;
        conv_half_kernel<<<n4w / 256, 256>>>(Wqkv, wh, n4w);
        zero_s_kernel<<<(BATCH * D_MODEL + 255) / 256, 256>>>();
    }

    // idx 3: G_b = X_b^T X_b  (profiled by ncu)
    syrk_kernel<<<dim3(36, BATCH), 256, S_SMEMB>>>(qh);

    // idx 4-5
    transpose_wv_kernel<<<dim3(32, 32), 256>>>(
        wh + (size_t)2 * D_MODEL * D_MODEL, wvT);
    colsum_kernel<<<dim3(BATCH, 64), 128>>>(qh);

    // idx 6: Ht = Wqk * G_b
    gemm_fp16_kernel<<<dim3(D_MODEL / BN, 2 * D_MODEL / BM, BATCH), NTHR, SMEMB>>>(
        wh, D_MODEL, 0,
        G, D_MODEL, (long long)D_MODEL * D_MODEL,
        zb, 0,
        nullptr, Ht, D_MODEL, (long long)2 * D_MODEL * D_MODEL,
        D_MODEL);

    // idx 7-8
    stats_asm_kernel<<<NHEADS_TOTAL, 256>>>(bqkv);
    corr_meff_kernel<<<NHEADS_TOTAL, 256>>>(Wout);

    // idx 9: P_b = Meff_b @ WvT^T
    gemm_fp16_kernel<<<dim3(D_MODEL / BN, D_MODEL / BM, BATCH), NTHR, SMEMB>>>(
        mh, D_MODEL, (long long)D_MODEL * D_MODEL,
        wvT, D_MODEL, 0,
        zb, 0,
        nullptr, P, D_MODEL, (long long)D_MODEL * D_MODEL,
        D_MODEL);

    // idx 10
    cbias_kernel<<<16, 256>>>(bqkv, bout);

    // idx 11: out = X @ P_b^T + c_b
    gemm_fp16_kernel<<<dim3(D_MODEL / BN, T_LEN / BM, BATCH), NTHR, SMEMB>>>(
        qh, BATCH * D_MODEL, D_MODEL,
        P, D_MODEL, (long long)D_MODEL * D_MODEL,
        cb, D_MODEL,
        out, nullptr, BATCH * D_MODEL, D_MODEL,
        D_MODEL);
}

// round 13
// speedup vs baseline: 1.4767x; 1.0242x over previous
#include <cuda_runtime.h>
#include <cuda_fp16.h>
#include <cstdint>

// Problem constants
#define T_LEN   8192
#define BATCH   4
#define D_MODEL 1024
#define NHEAD   16
#define HD      64
#define QKV_LD  (3 * D_MODEL)        // 3072
#define NROWS   (T_LEN * BATCH)      // 32768
#define NHEADS_TOTAL (BATCH * NHEAD) // 64
#define STATS_PER_HEAD 4352

// Scratch (device globals: allocation-free)
__device__ __half g_qh[(size_t)NROWS * D_MODEL];                 // 64 MB  query fp16
__device__ __half g_wh[(size_t)QKV_LD * D_MODEL];                // 6 MB   Wqkv fp16
__device__ __half g_wvT[(size_t)D_MODEL * D_MODEL];              // 2 MB   Wv^T fp16
__device__ __half g_mh[(size_t)BATCH * D_MODEL * D_MODEL];       // 8 MB   Meff fp16
__device__ __half g_P[(size_t)BATCH * D_MODEL * D_MODEL];        // 8 MB   P fp16
__device__ __half g_G[(size_t)BATCH * D_MODEL * D_MODEL];        // 8 MB   Gram fp16
__device__ __half g_Ht[(size_t)BATCH * 2 * D_MODEL * D_MODEL];   // 16 MB  Wqk*G fp16
__device__ float  g_s[BATCH * D_MODEL];                          // col sums
__device__ float  g_c[BATCH * D_MODEL];                          // per-batch out bias
__device__ float  g_zbias[D_MODEL];                              // zero bias (never written)
__device__ float  g_stats[NHEADS_TOTAL * STATS_PER_HEAD];        // RAW sums

// ===========================================================================
// helpers
// ===========================================================================
__device__ __forceinline__ uint32_t smem_to_u32(const void* p) {
    uint32_t a;
    asm("{ .reg .u64 t; cvta.to.shared.u64 t, %1; cvt.u32.u64 %0, t; }"
        : "=r"(a) : "l"(p));
    return a;
}

__device__ __forceinline__ void ldsm4(uint32_t (&r)[4], uint32_t addr) {
    asm volatile("ldmatrix.sync.aligned.m8n8.x4.shared.b16 {%0,%1,%2,%3}, [%4];"
        : "=r"(r[0]), "=r"(r[1]), "=r"(r[2]), "=r"(r[3]) : "r"(addr));
}

__device__ __forceinline__ void ldsm4t(uint32_t (&r)[4], uint32_t addr) {
    asm volatile("ldmatrix.sync.aligned.m8n8.x4.trans.shared.b16 {%0,%1,%2,%3}, [%4];"
        : "=r"(r[0]), "=r"(r[1]), "=r"(r[2]), "=r"(r[3]) : "r"(addr));
}

__device__ __forceinline__ void mma16816(float (&c)[4], const uint32_t (&a)[4],
                                         uint32_t b0, uint32_t b1) {
    asm volatile(
        "mma.sync.aligned.m16n8k16.row.col.f32.f16.f16.f32 "
        "{%0,%1,%2,%3}, {%4,%5,%6,%7}, {%8,%9}, {%0,%1,%2,%3};"
        : "+f"(c[0]), "+f"(c[1]), "+f"(c[2]), "+f"(c[3])
        : "r"(a[0]), "r"(a[1]), "r"(a[2]), "r"(a[3]), "r"(b0), "r"(b1));
}

#define CP_COMMIT() asm volatile("cp.async.commit_group;" ::: "memory")
#define CP16(dst, src) \
    asm volatile("cp.async.cg.shared.global [%0], [%1], 16;" \
        :: "r"(dst), "l"(src) : "memory")

// ===========================================================================
// fp16 single-pass HMMA GEMM (NT)  (unchanged)
// ===========================================================================
#define BM 256
#define BN 128
#define BK 32
#define NTHR 256
#define ROWB 80
#define A_TILEB (256 * ROWB)
#define B_TILEB (128 * ROWB)
#define OFF_A  0
#define OFF_B  A_TILEB
#define STAGEB (A_TILEB + B_TILEB)
#define NSTAGE 4
#define SMEMB (NSTAGE * STAGEB)         // 122880

__global__ void __launch_bounds__(NTHR, 1) gemm_fp16_kernel(
    const __half* __restrict__ Ah, int strideA, long long batchA,
    const __half* __restrict__ Bh, int strideB, long long batchB,
    const float* __restrict__ bias, long long biasBatch,
    float* __restrict__ C, __half* __restrict__ Ch,
    int strideC, long long batchC,
    int K)
{
    extern __shared__ char smem[];
    const uint32_t sb = smem_to_u32(smem);
    const int tid = threadIdx.x;
    const int lane = tid & 31;
    const int wid = tid >> 5;
    const int wm = (wid >> 1) * 64;
    const int wn = (wid & 1) * 64;
    const int z = blockIdx.z;

    const __half* Ab = Ah + (size_t)blockIdx.y * BM * strideA + (size_t)z * batchA;
    const __half* Bb = Bh + (size_t)blockIdx.x * BN * strideB + (size_t)z * batchB;
    const float* biasz = bias + (size_t)z * biasBatch;

    float acc[4][8][4];
    #pragma unroll
    for (int mt = 0; mt < 4; mt++)
        #pragma unroll
        for (int nt = 0; nt < 8; nt++)
            #pragma unroll
            for (int r = 0; r < 4; r++) acc[mt][nt][r] = 0.0f;

    const int NKT = K / BK;

    #define ISSUE_STAGE(kt, buf) do { \
        const uint32_t sbase = sb + (buf) * STAGEB; \
        _Pragma("unroll") \
        for (int i = 0; i < 6; i++) { \
            const int ci = i * NTHR + tid; \
            const __half* src; uint32_t dst; \
            if (i < 4) { \
                const int r_ = ci >> 2, c_ = ci & 3; \
                src = Ab + (size_t)r_ * strideA + (kt) * BK + c_ * 8; \
                dst = sbase + OFF_A + r_ * ROWB + c_ * 16; \
            } else { \
                const int j_ = ci - 1024, r_ = j_ >> 2, c_ = j_ & 3; \
                src = Bb + (size_t)r_ * strideB + (kt) * BK + c_ * 8; \
                dst = sbase + OFF_B + r_ * ROWB + c_ * 16; \
            } \
            CP16(dst, src); \
        } \
    } while (0)

    ISSUE_STAGE(0, 0); CP_COMMIT();
    ISSUE_STAGE(1, 1); CP_COMMIT();
    ISSUE_STAGE(2, 2); CP_COMMIT();

    const uint32_t a_off = (uint32_t)((lane & 15) * ROWB + (lane >> 4) * 16);
    const uint32_t b_row = (uint32_t)((lane & 7) + ((lane >> 4) << 3));
    const uint32_t b_off = (uint32_t)(b_row * ROWB + ((lane >> 3) & 1) * 16);

    for (int kt = 0; kt < NKT; kt++) {
        asm volatile("cp.async.wait_group 2;" ::: "memory");
        __syncthreads();

        if (kt + 3 < NKT) { ISSUE_STAGE(kt + 3, (kt + 3) % NSTAGE); CP_COMMIT(); }

        const uint32_t base = sb + (kt % NSTAGE) * STAGEB;
        #pragma unroll
        for (int kk = 0; kk < 2; kk++) {
            const uint32_t koff = kk * 32;
            uint32_t a[4][4];
            #pragma unroll
            for (int mt = 0; mt < 4; mt++)
                ldsm4(a[mt], base + OFF_A + (wm + mt * 16) * ROWB + a_off + koff);
            #pragma unroll
            for (int ng = 0; ng < 4; ng++) {
                uint32_t bh[4];
                ldsm4(bh, base + OFF_B + (wn + ng * 16) * ROWB + b_off + koff);
                #pragma unroll
                for (int mt = 0; mt < 4; mt++) {
                    mma16816(acc[mt][2*ng],   a[mt], bh[0], bh[1]);
                    mma16816(acc[mt][2*ng+1], a[mt], bh[2], bh[3]);
                }
            }
        }
    }

    const int rbase = blockIdx.y * BM + wm + (lane >> 2);
    const int cbase = blockIdx.x * BN + wn + (lane & 3) * 2;
    #pragma unroll
    for (int mt = 0; mt < 4; mt++) {
        #pragma unroll
        for (int nt = 0; nt < 8; nt++) {
            const int row = rbase + mt * 16;
            const int col = cbase + nt * 8;
            const float b0 = biasz[col], b1 = biasz[col + 1];
            const float v0 = acc[mt][nt][0] + b0, v1 = acc[mt][nt][1] + b1;
            const float v2 = acc[mt][nt][2] + b0, v3 = acc[mt][nt][3] + b1;
            if (Ch != nullptr) {
                __half* Chz = Ch + (size_t)z * batchC;
                *(__half2*)(Chz + (size_t)row * strideC + col)       = __floats2half2_rn(v0, v1);
                *(__half2*)(Chz + (size_t)(row + 8) * strideC + col) = __floats2half2_rn(v2, v3);
            } else {
                float* Cz = C + (size_t)z * batchC;
                float2 o0, o1;
                o0.x = v0; o0.y = v1; o1.x = v2; o1.y = v3;
                *(float2*)(Cz + (size_t)row * strideC + col) = o0;
                *(float2*)(Cz + (size_t)(row + 8) * strideC + col) = o1;
            }
        }
    }
}

// ===========================================================================
// Converter: fp32 -> fp16
// ===========================================================================
__global__ void conv_half_kernel(const float* __restrict__ in,
                                 __half* __restrict__ outh, int n4) {
    int idx = blockIdx.x * blockDim.x + threadIdx.x;
    if (idx < n4) {
        float4 v = ((const float4*)in)[idx];
        ((__half2*)outh)[2 * idx]     = __floats2half2_rn(v.x, v.y);
        ((__half2*)outh)[2 * idx + 1] = __floats2half2_rn(v.z, v.w);
    }
}

// zero g_s + g_stats in one launch
__global__ void zero_kernel() {
    int idx = blockIdx.x * blockDim.x + threadIdx.x;
    if (idx < BATCH * D_MODEL) g_s[idx] = 0.0f;
    if (idx < NHEADS_TOTAL * STATS_PER_HEAD) g_stats[idx] = 0.0f;
}

// ===========================================================================
// colsum (vectorized)
// ===========================================================================
__global__ __launch_bounds__(128) void colsum_kernel(const __half* __restrict__ X) {
    const int b = blockIdx.x;
    const int t0 = blockIdx.y * (T_LEN / 64);
    const int n0 = threadIdx.x * 8;
    float s[8];
    #pragma unroll
    for (int i = 0; i < 8; i++) s[i] = 0.f;
    const __half* p = X + (size_t)(t0 * BATCH + b) * D_MODEL + n0;
    #pragma unroll 4
    for (int t = 0; t < T_LEN / 64; t++) {
        uint4 v = *(const uint4*)(p + (size_t)t * BATCH * D_MODEL);
        const __half2* h = (const __half2*)&v;
        #pragma unroll
        for (int i = 0; i < 4; i++) {
            float2 f = __half22float2(h[i]);
            s[2*i] += f.x; s[2*i+1] += f.y;
        }
    }
    #pragma unroll
    for (int i = 0; i < 8; i++)
        atomicAdd(&g_s[b * D_MODEL + n0 + i], s[i]);
}

// ===========================================================================
// Transpose Wv
// ===========================================================================
__global__ __launch_bounds__(256) void transpose_wv_kernel(const __half* __restrict__ Wv,
                                                           __half* __restrict__ WvT) {
    __shared__ __half tile[32][33];
    const int bx = blockIdx.x * 32, by = blockIdx.y * 32;
    const int tx = threadIdx.x & 31, ty = threadIdx.x >> 5;
    #pragma unroll
    for (int i = 0; i < 4; i++)
        tile[ty + i * 8][tx] = Wv[(size_t)(by + ty + i * 8) * D_MODEL + bx + tx];
    __syncthreads();
    #pragma unroll
    for (int i = 0; i < 4; i++)
        WvT[(size_t)(bx + ty + i * 8) * D_MODEL + by + tx] = tile[tx][ty + i * 8];
}

// ===========================================================================
// cbias
// ===========================================================================
__global__ __launch_bounds__(256) void cbias_kernel(const float* __restrict__ bqkv,
                                                    const float* __restrict__ bout) {
    __shared__ float sbv[D_MODEL];
    for (int i = threadIdx.x; i < D_MODEL; i += 256)
        sbv[i] = bqkv[2 * D_MODEL + i];
    __syncthreads();
    const int idx = blockIdx.x * 256 + threadIdx.x;
    const int b = idx >> 10, o = idx & 1023;
    const __half* row = g_mh + (size_t)b * D_MODEL * D_MODEL + (size_t)o * D_MODEL;
    float s = 0.f;
    #pragma unroll 4
    for (int d8 = 0; d8 < D_MODEL / 8; d8++) {
        uint4 v = *(const uint4*)(row + d8 * 8);
        const __half2* h = (const __half2*)&v;
        #pragma unroll
        for (int i = 0; i < 4; i++) {
            float2 f = __half22float2(h[i]);
            s += f.x * sbv[d8 * 8 + 2 * i] + f.y * sbv[d8 * 8 + 2 * i + 1];
        }
    }
    g_c[idx] = s + bout[o];
}

// ===========================================================================
// SYRK (unchanged from R12 — at mma floor)
// ===========================================================================
#define SKT 32
#define SROWH 136
#define S_TILEB (SKT * SROWH * 2)
#define S_STG (2 * S_TILEB)
#define S_NST 4
#define S_SMEMB (S_NST * S_STG)         // 69632

__global__ __launch_bounds__(256) void syrk_kernel(const __half* __restrict__ X) {
    extern __shared__ char ssm[];
    const uint32_t sb = smem_to_u32(ssm);
    const int tid = threadIdx.x, lane = tid & 31, wid = tid >> 5;
    const int b = blockIdx.y;

    int x = blockIdx.x, ti = 0;
    while (x >= 8 - ti) { x -= 8 - ti; ti++; }
    const int tj = ti + x;

    const __half* Xb = X + (size_t)b * D_MODEL;

    #define SY_ISSUE(s, buf) do { \
        _Pragma("unroll") \
        for (int i = 0; i < 4; i++) { \
            const int ci = i * 256 + tid; \
            const int r_ = (ci & 511) >> 4, c_ = ci & 15; \
            const int irange = (ci < 512) ? ti : tj; \
            const uint32_t toff = (ci < 512) ? 0u : (uint32_t)S_TILEB; \
            const __half* src = Xb + (size_t)((s) * SKT + r_) * (BATCH * D_MODEL) \
                                + irange * 128 + c_ * 8; \
            CP16(sb + (buf) * S_STG + toff + r_ * 272 + c_ * 16, src); \
        } \
    } while (0)

    float acc[4][4][4];
    #pragma unroll
    for (int mt = 0; mt < 4; mt++)
        #pragma unroll
        for (int nt = 0; nt < 4; nt++)
            #pragma unroll
            for (int r = 0; r < 4; r++) acc[mt][nt][r] = 0.0f;

    const int wi = wid >> 2;
    const int wj = wid & 3;

    const uint32_t a_base = (uint32_t)(((lane & 7) + ((lane >> 4) << 3)) * 272
                                       + (wi * 64 + ((lane >> 3) & 1) * 8) * 2);
    const uint32_t b_base = (uint32_t)((lane & 15) * 272 + ((lane >> 4) * 8 + wj * 32) * 2);

    const int NS = T_LEN / SKT;
    SY_ISSUE(0, 0); CP_COMMIT();
    SY_ISSUE(1, 1); CP_COMMIT();
    SY_ISSUE(2, 2); CP_COMMIT();

    for (int s = 0; s < NS; s++) {
        if (s >= NS - 3) { asm volatile("cp.async.wait_group 0;" ::: "memory"); }
        else             { asm volatile("cp.async.wait_group 2;" ::: "memory"); }
        __syncthreads();
        if (s + 3 < NS) { SY_ISSUE(s + 3, (s + 3) % S_NST); CP_COMMIT(); }

        const uint32_t base = sb + (s % S_NST) * S_STG;
        #pragma unroll
        for (int kk = 0; kk < 2; kk++) {
            const uint32_t krow = kk * 16 * 272;
            uint32_t a[4][4];
            #pragma unroll
            for (int mt = 0; mt < 4; mt++)
                ldsm4t(a[mt], base + a_base + krow + mt * 32);
            #pragma unroll
            for (int jn = 0; jn < 2; jn++) {
                uint32_t bb[4];
                ldsm4t(bb, base + S_TILEB + b_base + krow + jn * 32);
                #pragma unroll
                for (int mt = 0; mt < 4; mt++) {
                    mma16816(acc[mt][2*jn],   a[mt], bb[0], bb[1]);
                    mma16816(acc[mt][2*jn+1], a[mt], bb[2], bb[3]);
                }
            }
        }
        __syncthreads();
    }

    __half* G = g_G + (size_t)b * D_MODEL * D_MODEL;
    #pragma unroll
    for (int mt = 0; mt < 4; mt++) {
        #pragma unroll
        for (int jn = 0; jn < 4; jn++) {
            const int i0 = ti * 128 + wi * 64 + mt * 16 + (lane >> 2);
            const int j0 = tj * 128 + wj * 32 + jn * 8 + (lane & 3) * 2;
            const __half c0 = __float2half_rn(acc[mt][jn][0]);
            const __half c1 = __float2half_rn(acc[mt][jn][1]);
            const __half c2 = __float2half_rn(acc[mt][jn][2]);
            const __half c3 = __float2half_rn(acc[mt][jn][3]);
            *(__half2*)(G + (size_t)i0 * D_MODEL + j0)       = __halves2half2(c0, c1);
            *(__half2*)(G + (size_t)(i0 + 8) * D_MODEL + j0) = __halves2half2(c2, c3);
            if (ti != tj) {
                G[(size_t)j0 * D_MODEL + i0]           = c0;
                G[(size_t)(j0 + 1) * D_MODEL + i0]     = c1;
                G[(size_t)j0 * D_MODEL + i0 + 8]       = c2;
                G[(size_t)(j0 + 1) * D_MODEL + i0 + 8] = c3;
            }
        }
    }
}

// ===========================================================================
// Stats partial: grid (4 n-chunks, 64 heads). Accumulates RAW sums into
// g_stats via atomics: C_raw[i][j], uq[i], qq[i], uk[j], kk[j].
// Bias algebra is applied later in corr_meff.
// ===========================================================================
__global__ __launch_bounds__(256) void stats_part_kernel() {
    const int chunk = blockIdx.x;         // 0..3
    const int head = blockIdx.y;
    const int b = head >> 4, h = head & 15;
    const int tid = threadIdx.x;

    __shared__ __half sT[3][64][72];    // 0=Hq 1=Wq 2=Hk
    __shared__ __half sTkT[64][68];     // Wk transposed: [n][j]
    __shared__ float sch[64];

    const __half* Hq = g_Ht + (size_t)b * 2 * D_MODEL * D_MODEL + (size_t)(h * 64) * D_MODEL;
    const __half* Hk = Hq + (size_t)D_MODEL * D_MODEL;
    const __half* Wq = g_wh + (size_t)(h * 64) * D_MODEL;
    const __half* Wk = g_wh + (size_t)(D_MODEL + h * 64) * D_MODEL;
    const float* sv = g_s + b * D_MODEL;

    const int ty = tid >> 4, tx = tid & 15;
    float accC[4][4];
    #pragma unroll
    for (int a = 0; a < 4; a++)
        #pragma unroll
        for (int c = 0; c < 4; c++) accC[a][c] = 0.f;
    float aqq = 0.f, auq = 0.f, akk = 0.f, auk = 0.f;

    for (int ncl = 0; ncl < 4; ncl++) {
        const int nc = chunk * 4 + ncl;
        #pragma unroll
        for (int i = 0; i < 8; i++) {
            const int ci = i * 256 + tid;
            const int tile = ci >> 9, r = (ci >> 3) & 63, c = ci & 7;
            if (tile < 3) {
                const __half* src = (tile == 0 ? Hq : tile == 1 ? Wq : Hk)
                                    + (size_t)r * D_MODEL + nc * 64 + c * 8;
                *(uint4*)&sT[tile][r][c * 8] = *(const uint4*)src;
            } else {
                const __half* src = Wk + (size_t)r * D_MODEL + nc * 64 + c * 8;
                uint4 v = *(const uint4*)src;
                const __half* hv = (const __half*)&v;
                #pragma unroll
                for (int e = 0; e < 8; e++) sTkT[c * 8 + e][r] = hv[e];
            }
        }
        if (tid < 64) sch[tid] = sv[nc * 64 + tid];
        __syncthreads();

        #pragma unroll 8
        for (int n = 0; n < 64; n++) {
            float hq[4], wk[4];
            #pragma unroll
            for (int a = 0; a < 4; a++) hq[a] = __half2float(sT[0][ty * 4 + a][n]);
            #pragma unroll
            for (int c = 0; c < 4; c++) wk[c] = __half2float(sTkT[n][tx * 4 + c]);
            #pragma unroll
            for (int a = 0; a < 4; a++)
                #pragma unroll
                for (int c = 0; c < 4; c++) accC[a][c] += hq[a] * wk[c];
        }
        if (tid < 64) {
            #pragma unroll 8
            for (int n = 0; n < 64; n++) {
                float hv = __half2float(sT[0][tid][n]);
                float wv = __half2float(sT[1][tid][n]);
                aqq += hv * wv; auq += wv * sch[n];
            }
        } else if (tid < 128) {
            const int j = tid - 64;
            #pragma unroll 8
            for (int n = 0; n < 64; n++) {
                float hv = __half2float(sT[2][j][n]);
                float wv = __half2float(sTkT[n][j]);
                akk += hv * wv; auk += wv * sch[n];
            }
        }
        __syncthreads();
    }

    float* st = g_stats + (size_t)head * STATS_PER_HEAD;
    #pragma unroll
    for (int a = 0; a < 4; a++)
        #pragma unroll
        for (int c = 0; c < 4; c++)
            atomicAdd(&st[(ty * 4 + a) * 64 + (tx * 4 + c)], accC[a][c]);
    if (tid < 64) {
        atomicAdd(&st[4096 + tid], auq);
        atomicAdd(&st[4224 + tid], aqq);
    } else if (tid < 128) {
        atomicAdd(&st[4160 + (tid - 64)], auk);
        atomicAdd(&st[4288 + (tid - 64)], akk);
    }
}

// ===========================================================================
// Fused corr + meff: applies bias algebra to RAW stats, then softmax + Meff.
// ===========================================================================
__global__ __launch_bounds__(256) void corr_meff_kernel(const float* __restrict__ bqkv,
                                                        const float* __restrict__ Wout) {
    const int head = blockIdx.x;
    const int b = head >> 4, h = head & 15;
    const int tid = threadIdx.x;
    __shared__ float sc[HD][HD + 1];
    __shared__ float mq[HD], mk[HD], isx[HD], isy[HD];
    __shared__ float suq[HD], suk[HD], sbq[HD], sbk[HD];

    const float* st = g_stats + (size_t)head * STATS_PER_HEAD;
    const float invT = 1.0f / (float)T_LEN;
    const float Tf = (float)T_LEN;

    if (tid < 64) {
        const int i = tid;
        const float uq = st[4096 + i], qq = st[4224 + i];
        const float bq = bqkv[h * 64 + i];
        const float Sq = uq + Tf * bq;
        const float Sqq = qq + 2.f * bq * uq + Tf * bq * bq;
        suq[i] = uq; sbq[i] = bq;
        mq[i] = Sq;
        isx[i] = rsqrtf(Sqq - Sq * Sq * invT);
    } else if (tid < 128) {
        const int j = tid - 64;
        const float uk = st[4160 + j], kk = st[4288 + j];
        const float bk = bqkv[D_MODEL + h * 64 + j];
        const float Sk = uk + Tf * bk;
        const float Skk = kk + 2.f * bk * uk + Tf * bk * bk;
        suk[j] = uk; sbk[j] = bk;
        mk[j] = Sk;
        isy[j] = rsqrtf(Skk - Sk * Sk * invT);
    }
    __syncthreads();

    for (int idx = tid; idx < HD * HD; idx += 256) {
        int i = idx >> 6, j = idx & 63;
        float C = st[idx] + sbq[i] * suk[j] + suq[i] * sbk[j] + Tf * sbq[i] * sbk[j];
        float cov = C - mq[i] * mk[j] * invT;
        float c = cov * isx[i] * isy[j];
        c = fminf(fmaxf(c, 0.0f), 1.0f);
        sc[i][j] = c;
    }
    __syncthreads();

    if (tid < 64) {
        int j = tid;
        float mx = -1e30f;
        #pragma unroll 4
        for (int i = 0; i < HD; i++) mx = fmaxf(mx, sc[i][j]);
        float sum = 0.f;
        #pragma unroll 4
        for (int i = 0; i < HD; i++) {
            float e = expf(sc[i][j] - mx);
            sc[i][j] = e; sum += e;
        }
        float inv = 1.0f / sum;
        #pragma unroll 4
        for (int i = 0; i < HD; i++) sc[i][j] *= inv;
    }
    __syncthreads();

    const size_t mbase = (size_t)b * D_MODEL * D_MODEL + h * HD;
    const float* Wb = Wout + h * HD;

    for (int idx = tid; idx < D_MODEL * HD; idx += 256) {
        int o = idx >> 6, d = idx & 63;
        const float* wrow = Wb + (size_t)o * D_MODEL;
        float s = 0.f;
        #pragma unroll
        for (int e = 0; e < HD; e++) s += sc[d][e] * wrow[e];
        g_mh[mbase + (size_t)o * D_MODEL + d] = __float2half_rn(s);
    }
}

// ===========================================================================
// Launch (Ht gemm at profile index 3)
// ===========================================================================
extern "C" void kernel_launch(void* const* d_in, const int* in_sizes, int n_in,
                              void* d_out, int out_size) {
    const float* query = (const float*)d_in[0];
    const float* Wqkv  = (const float*)d_in[1];
    const float* bqkv  = (const float*)d_in[2];
    const float* Wout  = (const float*)d_in[3];
    const float* bout  = (const float*)d_in[4];
    float* out = (float*)d_out;

    void* p;
    cudaGetSymbolAddress(&p, g_qh);    __half* qh  = (__half*)p;
    cudaGetSymbolAddress(&p, g_wh);    __half* wh  = (__half*)p;
    cudaGetSymbolAddress(&p, g_wvT);   __half* wvT = (__half*)p;
    cudaGetSymbolAddress(&p, g_mh);    __half* mh  = (__half*)p;
    cudaGetSymbolAddress(&p, g_P);     __half* P   = (__half*)p;
    cudaGetSymbolAddress(&p, g_G);     __half* G   = (__half*)p;
    cudaGetSymbolAddress(&p, g_Ht);    __half* Ht  = (__half*)p;
    cudaGetSymbolAddress(&p, g_zbias); float* zb   = (float*)p;
    cudaGetSymbolAddress(&p, g_c);     float* cb   = (float*)p;

    cudaFuncSetAttribute(gemm_fp16_kernel,
                         cudaFuncAttributeMaxDynamicSharedMemorySize, SMEMB);
    cudaFuncSetAttribute(syrk_kernel,
                         cudaFuncAttributeMaxDynamicSharedMemorySize, S_SMEMB);

    // idx 0: Wqkv -> fp16
    {
        int n4w = QKV_LD * D_MODEL / 4;
        conv_half_kernel<<<n4w / 256, 256>>>(Wqkv, wh, n4w);
    }
    // idx 1: query -> fp16
    {
        int n4q = NROWS * D_MODEL / 4;
        conv_half_kernel<<<n4q / 256, 256>>>(query, qh, n4q);
    }
    // idx 2: G_b = X_b^T X_b
    syrk_kernel<<<dim3(36, BATCH), 256, S_SMEMB>>>(qh);

    // idx 3: Ht = Wqk * G_b   (profiled by ncu)
    gemm_fp16_kernel<<<dim3(D_MODEL / BN, 2 * D_MODEL / BM, BATCH), NTHR, SMEMB>>>(
        wh, D_MODEL, 0,
        G, D_MODEL, (long long)D_MODEL * D_MODEL,
        zb, 0,
        nullptr, Ht, D_MODEL, (long long)2 * D_MODEL * D_MODEL,
        D_MODEL);

    // idx 4: zero accumulators
    {
        int total = NHEADS_TOTAL * STATS_PER_HEAD;
        zero_kernel<<<(total + 1023) / 1024, 1024>>>();
    }
    // idx 5-6
    colsum_kernel<<<dim3(BATCH, 64), 128>>>(qh);
    transpose_wv_kernel<<<dim3(32, 32), 256>>>(
        wh + (size_t)2 * D_MODEL * D_MODEL, wvT);

    // idx 7: raw stats (4-way parallel over n)
    stats_part_kernel<<<dim3(4, NHEADS_TOTAL), 256>>>();

    // idx 8: corr + softmax + Meff (bias algebra inside)
    corr_meff_kernel<<<NHEADS_TOTAL, 256>>>(bqkv, Wout);

    // idx 9: P_b = Meff_b @ WvT^T
    gemm_fp16_kernel<<<dim3(D_MODEL / BN, D_MODEL / BM, BATCH), NTHR, SMEMB>>>(
        mh, D_MODEL, (long long)D_MODEL * D_MODEL,
        wvT, D_MODEL, 0,
        zb, 0,
        nullptr, P, D_MODEL, (long long)D_MODEL * D_MODEL,
        D_MODEL);

    // idx 10
    cbias_kernel<<<16, 256>>>(bqkv, bout);

    // idx 11: out = X @ P_b^T + c_b
    gemm_fp16_kernel<<<dim3(D_MODEL / BN, T_LEN / BM, BATCH), NTHR, SMEMB>>>(
        qh, BATCH * D_MODEL, D_MODEL,
        P, D_MODEL, (long long)D_MODEL * D_MODEL,
        cb, D_MODEL,
        out, nullptr, BATCH * D_MODEL, D_MODEL,
        D_MODEL);
}

// round 14
// speedup vs baseline: 1.4951x; 1.0125x over previous
#include <cuda_runtime.h>
#include <cuda_fp16.h>
#include <cstdint>

// Problem constants
#define T_LEN   8192
#define BATCH   4
#define D_MODEL 1024
#define NHEAD   16
#define HD      64
#define QKV_LD  (3 * D_MODEL)        // 3072
#define NROWS   (T_LEN * BATCH)      // 32768
#define NHEADS_TOTAL (BATCH * NHEAD) // 64
#define STATS_PER_HEAD 4352

// Scratch (device globals: allocation-free)
__device__ __half g_qh[(size_t)NROWS * D_MODEL];                 // 64 MB  query fp16
__device__ __half g_wh[(size_t)QKV_LD * D_MODEL];                // 6 MB   Wqkv fp16
__device__ __half g_wvT[(size_t)D_MODEL * D_MODEL];              // 2 MB   Wv^T fp16
__device__ __half g_mh[(size_t)BATCH * D_MODEL * D_MODEL];       // 8 MB   Meff fp16
__device__ __half g_P[(size_t)BATCH * D_MODEL * D_MODEL];        // 8 MB   P fp16
__device__ __half g_G[(size_t)BATCH * D_MODEL * D_MODEL];        // 8 MB   Gram fp16
__device__ __half g_Ht[(size_t)BATCH * 2 * D_MODEL * D_MODEL];   // 16 MB  Wqk*G fp16
__device__ float  g_s[BATCH * D_MODEL];                          // col sums
__device__ float  g_c[BATCH * D_MODEL];                          // per-batch out bias
__device__ float  g_zbias[D_MODEL];                              // zero bias (never written)
__device__ float  g_stats[NHEADS_TOTAL * STATS_PER_HEAD];        // RAW sums

// ===========================================================================
// helpers
// ===========================================================================
__device__ __forceinline__ uint32_t smem_to_u32(const void* p) {
    uint32_t a;
    asm("{ .reg .u64 t; cvta.to.shared.u64 t, %1; cvt.u32.u64 %0, t; }"
        : "=r"(a) : "l"(p));
    return a;
}

__device__ __forceinline__ void ldsm4(uint32_t (&r)[4], uint32_t addr) {
    asm volatile("ldmatrix.sync.aligned.m8n8.x4.shared.b16 {%0,%1,%2,%3}, [%4];"
        : "=r"(r[0]), "=r"(r[1]), "=r"(r[2]), "=r"(r[3]) : "r"(addr));
}

__device__ __forceinline__ void ldsm4t(uint32_t (&r)[4], uint32_t addr) {
    asm volatile("ldmatrix.sync.aligned.m8n8.x4.trans.shared.b16 {%0,%1,%2,%3}, [%4];"
        : "=r"(r[0]), "=r"(r[1]), "=r"(r[2]), "=r"(r[3]) : "r"(addr));
}

__device__ __forceinline__ void mma16816(float (&c)[4], const uint32_t (&a)[4],
                                         uint32_t b0, uint32_t b1) {
    asm volatile(
        "mma.sync.aligned.m16n8k16.row.col.f32.f16.f16.f32 "
        "{%0,%1,%2,%3}, {%4,%5,%6,%7}, {%8,%9}, {%0,%1,%2,%3};"
        : "+f"(c[0]), "+f"(c[1]), "+f"(c[2]), "+f"(c[3])
        : "r"(a[0]), "r"(a[1]), "r"(a[2]), "r"(a[3]), "r"(b0), "r"(b1));
}

#define CP_COMMIT() asm volatile("cp.async.commit_group;" ::: "memory")
#define CP16(dst, src) \
    asm volatile("cp.async.cg.shared.global [%0], [%1], 16;" \
        :: "r"(dst), "l"(src) : "memory")

// ===========================================================================
// fp16 single-pass HMMA GEMM (NT)  (unchanged)
// ===========================================================================
#define BM 256
#define BN 128
#define BK 32
#define NTHR 256
#define ROWB 80
#define A_TILEB (256 * ROWB)
#define B_TILEB (128 * ROWB)
#define OFF_A  0
#define OFF_B  A_TILEB
#define STAGEB (A_TILEB + B_TILEB)
#define NSTAGE 4
#define SMEMB (NSTAGE * STAGEB)         // 122880

__global__ void __launch_bounds__(NTHR, 1) gemm_fp16_kernel(
    const __half* __restrict__ Ah, int strideA, long long batchA,
    const __half* __restrict__ Bh, int strideB, long long batchB,
    const float* __restrict__ bias, long long biasBatch,
    float* __restrict__ C, __half* __restrict__ Ch,
    int strideC, long long batchC,
    int K)
{
    extern __shared__ char smem[];
    const uint32_t sb = smem_to_u32(smem);
    const int tid = threadIdx.x;
    const int lane = tid & 31;
    const int wid = tid >> 5;
    const int wm = (wid >> 1) * 64;
    const int wn = (wid & 1) * 64;
    const int z = blockIdx.z;

    const __half* Ab = Ah + (size_t)blockIdx.y * BM * strideA + (size_t)z * batchA;
    const __half* Bb = Bh + (size_t)blockIdx.x * BN * strideB + (size_t)z * batchB;
    const float* biasz = bias + (size_t)z * biasBatch;

    float acc[4][8][4];
    #pragma unroll
    for (int mt = 0; mt < 4; mt++)
        #pragma unroll
        for (int nt = 0; nt < 8; nt++)
            #pragma unroll
            for (int r = 0; r < 4; r++) acc[mt][nt][r] = 0.0f;

    const int NKT = K / BK;

    #define ISSUE_STAGE(kt, buf) do { \
        const uint32_t sbase = sb + (buf) * STAGEB; \
        _Pragma("unroll") \
        for (int i = 0; i < 6; i++) { \
            const int ci = i * NTHR + tid; \
            const __half* src; uint32_t dst; \
            if (i < 4) { \
                const int r_ = ci >> 2, c_ = ci & 3; \
                src = Ab + (size_t)r_ * strideA + (kt) * BK + c_ * 8; \
                dst = sbase + OFF_A + r_ * ROWB + c_ * 16; \
            } else { \
                const int j_ = ci - 1024, r_ = j_ >> 2, c_ = j_ & 3; \
                src = Bb + (size_t)r_ * strideB + (kt) * BK + c_ * 8; \
                dst = sbase + OFF_B + r_ * ROWB + c_ * 16; \
            } \
            CP16(dst, src); \
        } \
    } while (0)

    ISSUE_STAGE(0, 0); CP_COMMIT();
    ISSUE_STAGE(1, 1); CP_COMMIT();
    ISSUE_STAGE(2, 2); CP_COMMIT();

    const uint32_t a_off = (uint32_t)((lane & 15) * ROWB + (lane >> 4) * 16);
    const uint32_t b_row = (uint32_t)((lane & 7) + ((lane >> 4) << 3));
    const uint32_t b_off = (uint32_t)(b_row * ROWB + ((lane >> 3) & 1) * 16);

    for (int kt = 0; kt < NKT; kt++) {
        asm volatile("cp.async.wait_group 2;" ::: "memory");
        __syncthreads();

        if (kt + 3 < NKT) { ISSUE_STAGE(kt + 3, (kt + 3) % NSTAGE); CP_COMMIT(); }

        const uint32_t base = sb + (kt % NSTAGE) * STAGEB;
        #pragma unroll
        for (int kk = 0; kk < 2; kk++) {
            const uint32_t koff = kk * 32;
            uint32_t a[4][4];
            #pragma unroll
            for (int mt = 0; mt < 4; mt++)
                ldsm4(a[mt], base + OFF_A + (wm + mt * 16) * ROWB + a_off + koff);
            #pragma unroll
            for (int ng = 0; ng < 4; ng++) {
                uint32_t bh[4];
                ldsm4(bh, base + OFF_B + (wn + ng * 16) * ROWB + b_off + koff);
                #pragma unroll
                for (int mt = 0; mt < 4; mt++) {
                    mma16816(acc[mt][2*ng],   a[mt], bh[0], bh[1]);
                    mma16816(acc[mt][2*ng+1], a[mt], bh[2], bh[3]);
                }
            }
        }
    }

    const int rbase = blockIdx.y * BM + wm + (lane >> 2);
    const int cbase = blockIdx.x * BN + wn + (lane & 3) * 2;
    #pragma unroll
    for (int mt = 0; mt < 4; mt++) {
        #pragma unroll
        for (int nt = 0; nt < 8; nt++) {
            const int row = rbase + mt * 16;
            const int col = cbase + nt * 8;
            const float b0 = biasz[col], b1 = biasz[col + 1];
            const float v0 = acc[mt][nt][0] + b0, v1 = acc[mt][nt][1] + b1;
            const float v2 = acc[mt][nt][2] + b0, v3 = acc[mt][nt][3] + b1;
            if (Ch != nullptr) {
                __half* Chz = Ch + (size_t)z * batchC;
                *(__half2*)(Chz + (size_t)row * strideC + col)       = __floats2half2_rn(v0, v1);
                *(__half2*)(Chz + (size_t)(row + 8) * strideC + col) = __floats2half2_rn(v2, v3);
            } else {
                float* Cz = C + (size_t)z * batchC;
                float2 o0, o1;
                o0.x = v0; o0.y = v1; o1.x = v2; o1.y = v3;
                *(float2*)(Cz + (size_t)row * strideC + col) = o0;
                *(float2*)(Cz + (size_t)(row + 8) * strideC + col) = o1;
            }
        }
    }
}

// ===========================================================================
// ILP converter: fp32 -> fp16. Each thread: 4 independent float4 loads
// (64B), 2 uint4 stores (32B). MLP=4 hides DRAM latency.
// n16 = number of 4-float4 groups.
// ===========================================================================
__global__ __launch_bounds__(256) void conv_half_ilp_kernel(
    const float4* __restrict__ in, uint4* __restrict__ out, int n16)
{
    const int idx = blockIdx.x * 256 + threadIdx.x;
    if (idx >= n16) return;
    const int i0 = idx * 4;
    float4 v0 = in[i0], v1 = in[i0 + 1], v2 = in[i0 + 2], v3 = in[i0 + 3];
    uint4 o0, o1;
    __half2 h;
    h = __floats2half2_rn(v0.x, v0.y); o0.x = *(uint32_t*)&h;
    h = __floats2half2_rn(v0.z, v0.w); o0.y = *(uint32_t*)&h;
    h = __floats2half2_rn(v1.x, v1.y); o0.z = *(uint32_t*)&h;
    h = __floats2half2_rn(v1.z, v1.w); o0.w = *(uint32_t*)&h;
    h = __floats2half2_rn(v2.x, v2.y); o1.x = *(uint32_t*)&h;
    h = __floats2half2_rn(v2.z, v2.w); o1.y = *(uint32_t*)&h;
    h = __floats2half2_rn(v3.x, v3.y); o1.z = *(uint32_t*)&h;
    h = __floats2half2_rn(v3.z, v3.w); o1.w = *(uint32_t*)&h;
    out[2 * idx]     = o0;
    out[2 * idx + 1] = o1;
}

// zero g_s + g_stats in one launch
__global__ void zero_kernel() {
    int idx = blockIdx.x * blockDim.x + threadIdx.x;
    if (idx < BATCH * D_MODEL) g_s[idx] = 0.0f;
    if (idx < NHEADS_TOTAL * STATS_PER_HEAD) g_stats[idx] = 0.0f;
}

// ===========================================================================
// colsum (vectorized)
// ===========================================================================
__global__ __launch_bounds__(128) void colsum_kernel(const __half* __restrict__ X) {
    const int b = blockIdx.x;
    const int t0 = blockIdx.y * (T_LEN / 64);
    const int n0 = threadIdx.x * 8;
    float s[8];
    #pragma unroll
    for (int i = 0; i < 8; i++) s[i] = 0.f;
    const __half* p = X + (size_t)(t0 * BATCH + b) * D_MODEL + n0;
    #pragma unroll 4
    for (int t = 0; t < T_LEN / 64; t++) {
        uint4 v = *(const uint4*)(p + (size_t)t * BATCH * D_MODEL);
        const __half2* h = (const __half2*)&v;
        #pragma unroll
        for (int i = 0; i < 4; i++) {
            float2 f = __half22float2(h[i]);
            s[2*i] += f.x; s[2*i+1] += f.y;
        }
    }
    #pragma unroll
    for (int i = 0; i < 8; i++)
        atomicAdd(&g_s[b * D_MODEL + n0 + i], s[i]);
}

// ===========================================================================
// Transpose Wv
// ===========================================================================
__global__ __launch_bounds__(256) void transpose_wv_kernel(const __half* __restrict__ Wv,
                                                           __half* __restrict__ WvT) {
    __shared__ __half tile[32][33];
    const int bx = blockIdx.x * 32, by = blockIdx.y * 32;
    const int tx = threadIdx.x & 31, ty = threadIdx.x >> 5;
    #pragma unroll
    for (int i = 0; i < 4; i++)
        tile[ty + i * 8][tx] = Wv[(size_t)(by + ty + i * 8) * D_MODEL + bx + tx];
    __syncthreads();
    #pragma unroll
    for (int i = 0; i < 4; i++)
        WvT[(size_t)(bx + ty + i * 8) * D_MODEL + by + tx] = tile[tx][ty + i * 8];
}

// ===========================================================================
// cbias
// ===========================================================================
__global__ __launch_bounds__(256) void cbias_kernel(const float* __restrict__ bqkv,
                                                    const float* __restrict__ bout) {
    __shared__ float sbv[D_MODEL];
    for (int i = threadIdx.x; i < D_MODEL; i += 256)
        sbv[i] = bqkv[2 * D_MODEL + i];
    __syncthreads();
    const int idx = blockIdx.x * 256 + threadIdx.x;
    const int b = idx >> 10, o = idx & 1023;
    const __half* row = g_mh + (size_t)b * D_MODEL * D_MODEL + (size_t)o * D_MODEL;
    float s = 0.f;
    #pragma unroll 4
    for (int d8 = 0; d8 < D_MODEL / 8; d8++) {
        uint4 v = *(const uint4*)(row + d8 * 8);
        const __half2* h = (const __half2*)&v;
        #pragma unroll
        for (int i = 0; i < 4; i++) {
            float2 f = __half22float2(h[i]);
            s += f.x * sbv[d8 * 8 + 2 * i] + f.y * sbv[d8 * 8 + 2 * i + 1];
        }
    }
    g_c[idx] = s + bout[o];
}

// ===========================================================================
// SYRK (unchanged — at mma floor)
// ===========================================================================
#define SKT 32
#define SROWH 136
#define S_TILEB (SKT * SROWH * 2)
#define S_STG (2 * S_TILEB)
#define S_NST 4
#define S_SMEMB (S_NST * S_STG)         // 69632

__global__ __launch_bounds__(256) void syrk_kernel(const __half* __restrict__ X) {
    extern __shared__ char ssm[];
    const uint32_t sb = smem_to_u32(ssm);
    const int tid = threadIdx.x, lane = tid & 31, wid = tid >> 5;
    const int b = blockIdx.y;

    int x = blockIdx.x, ti = 0;
    while (x >= 8 - ti) { x -= 8 - ti; ti++; }
    const int tj = ti + x;

    const __half* Xb = X + (size_t)b * D_MODEL;

    #define SY_ISSUE(s, buf) do { \
        _Pragma("unroll") \
        for (int i = 0; i < 4; i++) { \
            const int ci = i * 256 + tid; \
            const int r_ = (ci & 511) >> 4, c_ = ci & 15; \
            const int irange = (ci < 512) ? ti : tj; \
            const uint32_t toff = (ci < 512) ? 0u : (uint32_t)S_TILEB; \
            const __half* src = Xb + (size_t)((s) * SKT + r_) * (BATCH * D_MODEL) \
                                + irange * 128 + c_ * 8; \
            CP16(sb + (buf) * S_STG + toff + r_ * 272 + c_ * 16, src); \
        } \
    } while (0)

    float acc[4][4][4];
    #pragma unroll
    for (int mt = 0; mt < 4; mt++)
        #pragma unroll
        for (int nt = 0; nt < 4; nt++)
            #pragma unroll
            for (int r = 0; r < 4; r++) acc[mt][nt][r] = 0.0f;

    const int wi = wid >> 2;
    const int wj = wid & 3;

    const uint32_t a_base = (uint32_t)(((lane & 7) + ((lane >> 4) << 3)) * 272
                                       + (wi * 64 + ((lane >> 3) & 1) * 8) * 2);
    const uint32_t b_base = (uint32_t)((lane & 15) * 272 + ((lane >> 4) * 8 + wj * 32) * 2);

    const int NS = T_LEN / SKT;
    SY_ISSUE(0, 0); CP_COMMIT();
    SY_ISSUE(1, 1); CP_COMMIT();
    SY_ISSUE(2, 2); CP_COMMIT();

    for (int s = 0; s < NS; s++) {
        if (s >= NS - 3) { asm volatile("cp.async.wait_group 0;" ::: "memory"); }
        else             { asm volatile("cp.async.wait_group 2;" ::: "memory"); }
        __syncthreads();
        if (s + 3 < NS) { SY_ISSUE(s + 3, (s + 3) % S_NST); CP_COMMIT(); }

        const uint32_t base = sb + (s % S_NST) * S_STG;
        #pragma unroll
        for (int kk = 0; kk < 2; kk++) {
            const uint32_t krow = kk * 16 * 272;
            uint32_t a[4][4];
            #pragma unroll
            for (int mt = 0; mt < 4; mt++)
                ldsm4t(a[mt], base + a_base + krow + mt * 32);
            #pragma unroll
            for (int jn = 0; jn < 2; jn++) {
                uint32_t bb[4];
                ldsm4t(bb, base + S_TILEB + b_base + krow + jn * 32);
                #pragma unroll
                for (int mt = 0; mt < 4; mt++) {
                    mma16816(acc[mt][2*jn],   a[mt], bb[0], bb[1]);
                    mma16816(acc[mt][2*jn+1], a[mt], bb[2], bb[3]);
                }
            }
        }
        __syncthreads();
    }

    __half* G = g_G + (size_t)b * D_MODEL * D_MODEL;
    #pragma unroll
    for (int mt = 0; mt < 4; mt++) {
        #pragma unroll
        for (int jn = 0; jn < 4; jn++) {
            const int i0 = ti * 128 + wi * 64 + mt * 16 + (lane >> 2);
            const int j0 = tj * 128 + wj * 32 + jn * 8 + (lane & 3) * 2;
            const __half c0 = __float2half_rn(acc[mt][jn][0]);
            const __half c1 = __float2half_rn(acc[mt][jn][1]);
            const __half c2 = __float2half_rn(acc[mt][jn][2]);
            const __half c3 = __float2half_rn(acc[mt][jn][3]);
            *(__half2*)(G + (size_t)i0 * D_MODEL + j0)       = __halves2half2(c0, c1);
            *(__half2*)(G + (size_t)(i0 + 8) * D_MODEL + j0) = __halves2half2(c2, c3);
            if (ti != tj) {
                G[(size_t)j0 * D_MODEL + i0]           = c0;
                G[(size_t)(j0 + 1) * D_MODEL + i0]     = c1;
                G[(size_t)j0 * D_MODEL + i0 + 8]       = c2;
                G[(size_t)(j0 + 1) * D_MODEL + i0 + 8] = c3;
            }
        }
    }
}

// ===========================================================================
// Stats partial (unchanged from R13)
// ===========================================================================
__global__ __launch_bounds__(256) void stats_part_kernel() {
    const int chunk = blockIdx.x;
    const int head = blockIdx.y;
    const int b = head >> 4, h = head & 15;
    const int tid = threadIdx.x;

    __shared__ __half sT[3][64][72];
    __shared__ __half sTkT[64][68];
    __shared__ float sch[64];

    const __half* Hq = g_Ht + (size_t)b * 2 * D_MODEL * D_MODEL + (size_t)(h * 64) * D_MODEL;
    const __half* Hk = Hq + (size_t)D_MODEL * D_MODEL;
    const __half* Wq = g_wh + (size_t)(h * 64) * D_MODEL;
    const __half* Wk = g_wh + (size_t)(D_MODEL + h * 64) * D_MODEL;
    const float* sv = g_s + b * D_MODEL;

    const int ty = tid >> 4, tx = tid & 15;
    float accC[4][4];
    #pragma unroll
    for (int a = 0; a < 4; a++)
        #pragma unroll
        for (int c = 0; c < 4; c++) accC[a][c] = 0.f;
    float aqq = 0.f, auq = 0.f, akk = 0.f, auk = 0.f;

    for (int ncl = 0; ncl < 4; ncl++) {
        const int nc = chunk * 4 + ncl;
        #pragma unroll
        for (int i = 0; i < 8; i++) {
            const int ci = i * 256 + tid;
            const int tile = ci >> 9, r = (ci >> 3) & 63, c = ci & 7;
            if (tile < 3) {
                const __half* src = (tile == 0 ? Hq : tile == 1 ? Wq : Hk)
                                    + (size_t)r * D_MODEL + nc * 64 + c * 8;
                *(uint4*)&sT[tile][r][c * 8] = *(const uint4*)src;
            } else {
                const __half* src = Wk + (size_t)r * D_MODEL + nc * 64 + c * 8;
                uint4 v = *(const uint4*)src;
                const __half* hv = (const __half*)&v;
                #pragma unroll
                for (int e = 0; e < 8; e++) sTkT[c * 8 + e][r] = hv[e];
            }
        }
        if (tid < 64) sch[tid] = sv[nc * 64 + tid];
        __syncthreads();

        #pragma unroll 8
        for (int n = 0; n < 64; n++) {
            float hq[4], wk[4];
            #pragma unroll
            for (int a = 0; a < 4; a++) hq[a] = __half2float(sT[0][ty * 4 + a][n]);
            #pragma unroll
            for (int c = 0; c < 4; c++) wk[c] = __half2float(sTkT[n][tx * 4 + c]);
            #pragma unroll
            for (int a = 0; a < 4; a++)
                #pragma unroll
                for (int c = 0; c < 4; c++) accC[a][c] += hq[a] * wk[c];
        }
        if (tid < 64) {
            #pragma unroll 8
            for (int n = 0; n < 64; n++) {
                float hv = __half2float(sT[0][tid][n]);
                float wv = __half2float(sT[1][tid][n]);
                aqq += hv * wv; auq += wv * sch[n];
            }
        } else if (tid < 128) {
            const int j = tid - 64;
            #pragma unroll 8
            for (int n = 0; n < 64; n++) {
                float hv = __half2float(sT[2][j][n]);
                float wv = __half2float(sTkT[n][j]);
                akk += hv * wv; auk += wv * sch[n];
            }
        }
        __syncthreads();
    }

    float* st = g_stats + (size_t)head * STATS_PER_HEAD;
    #pragma unroll
    for (int a = 0; a < 4; a++)
        #pragma unroll
        for (int c = 0; c < 4; c++)
            atomicAdd(&st[(ty * 4 + a) * 64 + (tx * 4 + c)], accC[a][c]);
    if (tid < 64) {
        atomicAdd(&st[4096 + tid], auq);
        atomicAdd(&st[4224 + tid], aqq);
    } else if (tid < 128) {
        atomicAdd(&st[4160 + (tid - 64)], auk);
        atomicAdd(&st[4288 + (tid - 64)], akk);
    }
}

// ===========================================================================
// Fused corr + meff (unchanged from R13)
// ===========================================================================
__global__ __launch_bounds__(256) void corr_meff_kernel(const float* __restrict__ bqkv,
                                                        const float* __restrict__ Wout) {
    const int head = blockIdx.x;
    const int b = head >> 4, h = head & 15;
    const int tid = threadIdx.x;
    __shared__ float sc[HD][HD + 1];
    __shared__ float mq[HD], mk[HD], isx[HD], isy[HD];
    __shared__ float suq[HD], suk[HD], sbq[HD], sbk[HD];

    const float* st = g_stats + (size_t)head * STATS_PER_HEAD;
    const float invT = 1.0f / (float)T_LEN;
    const float Tf = (float)T_LEN;

    if (tid < 64) {
        const int i = tid;
        const float uq = st[4096 + i], qq = st[4224 + i];
        const float bq = bqkv[h * 64 + i];
        const float Sq = uq + Tf * bq;
        const float Sqq = qq + 2.f * bq * uq + Tf * bq * bq;
        suq[i] = uq; sbq[i] = bq;
        mq[i] = Sq;
        isx[i] = rsqrtf(Sqq - Sq * Sq * invT);
    } else if (tid < 128) {
        const int j = tid - 64;
        const float uk = st[4160 + j], kk = st[4288 + j];
        const float bk = bqkv[D_MODEL + h * 64 + j];
        const float Sk = uk + Tf * bk;
        const float Skk = kk + 2.f * bk * uk + Tf * bk * bk;
        suk[j] = uk; sbk[j] = bk;
        mk[j] = Sk;
        isy[j] = rsqrtf(Skk - Sk * Sk * invT);
    }
    __syncthreads();

    for (int idx = tid; idx < HD * HD; idx += 256) {
        int i = idx >> 6, j = idx & 63;
        float C = st[idx] + sbq[i] * suk[j] + suq[i] * sbk[j] + Tf * sbq[i] * sbk[j];
        float cov = C - mq[i] * mk[j] * invT;
        float c = cov * isx[i] * isy[j];
        c = fminf(fmaxf(c, 0.0f), 1.0f);
        sc[i][j] = c;
    }
    __syncthreads();

    if (tid < 64) {
        int j = tid;
        float mx = -1e30f;
        #pragma unroll 4
        for (int i = 0; i < HD; i++) mx = fmaxf(mx, sc[i][j]);
        float sum = 0.f;
        #pragma unroll 4
        for (int i = 0; i < HD; i++) {
            float e = expf(sc[i][j] - mx);
            sc[i][j] = e; sum += e;
        }
        float inv = 1.0f / sum;
        #pragma unroll 4
        for (int i = 0; i < HD; i++) sc[i][j] *= inv;
    }
    __syncthreads();

    const size_t mbase = (size_t)b * D_MODEL * D_MODEL + h * HD;
    const float* Wb = Wout + h * HD;

    for (int idx = tid; idx < D_MODEL * HD; idx += 256) {
        int o = idx >> 6, d = idx & 63;
        const float* wrow = Wb + (size_t)o * D_MODEL;
        float s = 0.f;
        #pragma unroll
        for (int e = 0; e < HD; e++) s += sc[d][e] * wrow[e];
        g_mh[mbase + (size_t)o * D_MODEL + d] = __float2half_rn(s);
    }
}

// ===========================================================================
// Launch (convQ at profile index 3)
// ===========================================================================
extern "C" void kernel_launch(void* const* d_in, const int* in_sizes, int n_in,
                              void* d_out, int out_size) {
    const float* query = (const float*)d_in[0];
    const float* Wqkv  = (const float*)d_in[1];
    const float* bqkv  = (const float*)d_in[2];
    const float* Wout  = (const float*)d_in[3];
    const float* bout  = (const float*)d_in[4];
    float* out = (float*)d_out;

    void* p;
    cudaGetSymbolAddress(&p, g_qh);    __half* qh  = (__half*)p;
    cudaGetSymbolAddress(&p, g_wh);    __half* wh  = (__half*)p;
    cudaGetSymbolAddress(&p, g_wvT);   __half* wvT = (__half*)p;
    cudaGetSymbolAddress(&p, g_mh);    __half* mh  = (__half*)p;
    cudaGetSymbolAddress(&p, g_P);     __half* P   = (__half*)p;
    cudaGetSymbolAddress(&p, g_G);     __half* G   = (__half*)p;
    cudaGetSymbolAddress(&p, g_Ht);    __half* Ht  = (__half*)p;
    cudaGetSymbolAddress(&p, g_zbias); float* zb   = (float*)p;
    cudaGetSymbolAddress(&p, g_c);     float* cb   = (float*)p;

    cudaFuncSetAttribute(gemm_fp16_kernel,
                         cudaFuncAttributeMaxDynamicSharedMemorySize, SMEMB);
    cudaFuncSetAttribute(syrk_kernel,
                         cudaFuncAttributeMaxDynamicSharedMemorySize, S_SMEMB);

    // idx 0: zero accumulators
    {
        int total = NHEADS_TOTAL * STATS_PER_HEAD;
        zero_kernel<<<(total + 1023) / 1024, 1024>>>();
    }
    // idx 1: Wqkv -> fp16 (ILP)
    {
        int n16 = QKV_LD * D_MODEL / 16;   // 196608
        conv_half_ilp_kernel<<<n16 / 256, 256>>>(
            (const float4*)Wqkv, (uint4*)wh, n16);
    }
    // idx 2: transpose Wv
    transpose_wv_kernel<<<dim3(32, 32), 256>>>(
        wh + (size_t)2 * D_MODEL * D_MODEL, wvT);

    // idx 3: query -> fp16 (ILP)   (profiled by ncu)
    {
        int n16 = NROWS * D_MODEL / 16;    // 2097152
        conv_half_ilp_kernel<<<n16 / 256, 256>>>(
            (const float4*)query, (uint4*)qh, n16);
    }

    // idx 4: G_b = X_b^T X_b
    syrk_kernel<<<dim3(36, BATCH), 256, S_SMEMB>>>(qh);

    // idx 5: Ht = Wqk * G_b
    gemm_fp16_kernel<<<dim3(D_MODEL / BN, 2 * D_MODEL / BM, BATCH), NTHR, SMEMB>>>(
        wh, D_MODEL, 0,
        G, D_MODEL, (long long)D_MODEL * D_MODEL,
        zb, 0,
        nullptr, Ht, D_MODEL, (long long)2 * D_MODEL * D_MODEL,
        D_MODEL);

    // idx 6: col sums
    colsum_kernel<<<dim3(BATCH, 64), 128>>>(qh);

    // idx 7: raw stats
    stats_part_kernel<<<dim3(4, NHEADS_TOTAL), 256>>>();

    // idx 8: corr + softmax + Meff
    corr_meff_kernel<<<NHEADS_TOTAL, 256>>>(bqkv, Wout);

    // idx 9: P_b = Meff_b @ WvT^T
    gemm_fp16_kernel<<<dim3(D_MODEL / BN, D_MODEL / BM, BATCH), NTHR, SMEMB>>>(
        mh, D_MODEL, (long long)D_MODEL * D_MODEL,
        wvT, D_MODEL, 0,
        zb, 0,
        nullptr, P, D_MODEL, (long long)D_MODEL * D_MODEL,
        D_MODEL);

    // idx 10: c_b
    cbias_kernel<<<16, 256>>>(bqkv, bout);

    // idx 11: out = X @ P_b^T + c_b
    gemm_fp16_kernel<<<dim3(D_MODEL / BN, T_LEN / BM, BATCH), NTHR, SMEMB>>>(
        qh, BATCH * D_MODEL, D_MODEL,
        P, D_MODEL, (long long)D_MODEL * D_MODEL,
        cb, D_MODEL,
        out, nullptr, BATCH * D_MODEL, D_MODEL,
        D_MODEL);
}